// round 9
// baseline (speedup 1.0000x reference)
#include <cuda_runtime.h>
#include <cuda_bf16.h>
#include <cstdint>

#define BATCH 2
#define SEQ   2048
#define EMB   512
#define NHEAD 8
#define HDIM  64
#define M1    (BATCH * SEQ)     // 4096
#define N1    (3 * EMB)         // 1536
#define KD    EMB               // 512
#define ATT_SCALE 0.125f

// ---------------------------------------------------------------------------
// helpers
// ---------------------------------------------------------------------------
__device__ __forceinline__ uint32_t smem_u32(const void* p) {
    uint32_t a;
    asm("{ .reg .u64 t; cvta.to.shared.u64 t, %1; cvt.u32.u64 %0, t; }" : "=r"(a) : "l"(p));
    return a;
}
__device__ __forceinline__ void ldsm4(uint32_t addr, uint32_t& r0, uint32_t& r1,
                                      uint32_t& r2, uint32_t& r3) {
    asm volatile("ldmatrix.sync.aligned.m8n8.x4.shared.b16 {%0,%1,%2,%3}, [%4];"
                 : "=r"(r0), "=r"(r1), "=r"(r2), "=r"(r3) : "r"(addr));
}
__device__ __forceinline__ void mma16816(float* c, uint32_t a0, uint32_t a1,
                                         uint32_t a2, uint32_t a3,
                                         uint32_t b0, uint32_t b1) {
    asm volatile("mma.sync.aligned.m16n8k16.row.col.f32.bf16.bf16.f32 "
                 "{%0,%1,%2,%3}, {%4,%5,%6,%7}, {%8,%9}, {%0,%1,%2,%3};"
                 : "+f"(c[0]), "+f"(c[1]), "+f"(c[2]), "+f"(c[3])
                 : "r"(a0), "r"(a1), "r"(a2), "r"(a3), "r"(b0), "r"(b1));
}
__device__ __forceinline__ void cp16(uint32_t dst, const void* src) {
    asm volatile("cp.async.cg.shared.global [%0], [%1], 16;" :: "r"(dst), "l"(src));
}
#define CP_COMMIT() asm volatile("cp.async.commit_group;" ::: "memory")
#define CP_WAIT(n)  asm volatile("cp.async.wait_group %0;" :: "n"(n) : "memory")

__device__ __forceinline__ void split2(float v, __nv_bfloat16& h, __nv_bfloat16& l) {
    h = __float2bfloat16(v);
    l = __float2bfloat16(v - __bfloat162float(h));
}
__device__ __forceinline__ uint32_t pack2(__nv_bfloat16 x, __nv_bfloat16 y) {
    __nv_bfloat162 t; t.x = x; t.y = y;
    return *(uint32_t*)&t;
}
__device__ __forceinline__ uint32_t a_addr(uint32_t base, int r0, int c0, int lane, int stride) {
    return base + (uint32_t)(r0 + (lane & 15)) * stride + (uint32_t)(c0 + ((lane >> 4) << 3)) * 2;
}
__device__ __forceinline__ uint32_t b_addr(uint32_t base, int n0, int c0, int lane, int stride) {
    int n = n0 + (lane & 7) + ((lane >> 4) << 3);
    int k = c0 + (((lane >> 3) & 1) << 3);
    return base + (uint32_t)n * stride + (uint32_t)k * 2;
}

// ---------------------------------------------------------------------------
// Scratch (bf16 hi/lo pairs)
// ---------------------------------------------------------------------------
__device__ __nv_bfloat16 g_Xh[M1 * KD],  g_Xl[M1 * KD];
__device__ __nv_bfloat16 g_Wqh[N1 * KD], g_Wql[N1 * KD];       // w_qkv^T [N,K]
__device__ __nv_bfloat16 g_Woh[EMB * EMB], g_Wol[EMB * EMB];   // w_o^T   [N,K]
__device__ __nv_bfloat16 g_Qh[BATCH*NHEAD*SEQ*HDIM], g_Ql[BATCH*NHEAD*SEQ*HDIM];
__device__ __nv_bfloat16 g_Kh[BATCH*NHEAD*SEQ*HDIM], g_Kl[BATCH*NHEAD*SEQ*HDIM];
__device__ __nv_bfloat16 g_Vth[BATCH*NHEAD*HDIM*SEQ], g_Vtl[BATCH*NHEAD*HDIM*SEQ];
__device__ __nv_bfloat16 g_Ah[M1 * EMB], g_Al[M1 * EMB];

// ---------------------------------------------------------------------------
__global__ __launch_bounds__(256) void split_kernel(const float* __restrict__ in,
                                                    __nv_bfloat16* __restrict__ h,
                                                    __nv_bfloat16* __restrict__ l, int n)
{
    int i = blockIdx.x * 256 + threadIdx.x;
    if (i < n) { __nv_bfloat16 a, b; split2(in[i], a, b); h[i] = a; l[i] = b; }
}
__global__ __launch_bounds__(256) void tsplit_kernel(const float* __restrict__ in,
                                                     __nv_bfloat16* __restrict__ h,
                                                     __nv_bfloat16* __restrict__ l,
                                                     int K, int N)
{
    int i = blockIdx.x * 256 + threadIdx.x;
    if (i < K * N) {
        int k = i / N, n = i - k * N;
        __nv_bfloat16 a, b; split2(in[i], a, b);
        h[(size_t)n * K + k] = a; l[(size_t)n * K + k] = b;
    }
}

// ---------------------------------------------------------------------------
// GEMM: acc[2][8][4] += A[m0:+128,:] @ B[n0:+128,:]^T (bf16x3)
// BK=32, 2-stage cp.async, 2 CTAs/SM. 256 thr, warps 4x2.
// smem stride 80B (64B data + 16B pad: 16B-aligned rows, 5r mod 8 distinct
// chunk-banks -> conflict-free ldmatrix).
// ---------------------------------------------------------------------------
#define GSTR 80
#define G_AH 0
#define G_AL 10240
#define G_BH 20480
#define G_BL 30720
#define G_STAGE 40960
#define G_SMEM_SZ (2 * G_STAGE)

__device__ __forceinline__ void gemm_load_stage(uint32_t sbase,
    const __nv_bfloat16* Ah, const __nv_bfloat16* Al,
    const __nv_bfloat16* Bh, const __nv_bfloat16* Bl,
    int Kdim, int m0, int n0, int k0)
{
    const int tid = threadIdx.x;
    #pragma unroll
    for (int i = 0; i < 2; i++) {
        int idx = tid + i * 256;          // 0..511
        int row = idx >> 2, q = idx & 3;  // 128 rows x 4 quads (64B row)
        uint32_t so = (uint32_t)row * GSTR + q * 16;
        size_t asrc = (size_t)(m0 + row) * Kdim + k0 + q * 8;
        size_t bsrc = (size_t)(n0 + row) * Kdim + k0 + q * 8;
        cp16(sbase + G_AH + so, Ah + asrc);
        cp16(sbase + G_AL + so, Al + asrc);
        cp16(sbase + G_BH + so, Bh + bsrc);
        cp16(sbase + G_BL + so, Bl + bsrc);
    }
}

__device__ __forceinline__ void gemm_compute_stage(uint32_t sbase, int warp, int lane,
                                                   float acc[2][8][4])
{
    const int wm = warp & 3, wn = warp >> 2;
    #pragma unroll
    for (int kk = 0; kk < 2; kk++) {
        uint32_t ah[2][4], al[2][4];
        #pragma unroll
        for (int mi = 0; mi < 2; mi++) {
            ldsm4(a_addr(sbase + G_AH, wm * 32 + mi * 16, kk * 16, lane, GSTR),
                  ah[mi][0], ah[mi][1], ah[mi][2], ah[mi][3]);
            ldsm4(a_addr(sbase + G_AL, wm * 32 + mi * 16, kk * 16, lane, GSTR),
                  al[mi][0], al[mi][1], al[mi][2], al[mi][3]);
        }
        #pragma unroll
        for (int njp = 0; njp < 4; njp++) {
            uint32_t bh[4], bl[4];
            ldsm4(b_addr(sbase + G_BH, wn * 64 + njp * 16, kk * 16, lane, GSTR),
                  bh[0], bh[1], bh[2], bh[3]);
            ldsm4(b_addr(sbase + G_BL, wn * 64 + njp * 16, kk * 16, lane, GSTR),
                  bl[0], bl[1], bl[2], bl[3]);
            #pragma unroll
            for (int mi = 0; mi < 2; mi++) {
                float* c0 = acc[mi][2 * njp];
                float* c1 = acc[mi][2 * njp + 1];
                mma16816(c0, ah[mi][0], ah[mi][1], ah[mi][2], ah[mi][3], bh[0], bh[1]);
                mma16816(c0, al[mi][0], al[mi][1], al[mi][2], al[mi][3], bh[0], bh[1]);
                mma16816(c0, ah[mi][0], ah[mi][1], ah[mi][2], ah[mi][3], bl[0], bl[1]);
                mma16816(c1, ah[mi][0], ah[mi][1], ah[mi][2], ah[mi][3], bh[2], bh[3]);
                mma16816(c1, al[mi][0], al[mi][1], al[mi][2], al[mi][3], bh[2], bh[3]);
                mma16816(c1, ah[mi][0], ah[mi][1], ah[mi][2], ah[mi][3], bl[2], bl[3]);
            }
        }
    }
}

__device__ __forceinline__ void gemm_mainloop(uint32_t sb,
    const __nv_bfloat16* __restrict__ Ah, const __nv_bfloat16* __restrict__ Al,
    const __nv_bfloat16* __restrict__ Bh, const __nv_bfloat16* __restrict__ Bl,
    int Kdim, int m0, int n0, float acc[2][8][4])
{
    const int warp = threadIdx.x >> 5, lane = threadIdx.x & 31;
    const int nk = Kdim / 32;

    gemm_load_stage(sb, Ah, Al, Bh, Bl, Kdim, m0, n0, 0);
    CP_COMMIT();
    for (int kc = 0; kc < nk; kc++) {
        if (kc + 1 < nk) {
            gemm_load_stage(sb + ((kc + 1) & 1) * G_STAGE, Ah, Al, Bh, Bl,
                            Kdim, m0, n0, (kc + 1) * 32);
            CP_COMMIT();
            CP_WAIT(1);
        } else {
            CP_WAIT(0);
        }
        __syncthreads();
        gemm_compute_stage(sb + (kc & 1) * G_STAGE, warp, lane, acc);
        __syncthreads();
    }
}

// ---------------------------------------------------------------------------
// QKV GEMM + scatter epilogue. grid (12, 32)
// ---------------------------------------------------------------------------
__global__ __launch_bounds__(256, 2) void gemm_qkv_tc()
{
    extern __shared__ char smem[];
    uint32_t sb = smem_u32(smem);
    const int warp = threadIdx.x >> 5, lane = threadIdx.x & 31;
    const int wm = warp & 3, wn = warp >> 2;
    const int m0 = blockIdx.y * 128, n0 = blockIdx.x * 128;

    float acc[2][8][4];
    #pragma unroll
    for (int a = 0; a < 2; a++)
        #pragma unroll
        for (int b = 0; b < 8; b++)
            #pragma unroll
            for (int c = 0; c < 4; c++) acc[a][b][c] = 0.f;

    gemm_mainloop(sb, g_Xh, g_Xl, g_Wqh, g_Wql, KD, m0, n0, acc);

    const int region = n0 >> 9;  // 0=Q 1=K 2=V
    #pragma unroll
    for (int mi = 0; mi < 2; mi++) {
        #pragma unroll
        for (int ri = 0; ri < 2; ri++) {
            int r = m0 + wm * 32 + mi * 16 + (lane >> 2) + ri * 8;
            int b = r >> 11, s = r & 2047;
            #pragma unroll
            for (int nj = 0; nj < 8; nj++) {
                int c = n0 + wn * 64 + nj * 8 + (lane & 3) * 2;
                int within = c & 511;
                int h = within >> 6, dd = within & 63;
                float v0 = acc[mi][nj][ri * 2 + 0];
                float v1 = acc[mi][nj][ri * 2 + 1];
                if (region == 0) { v0 *= ATT_SCALE; v1 *= ATT_SCALE; }
                __nv_bfloat16 h0, l0, h1, l1;
                split2(v0, h0, l0); split2(v1, h1, l1);
                if (region < 2) {
                    __nv_bfloat16* H = region == 0 ? g_Qh : g_Kh;
                    __nv_bfloat16* L = region == 0 ? g_Ql : g_Kl;
                    size_t idx = (((size_t)(b * NHEAD + h) * SEQ + s) * HDIM + dd);
                    *(uint32_t*)(H + idx) = pack2(h0, h1);
                    *(uint32_t*)(L + idx) = pack2(l0, l1);
                } else {
                    size_t base = ((size_t)(b * NHEAD + h) * HDIM + dd) * SEQ + s;
                    g_Vth[base] = h0;       g_Vtl[base] = l0;
                    g_Vth[base + SEQ] = h1; g_Vtl[base + SEQ] = l1;
                }
            }
        }
    }
}

// ---------------------------------------------------------------------------
// Out projection + bias. grid (4, 32)
// ---------------------------------------------------------------------------
__global__ __launch_bounds__(256, 2) void gemm_out_tc(const float* __restrict__ bias,
                                                      float* __restrict__ out)
{
    extern __shared__ char smem[];
    uint32_t sb = smem_u32(smem);
    const int warp = threadIdx.x >> 5, lane = threadIdx.x & 31;
    const int wm = warp & 3, wn = warp >> 2;
    const int m0 = blockIdx.y * 128, n0 = blockIdx.x * 128;

    float acc[2][8][4];
    #pragma unroll
    for (int a = 0; a < 2; a++)
        #pragma unroll
        for (int b = 0; b < 8; b++)
            #pragma unroll
            for (int c = 0; c < 4; c++) acc[a][b][c] = 0.f;

    gemm_mainloop(sb, g_Ah, g_Al, g_Woh, g_Wol, EMB, m0, n0, acc);

    #pragma unroll
    for (int mi = 0; mi < 2; mi++) {
        #pragma unroll
        for (int ri = 0; ri < 2; ri++) {
            int r = m0 + wm * 32 + mi * 16 + (lane >> 2) + ri * 8;
            #pragma unroll
            for (int nj = 0; nj < 8; nj++) {
                int c = n0 + wn * 64 + nj * 8 + (lane & 3) * 2;
                float2 v;
                v.x = acc[mi][nj][ri * 2 + 0] + bias[c];
                v.y = acc[mi][nj][ri * 2 + 1] + bias[c + 1];
                *(float2*)(out + (size_t)r * EMB + c) = v;
            }
        }
    }
}

// ---------------------------------------------------------------------------
// Flash attention. grid (16 qtiles, 16 bh), 256 threads, 2 CTAs/SM.
// 64-key tiles, 2-stage cp.async, register P path.
// smem stage: KH/KL [64x72 bf16, 144B], VH/VL [64x72, 144B] = 36864B.
// ---------------------------------------------------------------------------
#define ASTR 144
#define A_KH 0
#define A_KL 9216
#define A_VH 18432
#define A_VL 27648
#define A_STAGE 36864
#define A_SMEM_SZ (2 * A_STAGE)

__device__ __forceinline__ void attn_load_stage(uint32_t sbase, size_t qk_base, int t)
{
    const int tid = threadIdx.x;
    #pragma unroll
    for (int i = 0; i < 2; i++) {
        int idx = tid + i * 256;          // 0..511: 64 rows x 8 quads (128B row)
        int row = idx >> 3, q = idx & 7;
        uint32_t so = (uint32_t)row * ASTR + q * 16;
        { size_t src = qk_base + (size_t)(t * 64 + row) * HDIM + q * 8;
          cp16(sbase + A_KH + so, g_Kh + src);
          cp16(sbase + A_KL + so, g_Kl + src); }
        { size_t src = qk_base + (size_t)row * SEQ + t * 64 + q * 8;
          cp16(sbase + A_VH + so, g_Vth + src);
          cp16(sbase + A_VL + so, g_Vtl + src); }
    }
}

__global__ __launch_bounds__(256, 2) void attn_tc()
{
    extern __shared__ char smem[];
    uint32_t sb = smem_u32(smem);
    const int tid = threadIdx.x;
    const int warp = tid >> 5, lane = tid & 31;
    const int bh = blockIdx.y;
    const int q0 = blockIdx.x * 128;
    const size_t qk_base = (size_t)bh * SEQ * HDIM;

    // Stage Q (hi/lo) across the double-buffer space, hoist frags, then free.
    #pragma unroll
    for (int i = 0; i < 4; i++) {
        int idx = tid + i * 256;          // 0..1023: 128 rows x 8 quads
        int row = idx >> 3, q = idx & 7;
        uint32_t so = (uint32_t)row * ASTR + q * 16;
        size_t src = qk_base + (size_t)(q0 + row) * HDIM + q * 8;
        *(uint4*)(smem + so)         = *(const uint4*)(g_Qh + src);
        *(uint4*)(smem + 18432 + so) = *(const uint4*)(g_Ql + src);
    }
    __syncthreads();
    uint32_t qh[4][4], ql[4][4];
    #pragma unroll
    for (int kk = 0; kk < 4; kk++) {
        ldsm4(a_addr(sb,         warp * 16, kk * 16, lane, ASTR),
              qh[kk][0], qh[kk][1], qh[kk][2], qh[kk][3]);
        ldsm4(a_addr(sb + 18432, warp * 16, kk * 16, lane, ASTR),
              ql[kk][0], ql[kk][1], ql[kk][2], ql[kk][3]);
    }
    __syncthreads();

    float o[8][4];
    #pragma unroll
    for (int a = 0; a < 8; a++)
        #pragma unroll
        for (int c = 0; c < 4; c++) o[a][c] = 0.f;
    float m[2] = {-1e30f, -1e30f};
    float lsum[2] = {0.f, 0.f};

    const int NT = SEQ / 64;
    attn_load_stage(sb, qk_base, 0);
    CP_COMMIT();

    for (int t = 0; t < NT; t++) {
        if (t + 1 < NT) {
            attn_load_stage(sb + ((t + 1) & 1) * A_STAGE, qk_base, t + 1);
            CP_COMMIT();
            CP_WAIT(1);
        } else {
            CP_WAIT(0);
        }
        __syncthreads();
        const uint32_t st = sb + (t & 1) * A_STAGE;

        // S = Q K^T (bf16x3): rows warp*16..+15, 64 key cols
        float sc[8][4];
        #pragma unroll
        for (int a = 0; a < 8; a++)
            #pragma unroll
            for (int c = 0; c < 4; c++) sc[a][c] = 0.f;

        #pragma unroll
        for (int kk = 0; kk < 4; kk++) {
            #pragma unroll
            for (int njp = 0; njp < 4; njp++) {
                uint32_t bh4[4], bl4[4];
                ldsm4(b_addr(st + A_KH, njp * 16, kk * 16, lane, ASTR), bh4[0], bh4[1], bh4[2], bh4[3]);
                ldsm4(b_addr(st + A_KL, njp * 16, kk * 16, lane, ASTR), bl4[0], bl4[1], bl4[2], bl4[3]);
                float* c0 = sc[2 * njp];
                float* c1 = sc[2 * njp + 1];
                mma16816(c0, qh[kk][0], qh[kk][1], qh[kk][2], qh[kk][3], bh4[0], bh4[1]);
                mma16816(c0, ql[kk][0], ql[kk][1], ql[kk][2], ql[kk][3], bh4[0], bh4[1]);
                mma16816(c0, qh[kk][0], qh[kk][1], qh[kk][2], qh[kk][3], bl4[0], bl4[1]);
                mma16816(c1, qh[kk][0], qh[kk][1], qh[kk][2], qh[kk][3], bh4[2], bh4[3]);
                mma16816(c1, ql[kk][0], ql[kk][1], ql[kk][2], ql[kk][3], bh4[2], bh4[3]);
                mma16816(c1, qh[kk][0], qh[kk][1], qh[kk][2], qh[kk][3], bl4[2], bl4[3]);
            }
        }

        // online softmax; rows r = lane>>2 (ri=0) and r+8 (ri=1)
        float mx[2] = {-1e30f, -1e30f};
        #pragma unroll
        for (int nj = 0; nj < 8; nj++) {
            mx[0] = fmaxf(mx[0], fmaxf(sc[nj][0], sc[nj][1]));
            mx[1] = fmaxf(mx[1], fmaxf(sc[nj][2], sc[nj][3]));
        }
        #pragma unroll
        for (int ri = 0; ri < 2; ri++) {
            mx[ri] = fmaxf(mx[ri], __shfl_xor_sync(0xffffffff, mx[ri], 1));
            mx[ri] = fmaxf(mx[ri], __shfl_xor_sync(0xffffffff, mx[ri], 2));
        }
        float corr[2];
        #pragma unroll
        for (int ri = 0; ri < 2; ri++) {
            float nm = fmaxf(m[ri], mx[ri]);
            corr[ri] = __expf(m[ri] - nm);
            m[ri] = nm;
        }

        float ls[2] = {0.f, 0.f};
        uint32_t ph[8][2], pl[8][2];
        #pragma unroll
        for (int nj = 0; nj < 8; nj++) {
            float p0 = __expf(sc[nj][0] - m[0]);
            float p1 = __expf(sc[nj][1] - m[0]);
            float p2 = __expf(sc[nj][2] - m[1]);
            float p3 = __expf(sc[nj][3] - m[1]);
            ls[0] += p0 + p1; ls[1] += p2 + p3;
            __nv_bfloat16 a0, b0, a1, b1, a2, b2, a3, b3;
            split2(p0, a0, b0); split2(p1, a1, b1);
            split2(p2, a2, b2); split2(p3, a3, b3);
            ph[nj][0] = pack2(a0, a1); pl[nj][0] = pack2(b0, b1);
            ph[nj][1] = pack2(a2, a3); pl[nj][1] = pack2(b2, b3);
        }
        #pragma unroll
        for (int ri = 0; ri < 2; ri++) {
            ls[ri] += __shfl_xor_sync(0xffffffff, ls[ri], 1);
            ls[ri] += __shfl_xor_sync(0xffffffff, ls[ri], 2);
        }
        lsum[0] = lsum[0] * corr[0] + ls[0];
        lsum[1] = lsum[1] * corr[1] + ls[1];
        #pragma unroll
        for (int nj = 0; nj < 8; nj++) {
            o[nj][0] *= corr[0]; o[nj][1] *= corr[0];
            o[nj][2] *= corr[1]; o[nj][3] *= corr[1];
        }

        // O += P V (bf16x3): A frags from registers, B from V^T smem
        #pragma unroll
        for (int kk = 0; kk < 4; kk++) {
            uint32_t a0h = ph[2 * kk][0],     a1h = ph[2 * kk][1];
            uint32_t a2h = ph[2 * kk + 1][0], a3h = ph[2 * kk + 1][1];
            uint32_t a0l = pl[2 * kk][0],     a1l = pl[2 * kk][1];
            uint32_t a2l = pl[2 * kk + 1][0], a3l = pl[2 * kk + 1][1];
            #pragma unroll
            for (int njp = 0; njp < 4; njp++) {
                uint32_t bh4[4], bl4[4];
                ldsm4(b_addr(st + A_VH, njp * 16, kk * 16, lane, ASTR), bh4[0], bh4[1], bh4[2], bh4[3]);
                ldsm4(b_addr(st + A_VL, njp * 16, kk * 16, lane, ASTR), bl4[0], bl4[1], bl4[2], bl4[3]);
                float* c0 = o[2 * njp];
                float* c1 = o[2 * njp + 1];
                mma16816(c0, a0h, a1h, a2h, a3h, bh4[0], bh4[1]);
                mma16816(c0, a0l, a1l, a2l, a3l, bh4[0], bh4[1]);
                mma16816(c0, a0h, a1h, a2h, a3h, bl4[0], bl4[1]);
                mma16816(c1, a0h, a1h, a2h, a3h, bh4[2], bh4[3]);
                mma16816(c1, a0l, a1l, a2l, a3l, bh4[2], bh4[3]);
                mma16816(c1, a0h, a1h, a2h, a3h, bl4[2], bl4[3]);
            }
        }
        __syncthreads();
    }

    // epilogue: normalize + split-write to g_Ah/g_Al
    const int b = bh >> 3, h = bh & 7;
    float inv[2] = {1.f / lsum[0], 1.f / lsum[1]};
    #pragma unroll
    for (int ri = 0; ri < 2; ri++) {
        int r = q0 + warp * 16 + (lane >> 2) + ri * 8;
        size_t R = (size_t)(b * SEQ + r) * EMB + h * HDIM;
        #pragma unroll
        for (int nj = 0; nj < 8; nj++) {
            int dd = nj * 8 + (lane & 3) * 2;
            float v0 = o[nj][ri * 2 + 0] * inv[ri];
            float v1 = o[nj][ri * 2 + 1] * inv[ri];
            __nv_bfloat16 h0, l0, h1, l1;
            split2(v0, h0, l0); split2(v1, h1, l1);
            *(uint32_t*)(g_Ah + R + dd) = pack2(h0, h1);
            *(uint32_t*)(g_Al + R + dd) = pack2(l0, l1);
        }
    }
}

// ---------------------------------------------------------------------------
extern "C" void kernel_launch(void* const* d_in, const int* in_sizes, int n_in,
                              void* d_out, int out_size)
{
    const float* x     = (const float*)d_in[0];
    const float* w_qkv = (const float*)d_in[1];
    const float* w_o   = (const float*)d_in[2];
    const float* b_o   = (const float*)d_in[3];
    float* out = (float*)d_out;

    cudaFuncSetAttribute(gemm_qkv_tc, cudaFuncAttributeMaxDynamicSharedMemorySize, G_SMEM_SZ);
    cudaFuncSetAttribute(gemm_out_tc, cudaFuncAttributeMaxDynamicSharedMemorySize, G_SMEM_SZ);
    cudaFuncSetAttribute(attn_tc,     cudaFuncAttributeMaxDynamicSharedMemorySize, A_SMEM_SZ);

    __nv_bfloat16 *xh, *xl, *wqh, *wql, *woh, *wol;
    cudaGetSymbolAddress((void**)&xh,  g_Xh);  cudaGetSymbolAddress((void**)&xl,  g_Xl);
    cudaGetSymbolAddress((void**)&wqh, g_Wqh); cudaGetSymbolAddress((void**)&wql, g_Wql);
    cudaGetSymbolAddress((void**)&woh, g_Woh); cudaGetSymbolAddress((void**)&wol, g_Wol);

    split_kernel<<<(M1 * KD + 255) / 256, 256>>>(x, xh, xl, M1 * KD);
    tsplit_kernel<<<(KD * N1 + 255) / 256, 256>>>(w_qkv, wqh, wql, KD, N1);
    tsplit_kernel<<<(KD * EMB + 255) / 256, 256>>>(w_o, woh, wol, KD, EMB);

    gemm_qkv_tc<<<dim3(N1 / 128, M1 / 128), 256, G_SMEM_SZ>>>();
    attn_tc<<<dim3(SEQ / 128, BATCH * NHEAD), 256, A_SMEM_SZ>>>();
    gemm_out_tc<<<dim3(EMB / 128, M1 / 128), 256, G_SMEM_SZ>>>(b_o, out);
}

// round 10
// speedup vs baseline: 1.0388x; 1.0388x over previous
#include <cuda_runtime.h>
#include <cuda_bf16.h>
#include <cstdint>

#define BATCH 2
#define SEQ   2048
#define EMB   512
#define NHEAD 8
#define HDIM  64
#define M1    (BATCH * SEQ)     // 4096
#define N1    (3 * EMB)         // 1536
#define KD    EMB               // 512
#define ATT_SCALE 0.125f

// ---------------------------------------------------------------------------
// helpers
// ---------------------------------------------------------------------------
__device__ __forceinline__ uint32_t smem_u32(const void* p) {
    uint32_t a;
    asm("{ .reg .u64 t; cvta.to.shared.u64 t, %1; cvt.u32.u64 %0, t; }" : "=r"(a) : "l"(p));
    return a;
}
__device__ __forceinline__ void ldsm4(uint32_t addr, uint32_t& r0, uint32_t& r1,
                                      uint32_t& r2, uint32_t& r3) {
    asm volatile("ldmatrix.sync.aligned.m8n8.x4.shared.b16 {%0,%1,%2,%3}, [%4];"
                 : "=r"(r0), "=r"(r1), "=r"(r2), "=r"(r3) : "r"(addr));
}
__device__ __forceinline__ void mma16816(float* c, uint32_t a0, uint32_t a1,
                                         uint32_t a2, uint32_t a3,
                                         uint32_t b0, uint32_t b1) {
    asm volatile("mma.sync.aligned.m16n8k16.row.col.f32.bf16.bf16.f32 "
                 "{%0,%1,%2,%3}, {%4,%5,%6,%7}, {%8,%9}, {%0,%1,%2,%3};"
                 : "+f"(c[0]), "+f"(c[1]), "+f"(c[2]), "+f"(c[3])
                 : "r"(a0), "r"(a1), "r"(a2), "r"(a3), "r"(b0), "r"(b1));
}
__device__ __forceinline__ void cp16(uint32_t dst, const void* src) {
    asm volatile("cp.async.cg.shared.global [%0], [%1], 16;" :: "r"(dst), "l"(src));
}
#define CP_COMMIT() asm volatile("cp.async.commit_group;" ::: "memory")
#define CP_WAIT(n)  asm volatile("cp.async.wait_group %0;" :: "n"(n) : "memory")

__device__ __forceinline__ void split2(float v, __nv_bfloat16& h, __nv_bfloat16& l) {
    h = __float2bfloat16(v);
    l = __float2bfloat16(v - __bfloat162float(h));
}
__device__ __forceinline__ uint32_t pack2(__nv_bfloat16 x, __nv_bfloat16 y) {
    __nv_bfloat162 t; t.x = x; t.y = y;
    return *(uint32_t*)&t;
}
// padded-layout ldmatrix addresses (attention, stride bytes)
__device__ __forceinline__ uint32_t a_addr(uint32_t base, int r0, int c0, int lane, int stride) {
    return base + (uint32_t)(r0 + (lane & 15)) * stride + (uint32_t)(c0 + ((lane >> 4) << 3)) * 2;
}
__device__ __forceinline__ uint32_t b_addr(uint32_t base, int n0, int c0, int lane, int stride) {
    int n = n0 + (lane & 7) + ((lane >> 4) << 3);
    int k = c0 + (((lane >> 3) & 1) << 3);
    return base + (uint32_t)n * stride + (uint32_t)k * 2;
}
// GEMM swizzled layout: 64B rows, quad q placed at q ^ ((row>>1)&3)
__device__ __forceinline__ uint32_t gsw(int row, int qb) {
    return (uint32_t)row * 64 + (uint32_t)((((qb >> 4) ^ ((row >> 1) & 3)) << 4));
}
__device__ __forceinline__ uint32_t ga_addr(uint32_t base, int r0, int kk, int lane) {
    int r  = r0 + (lane & 15);
    int qb = kk * 32 + ((lane >> 4) << 4);
    return base + gsw(r, qb);
}
__device__ __forceinline__ uint32_t gb_addr(uint32_t base, int n0, int kk, int lane) {
    int n  = n0 + (lane & 7) + ((lane >> 4) << 3);
    int qb = kk * 32 + (((lane >> 3) & 1) << 4);
    return base + gsw(n, qb);
}

// ---------------------------------------------------------------------------
// Scratch (bf16 hi/lo pairs)
// ---------------------------------------------------------------------------
__device__ __nv_bfloat16 g_Xh[M1 * KD],  g_Xl[M1 * KD];
__device__ __nv_bfloat16 g_Wqh[N1 * KD], g_Wql[N1 * KD];       // w_qkv^T [N,K]
__device__ __nv_bfloat16 g_Woh[EMB * EMB], g_Wol[EMB * EMB];   // w_o^T   [N,K]
__device__ __nv_bfloat16 g_Qh[BATCH*NHEAD*SEQ*HDIM], g_Ql[BATCH*NHEAD*SEQ*HDIM];
__device__ __nv_bfloat16 g_Kh[BATCH*NHEAD*SEQ*HDIM], g_Kl[BATCH*NHEAD*SEQ*HDIM];
__device__ __nv_bfloat16 g_Vth[BATCH*NHEAD*HDIM*SEQ], g_Vtl[BATCH*NHEAD*HDIM*SEQ];
__device__ __nv_bfloat16 g_Ah[M1 * EMB], g_Al[M1 * EMB];

// ---------------------------------------------------------------------------
__global__ __launch_bounds__(256) void split_kernel(const float* __restrict__ in,
                                                    __nv_bfloat16* __restrict__ h,
                                                    __nv_bfloat16* __restrict__ l, int n)
{
    int i = blockIdx.x * 256 + threadIdx.x;
    if (i < n) { __nv_bfloat16 a, b; split2(in[i], a, b); h[i] = a; l[i] = b; }
}
__global__ __launch_bounds__(256) void tsplit_kernel(const float* __restrict__ in,
                                                     __nv_bfloat16* __restrict__ h,
                                                     __nv_bfloat16* __restrict__ l,
                                                     int K, int N)
{
    int i = blockIdx.x * 256 + threadIdx.x;
    if (i < K * N) {
        int k = i / N, n = i - k * N;
        __nv_bfloat16 a, b; split2(in[i], a, b);
        h[(size_t)n * K + k] = a; l[(size_t)n * K + k] = b;
    }
}

// ---------------------------------------------------------------------------
// GEMM: acc[2][8][4] += A[m0:+128,:] @ B[n0:+128,:]^T (bf16x3)
// BK=32, 3-stage cp.async (single sync/iter, load overlapped with math),
// 2 CTAs/SM. XOR-swizzled 64B rows (no padding). Stage 32KB, 3 stages 96KB.
// ---------------------------------------------------------------------------
#define G_AH 0
#define G_AL 8192
#define G_BH 16384
#define G_BL 24576
#define G_STAGE 32768
#define G_SMEM_SZ (3 * G_STAGE)

__device__ __forceinline__ void gemm_load_stage(uint32_t sbase,
    const __nv_bfloat16* Ah, const __nv_bfloat16* Al,
    const __nv_bfloat16* Bh, const __nv_bfloat16* Bl,
    int Kdim, int m0, int n0, int k0)
{
    const int tid = threadIdx.x;
    #pragma unroll
    for (int i = 0; i < 2; i++) {
        int idx = tid + i * 256;          // 0..511
        int row = idx >> 2, q = idx & 3;  // 128 rows x 4 quads (64B row)
        uint32_t so = gsw(row, q << 4);
        size_t asrc = (size_t)(m0 + row) * Kdim + k0 + q * 8;
        size_t bsrc = (size_t)(n0 + row) * Kdim + k0 + q * 8;
        cp16(sbase + G_AH + so, Ah + asrc);
        cp16(sbase + G_AL + so, Al + asrc);
        cp16(sbase + G_BH + so, Bh + bsrc);
        cp16(sbase + G_BL + so, Bl + bsrc);
    }
}

__device__ __forceinline__ void gemm_compute_stage(uint32_t sbase, int warp, int lane,
                                                   float acc[2][8][4])
{
    const int wm = warp & 3, wn = warp >> 2;
    #pragma unroll
    for (int kk = 0; kk < 2; kk++) {
        uint32_t ah[2][4], al[2][4];
        #pragma unroll
        for (int mi = 0; mi < 2; mi++) {
            ldsm4(ga_addr(sbase + G_AH, wm * 32 + mi * 16, kk, lane),
                  ah[mi][0], ah[mi][1], ah[mi][2], ah[mi][3]);
            ldsm4(ga_addr(sbase + G_AL, wm * 32 + mi * 16, kk, lane),
                  al[mi][0], al[mi][1], al[mi][2], al[mi][3]);
        }
        #pragma unroll
        for (int njp = 0; njp < 4; njp++) {
            uint32_t bh[4], bl[4];
            ldsm4(gb_addr(sbase + G_BH, wn * 64 + njp * 16, kk, lane),
                  bh[0], bh[1], bh[2], bh[3]);
            ldsm4(gb_addr(sbase + G_BL, wn * 64 + njp * 16, kk, lane),
                  bl[0], bl[1], bl[2], bl[3]);
            #pragma unroll
            for (int mi = 0; mi < 2; mi++) {
                float* c0 = acc[mi][2 * njp];
                float* c1 = acc[mi][2 * njp + 1];
                mma16816(c0, ah[mi][0], ah[mi][1], ah[mi][2], ah[mi][3], bh[0], bh[1]);
                mma16816(c0, al[mi][0], al[mi][1], al[mi][2], al[mi][3], bh[0], bh[1]);
                mma16816(c0, ah[mi][0], ah[mi][1], ah[mi][2], ah[mi][3], bl[0], bl[1]);
                mma16816(c1, ah[mi][0], ah[mi][1], ah[mi][2], ah[mi][3], bh[2], bh[3]);
                mma16816(c1, al[mi][0], al[mi][1], al[mi][2], al[mi][3], bh[2], bh[3]);
                mma16816(c1, ah[mi][0], ah[mi][1], ah[mi][2], ah[mi][3], bl[2], bl[3]);
            }
        }
    }
}

__device__ __forceinline__ void gemm_mainloop(uint32_t sb,
    const __nv_bfloat16* __restrict__ Ah, const __nv_bfloat16* __restrict__ Al,
    const __nv_bfloat16* __restrict__ Bh, const __nv_bfloat16* __restrict__ Bl,
    int Kdim, int m0, int n0, float acc[2][8][4])
{
    const int warp = threadIdx.x >> 5, lane = threadIdx.x & 31;
    const int nk = Kdim / 32;

    gemm_load_stage(sb,           Ah, Al, Bh, Bl, Kdim, m0, n0, 0);
    CP_COMMIT();
    gemm_load_stage(sb + G_STAGE, Ah, Al, Bh, Bl, Kdim, m0, n0, 32);
    CP_COMMIT();

    for (int kc = 0; kc < nk; kc++) {
        if (kc + 1 < nk) { CP_WAIT(1); } else { CP_WAIT(0); }
        __syncthreads();   // stage kc visible; all warps done with stage (kc-1)
        if (kc + 2 < nk) {
            gemm_load_stage(sb + ((kc + 2) % 3) * G_STAGE, Ah, Al, Bh, Bl,
                            Kdim, m0, n0, (kc + 2) * 32);
            CP_COMMIT();
        }
        gemm_compute_stage(sb + (kc % 3) * G_STAGE, warp, lane, acc);
    }
}

// ---------------------------------------------------------------------------
// QKV GEMM + scatter epilogue. grid (12, 32)
// ---------------------------------------------------------------------------
__global__ __launch_bounds__(256, 2) void gemm_qkv_tc()
{
    extern __shared__ char smem[];
    uint32_t sb = smem_u32(smem);
    const int warp = threadIdx.x >> 5, lane = threadIdx.x & 31;
    const int wm = warp & 3, wn = warp >> 2;
    const int m0 = blockIdx.y * 128, n0 = blockIdx.x * 128;

    float acc[2][8][4];
    #pragma unroll
    for (int a = 0; a < 2; a++)
        #pragma unroll
        for (int b = 0; b < 8; b++)
            #pragma unroll
            for (int c = 0; c < 4; c++) acc[a][b][c] = 0.f;

    gemm_mainloop(sb, g_Xh, g_Xl, g_Wqh, g_Wql, KD, m0, n0, acc);

    const int region = n0 >> 9;  // 0=Q 1=K 2=V
    #pragma unroll
    for (int mi = 0; mi < 2; mi++) {
        #pragma unroll
        for (int ri = 0; ri < 2; ri++) {
            int r = m0 + wm * 32 + mi * 16 + (lane >> 2) + ri * 8;
            int b = r >> 11, s = r & 2047;
            #pragma unroll
            for (int nj = 0; nj < 8; nj++) {
                int c = n0 + wn * 64 + nj * 8 + (lane & 3) * 2;
                int within = c & 511;
                int h = within >> 6, dd = within & 63;
                float v0 = acc[mi][nj][ri * 2 + 0];
                float v1 = acc[mi][nj][ri * 2 + 1];
                if (region == 0) { v0 *= ATT_SCALE; v1 *= ATT_SCALE; }
                __nv_bfloat16 h0, l0, h1, l1;
                split2(v0, h0, l0); split2(v1, h1, l1);
                if (region < 2) {
                    __nv_bfloat16* H = region == 0 ? g_Qh : g_Kh;
                    __nv_bfloat16* L = region == 0 ? g_Ql : g_Kl;
                    size_t idx = (((size_t)(b * NHEAD + h) * SEQ + s) * HDIM + dd);
                    *(uint32_t*)(H + idx) = pack2(h0, h1);
                    *(uint32_t*)(L + idx) = pack2(l0, l1);
                } else {
                    size_t base = ((size_t)(b * NHEAD + h) * HDIM + dd) * SEQ + s;
                    g_Vth[base] = h0;       g_Vtl[base] = l0;
                    g_Vth[base + SEQ] = h1; g_Vtl[base + SEQ] = l1;
                }
            }
        }
    }
}

// ---------------------------------------------------------------------------
// Out projection + bias. grid (4, 32)
// ---------------------------------------------------------------------------
__global__ __launch_bounds__(256, 2) void gemm_out_tc(const float* __restrict__ bias,
                                                      float* __restrict__ out)
{
    extern __shared__ char smem[];
    uint32_t sb = smem_u32(smem);
    const int warp = threadIdx.x >> 5, lane = threadIdx.x & 31;
    const int wm = warp & 3, wn = warp >> 2;
    const int m0 = blockIdx.y * 128, n0 = blockIdx.x * 128;

    float acc[2][8][4];
    #pragma unroll
    for (int a = 0; a < 2; a++)
        #pragma unroll
        for (int b = 0; b < 8; b++)
            #pragma unroll
            for (int c = 0; c < 4; c++) acc[a][b][c] = 0.f;

    gemm_mainloop(sb, g_Ah, g_Al, g_Woh, g_Wol, EMB, m0, n0, acc);

    #pragma unroll
    for (int mi = 0; mi < 2; mi++) {
        #pragma unroll
        for (int ri = 0; ri < 2; ri++) {
            int r = m0 + wm * 32 + mi * 16 + (lane >> 2) + ri * 8;
            #pragma unroll
            for (int nj = 0; nj < 8; nj++) {
                int c = n0 + wn * 64 + nj * 8 + (lane & 3) * 2;
                float2 v;
                v.x = acc[mi][nj][ri * 2 + 0] + bias[c];
                v.y = acc[mi][nj][ri * 2 + 1] + bias[c + 1];
                *(float2*)(out + (size_t)r * EMB + c) = v;
            }
        }
    }
}

// ---------------------------------------------------------------------------
// Flash attention. grid (16 qtiles, 16 bh), 256 threads, 2 CTAs/SM.
// 64-key tiles, 3-stage cp.async (single sync/tile), register P path.
// smem stage: KH/KL [64x72 bf16, 144B], VH/VL [64x72, 144B] = 36864B.
// ---------------------------------------------------------------------------
#define ASTR 144
#define A_KH 0
#define A_KL 9216
#define A_VH 18432
#define A_VL 27648
#define A_STAGE 36864
#define A_SMEM_SZ (3 * A_STAGE)

__device__ __forceinline__ void attn_load_stage(uint32_t sbase, size_t qk_base, int t)
{
    const int tid = threadIdx.x;
    #pragma unroll
    for (int i = 0; i < 2; i++) {
        int idx = tid + i * 256;          // 0..511: 64 rows x 8 quads (128B row)
        int row = idx >> 3, q = idx & 7;
        uint32_t so = (uint32_t)row * ASTR + q * 16;
        { size_t src = qk_base + (size_t)(t * 64 + row) * HDIM + q * 8;
          cp16(sbase + A_KH + so, g_Kh + src);
          cp16(sbase + A_KL + so, g_Kl + src); }
        { size_t src = qk_base + (size_t)row * SEQ + t * 64 + q * 8;
          cp16(sbase + A_VH + so, g_Vth + src);
          cp16(sbase + A_VL + so, g_Vtl + src); }
    }
}

__global__ __launch_bounds__(256, 2) void attn_tc()
{
    extern __shared__ char smem[];
    uint32_t sb = smem_u32(smem);
    const int tid = threadIdx.x;
    const int warp = tid >> 5, lane = tid & 31;
    const int bh = blockIdx.y;
    const int q0 = blockIdx.x * 128;
    const size_t qk_base = (size_t)bh * SEQ * HDIM;

    // Stage Q (hi/lo) into stage-0 region, hoist frags, then free.
    #pragma unroll
    for (int i = 0; i < 4; i++) {
        int idx = tid + i * 256;          // 0..1023: 128 rows x 8 quads
        int row = idx >> 3, q = idx & 7;
        uint32_t so = (uint32_t)row * ASTR + q * 16;
        size_t src = qk_base + (size_t)(q0 + row) * HDIM + q * 8;
        *(uint4*)(smem + so)         = *(const uint4*)(g_Qh + src);
        *(uint4*)(smem + 18432 + so) = *(const uint4*)(g_Ql + src);
    }
    __syncthreads();
    uint32_t qh[4][4], ql[4][4];
    #pragma unroll
    for (int kk = 0; kk < 4; kk++) {
        ldsm4(a_addr(sb,         warp * 16, kk * 16, lane, ASTR),
              qh[kk][0], qh[kk][1], qh[kk][2], qh[kk][3]);
        ldsm4(a_addr(sb + 18432, warp * 16, kk * 16, lane, ASTR),
              ql[kk][0], ql[kk][1], ql[kk][2], ql[kk][3]);
    }
    __syncthreads();

    float o[8][4];
    #pragma unroll
    for (int a = 0; a < 8; a++)
        #pragma unroll
        for (int c = 0; c < 4; c++) o[a][c] = 0.f;
    float m[2] = {-1e30f, -1e30f};
    float lsum[2] = {0.f, 0.f};

    const int NT = SEQ / 64;
    attn_load_stage(sb,           qk_base, 0); CP_COMMIT();
    attn_load_stage(sb + A_STAGE, qk_base, 1); CP_COMMIT();

    for (int t = 0; t < NT; t++) {
        if (t + 1 < NT) { CP_WAIT(1); } else { CP_WAIT(0); }
        __syncthreads();   // stage t visible; all warps done with stage (t-1)
        if (t + 2 < NT) {
            attn_load_stage(sb + ((t + 2) % 3) * A_STAGE, qk_base, t + 2);
            CP_COMMIT();
        }
        const uint32_t st = sb + (t % 3) * A_STAGE;

        // S = Q K^T (bf16x3): rows warp*16..+15, 64 key cols
        float sc[8][4];
        #pragma unroll
        for (int a = 0; a < 8; a++)
            #pragma unroll
            for (int c = 0; c < 4; c++) sc[a][c] = 0.f;

        #pragma unroll
        for (int kk = 0; kk < 4; kk++) {
            #pragma unroll
            for (int njp = 0; njp < 4; njp++) {
                uint32_t bh4[4], bl4[4];
                ldsm4(b_addr(st + A_KH, njp * 16, kk * 16, lane, ASTR), bh4[0], bh4[1], bh4[2], bh4[3]);
                ldsm4(b_addr(st + A_KL, njp * 16, kk * 16, lane, ASTR), bl4[0], bl4[1], bl4[2], bl4[3]);
                float* c0 = sc[2 * njp];
                float* c1 = sc[2 * njp + 1];
                mma16816(c0, qh[kk][0], qh[kk][1], qh[kk][2], qh[kk][3], bh4[0], bh4[1]);
                mma16816(c0, ql[kk][0], ql[kk][1], ql[kk][2], ql[kk][3], bh4[0], bh4[1]);
                mma16816(c0, qh[kk][0], qh[kk][1], qh[kk][2], qh[kk][3], bl4[0], bl4[1]);
                mma16816(c1, qh[kk][0], qh[kk][1], qh[kk][2], qh[kk][3], bh4[2], bh4[3]);
                mma16816(c1, ql[kk][0], ql[kk][1], ql[kk][2], ql[kk][3], bh4[2], bh4[3]);
                mma16816(c1, qh[kk][0], qh[kk][1], qh[kk][2], qh[kk][3], bl4[2], bl4[3]);
            }
        }

        // online softmax; rows r = lane>>2 (ri=0) and r+8 (ri=1)
        float mx[2] = {-1e30f, -1e30f};
        #pragma unroll
        for (int nj = 0; nj < 8; nj++) {
            mx[0] = fmaxf(mx[0], fmaxf(sc[nj][0], sc[nj][1]));
            mx[1] = fmaxf(mx[1], fmaxf(sc[nj][2], sc[nj][3]));
        }
        #pragma unroll
        for (int ri = 0; ri < 2; ri++) {
            mx[ri] = fmaxf(mx[ri], __shfl_xor_sync(0xffffffff, mx[ri], 1));
            mx[ri] = fmaxf(mx[ri], __shfl_xor_sync(0xffffffff, mx[ri], 2));
        }
        float corr[2];
        #pragma unroll
        for (int ri = 0; ri < 2; ri++) {
            float nm = fmaxf(m[ri], mx[ri]);
            corr[ri] = __expf(m[ri] - nm);
            m[ri] = nm;
        }

        float ls[2] = {0.f, 0.f};
        uint32_t ph[8][2], pl[8][2];
        #pragma unroll
        for (int nj = 0; nj < 8; nj++) {
            float p0 = __expf(sc[nj][0] - m[0]);
            float p1 = __expf(sc[nj][1] - m[0]);
            float p2 = __expf(sc[nj][2] - m[1]);
            float p3 = __expf(sc[nj][3] - m[1]);
            ls[0] += p0 + p1; ls[1] += p2 + p3;
            __nv_bfloat16 a0, b0, a1, b1, a2, b2, a3, b3;
            split2(p0, a0, b0); split2(p1, a1, b1);
            split2(p2, a2, b2); split2(p3, a3, b3);
            ph[nj][0] = pack2(a0, a1); pl[nj][0] = pack2(b0, b1);
            ph[nj][1] = pack2(a2, a3); pl[nj][1] = pack2(b2, b3);
        }
        #pragma unroll
        for (int ri = 0; ri < 2; ri++) {
            ls[ri] += __shfl_xor_sync(0xffffffff, ls[ri], 1);
            ls[ri] += __shfl_xor_sync(0xffffffff, ls[ri], 2);
        }
        lsum[0] = lsum[0] * corr[0] + ls[0];
        lsum[1] = lsum[1] * corr[1] + ls[1];
        #pragma unroll
        for (int nj = 0; nj < 8; nj++) {
            o[nj][0] *= corr[0]; o[nj][1] *= corr[0];
            o[nj][2] *= corr[1]; o[nj][3] *= corr[1];
        }

        // O += P V (bf16x3): A frags from registers, B from V^T smem
        #pragma unroll
        for (int kk = 0; kk < 4; kk++) {
            uint32_t a0h = ph[2 * kk][0],     a1h = ph[2 * kk][1];
            uint32_t a2h = ph[2 * kk + 1][0], a3h = ph[2 * kk + 1][1];
            uint32_t a0l = pl[2 * kk][0],     a1l = pl[2 * kk][1];
            uint32_t a2l = pl[2 * kk + 1][0], a3l = pl[2 * kk + 1][1];
            #pragma unroll
            for (int njp = 0; njp < 4; njp++) {
                uint32_t bh4[4], bl4[4];
                ldsm4(b_addr(st + A_VH, njp * 16, kk * 16, lane, ASTR), bh4[0], bh4[1], bh4[2], bh4[3]);
                ldsm4(b_addr(st + A_VL, njp * 16, kk * 16, lane, ASTR), bl4[0], bl4[1], bl4[2], bl4[3]);
                float* c0 = o[2 * njp];
                float* c1 = o[2 * njp + 1];
                mma16816(c0, a0h, a1h, a2h, a3h, bh4[0], bh4[1]);
                mma16816(c0, a0l, a1l, a2l, a3l, bh4[0], bh4[1]);
                mma16816(c0, a0h, a1h, a2h, a3h, bl4[0], bl4[1]);
                mma16816(c1, a0h, a1h, a2h, a3h, bh4[2], bh4[3]);
                mma16816(c1, a0l, a1l, a2l, a3l, bh4[2], bh4[3]);
                mma16816(c1, a0h, a1h, a2h, a3h, bl4[2], bl4[3]);
            }
        }
    }

    // epilogue: normalize + split-write to g_Ah/g_Al
    const int b = bh >> 3, h = bh & 7;
    float inv[2] = {1.f / lsum[0], 1.f / lsum[1]};
    #pragma unroll
    for (int ri = 0; ri < 2; ri++) {
        int r = q0 + warp * 16 + (lane >> 2) + ri * 8;
        size_t R = (size_t)(b * SEQ + r) * EMB + h * HDIM;
        #pragma unroll
        for (int nj = 0; nj < 8; nj++) {
            int dd = nj * 8 + (lane & 3) * 2;
            float v0 = o[nj][ri * 2 + 0] * inv[ri];
            float v1 = o[nj][ri * 2 + 1] * inv[ri];
            __nv_bfloat16 h0, l0, h1, l1;
            split2(v0, h0, l0); split2(v1, h1, l1);
            *(uint32_t*)(g_Ah + R + dd) = pack2(h0, h1);
            *(uint32_t*)(g_Al + R + dd) = pack2(l0, l1);
        }
    }
}

// ---------------------------------------------------------------------------
extern "C" void kernel_launch(void* const* d_in, const int* in_sizes, int n_in,
                              void* d_out, int out_size)
{
    const float* x     = (const float*)d_in[0];
    const float* w_qkv = (const float*)d_in[1];
    const float* w_o   = (const float*)d_in[2];
    const float* b_o   = (const float*)d_in[3];
    float* out = (float*)d_out;

    cudaFuncSetAttribute(gemm_qkv_tc, cudaFuncAttributeMaxDynamicSharedMemorySize, G_SMEM_SZ);
    cudaFuncSetAttribute(gemm_out_tc, cudaFuncAttributeMaxDynamicSharedMemorySize, G_SMEM_SZ);
    cudaFuncSetAttribute(attn_tc,     cudaFuncAttributeMaxDynamicSharedMemorySize, A_SMEM_SZ);

    __nv_bfloat16 *xh, *xl, *wqh, *wql, *woh, *wol;
    cudaGetSymbolAddress((void**)&xh,  g_Xh);  cudaGetSymbolAddress((void**)&xl,  g_Xl);
    cudaGetSymbolAddress((void**)&wqh, g_Wqh); cudaGetSymbolAddress((void**)&wql, g_Wql);
    cudaGetSymbolAddress((void**)&woh, g_Woh); cudaGetSymbolAddress((void**)&wol, g_Wol);

    split_kernel<<<(M1 * KD + 255) / 256, 256>>>(x, xh, xl, M1 * KD);
    tsplit_kernel<<<(KD * N1 + 255) / 256, 256>>>(w_qkv, wqh, wql, KD, N1);
    tsplit_kernel<<<(KD * EMB + 255) / 256, 256>>>(w_o, woh, wol, KD, EMB);

    gemm_qkv_tc<<<dim3(N1 / 128, M1 / 128), 256, G_SMEM_SZ>>>();
    attn_tc<<<dim3(SEQ / 128, BATCH * NHEAD), 256, A_SMEM_SZ>>>();
    gemm_out_tc<<<dim3(EMB / 128, M1 / 128), 256, G_SMEM_SZ>>>(b_o, out);
}

// round 11
// speedup vs baseline: 1.1349x; 1.0926x over previous
#include <cuda_runtime.h>
#include <cuda_bf16.h>
#include <cstdint>

#define BATCH 2
#define SEQ   2048
#define EMB   512
#define NHEAD 8
#define HDIM  64
#define M1    (BATCH * SEQ)     // 4096
#define N1    (3 * EMB)         // 1536
#define KD    EMB               // 512
#define ATT_SCALE 0.125f

// ---------------------------------------------------------------------------
// helpers
// ---------------------------------------------------------------------------
__device__ __forceinline__ uint32_t smem_u32(const void* p) {
    uint32_t a;
    asm("{ .reg .u64 t; cvta.to.shared.u64 t, %1; cvt.u32.u64 %0, t; }" : "=r"(a) : "l"(p));
    return a;
}
__device__ __forceinline__ void ldsm4(uint32_t addr, uint32_t& r0, uint32_t& r1,
                                      uint32_t& r2, uint32_t& r3) {
    asm volatile("ldmatrix.sync.aligned.m8n8.x4.shared.b16 {%0,%1,%2,%3}, [%4];"
                 : "=r"(r0), "=r"(r1), "=r"(r2), "=r"(r3) : "r"(addr));
}
__device__ __forceinline__ void mma16816(float* c, uint32_t a0, uint32_t a1,
                                         uint32_t a2, uint32_t a3,
                                         uint32_t b0, uint32_t b1) {
    asm volatile("mma.sync.aligned.m16n8k16.row.col.f32.bf16.bf16.f32 "
                 "{%0,%1,%2,%3}, {%4,%5,%6,%7}, {%8,%9}, {%0,%1,%2,%3};"
                 : "+f"(c[0]), "+f"(c[1]), "+f"(c[2]), "+f"(c[3])
                 : "r"(a0), "r"(a1), "r"(a2), "r"(a3), "r"(b0), "r"(b1));
}
__device__ __forceinline__ void mma_tf32(float* c, uint32_t a0, uint32_t a1,
                                         uint32_t a2, uint32_t a3,
                                         uint32_t b0, uint32_t b1) {
    asm volatile("mma.sync.aligned.m16n8k8.row.col.f32.tf32.tf32.f32 "
                 "{%0,%1,%2,%3}, {%4,%5,%6,%7}, {%8,%9}, {%0,%1,%2,%3};"
                 : "+f"(c[0]), "+f"(c[1]), "+f"(c[2]), "+f"(c[3])
                 : "r"(a0), "r"(a1), "r"(a2), "r"(a3), "r"(b0), "r"(b1));
}
__device__ __forceinline__ void cp16(uint32_t dst, const void* src) {
    asm volatile("cp.async.cg.shared.global [%0], [%1], 16;" :: "r"(dst), "l"(src));
}
#define CP_COMMIT() asm volatile("cp.async.commit_group;" ::: "memory")
#define CP_WAIT(n)  asm volatile("cp.async.wait_group %0;" :: "n"(n) : "memory")

__device__ __forceinline__ void split2(float v, __nv_bfloat16& h, __nv_bfloat16& l) {
    h = __float2bfloat16(v);
    l = __float2bfloat16(v - __bfloat162float(h));
}
__device__ __forceinline__ uint32_t pack2(__nv_bfloat16 x, __nv_bfloat16 y) {
    __nv_bfloat162 t; t.x = x; t.y = y;
    return *(uint32_t*)&t;
}
__device__ __forceinline__ uint32_t tf32r(float x) {   // round-to-nearest tf32 bits
    uint32_t r;
    asm("cvt.rna.tf32.f32 %0, %1;" : "=r"(r) : "f"(x));
    return r;
}
__device__ __forceinline__ float tf32f(float x) { return __uint_as_float(tf32r(x)); }

// padded-layout ldmatrix addresses (stride bytes)
__device__ __forceinline__ uint32_t a_addr(uint32_t base, int r0, int c0, int lane, int stride) {
    return base + (uint32_t)(r0 + (lane & 15)) * stride + (uint32_t)(c0 + ((lane >> 4) << 3)) * 2;
}
__device__ __forceinline__ uint32_t b_addr(uint32_t base, int n0, int c0, int lane, int stride) {
    int n = n0 + (lane & 7) + ((lane >> 4) << 3);
    int k = c0 + (((lane >> 3) & 1) << 3);
    return base + (uint32_t)n * stride + (uint32_t)k * 2;
}
// fp32 (tf32) variants: k offsets in BYTES
__device__ __forceinline__ uint32_t a32_addr(uint32_t base, int r0, int kbyte, int lane, int stride) {
    return base + (uint32_t)(r0 + (lane & 15)) * stride + (uint32_t)(kbyte + ((lane >> 4) << 4));
}
__device__ __forceinline__ uint32_t b32_addr(uint32_t base, int n0, int kbyte, int lane, int stride) {
    int n = n0 + (lane & 7) + ((lane >> 4) << 3);
    return base + (uint32_t)n * stride + (uint32_t)(kbyte + (((lane >> 3) & 1) << 4));
}
// GEMM bf16 swizzled layout: 64B rows, quad q placed at q ^ ((row>>1)&3)
__device__ __forceinline__ uint32_t gsw(int row, int qb) {
    return (uint32_t)row * 64 + (uint32_t)((((qb >> 4) ^ ((row >> 1) & 3)) << 4));
}
__device__ __forceinline__ uint32_t ga_addr(uint32_t base, int r0, int kk, int lane) {
    int r  = r0 + (lane & 15);
    int qb = kk * 32 + ((lane >> 4) << 4);
    return base + gsw(r, qb);
}
__device__ __forceinline__ uint32_t gb_addr(uint32_t base, int n0, int kk, int lane) {
    int n  = n0 + (lane & 7) + ((lane >> 4) << 3);
    int qb = kk * 32 + (((lane >> 3) & 1) << 4);
    return base + gsw(n, qb);
}

// ---------------------------------------------------------------------------
// Scratch
// ---------------------------------------------------------------------------
__device__ __nv_bfloat16 g_Xh[M1 * KD],  g_Xl[M1 * KD];
__device__ __nv_bfloat16 g_Wqh[N1 * KD], g_Wql[N1 * KD];       // w_qkv^T [N,K]
__device__ __nv_bfloat16 g_Qh[BATCH*NHEAD*SEQ*HDIM], g_Ql[BATCH*NHEAD*SEQ*HDIM];
__device__ __nv_bfloat16 g_Kh[BATCH*NHEAD*SEQ*HDIM], g_Kl[BATCH*NHEAD*SEQ*HDIM];
__device__ float g_Vt[BATCH*NHEAD*HDIM*SEQ];   // V^T fp32 (tf32-rounded)
__device__ float g_A[M1 * EMB];                // attention out fp32 (tf32-rounded)
__device__ float g_WoT[EMB * EMB];             // w_o^T fp32 (tf32-rounded)

// ---------------------------------------------------------------------------
__global__ __launch_bounds__(256) void split_kernel(const float* __restrict__ in,
                                                    __nv_bfloat16* __restrict__ h,
                                                    __nv_bfloat16* __restrict__ l, int n)
{
    int i = blockIdx.x * 256 + threadIdx.x;
    if (i < n) { __nv_bfloat16 a, b; split2(in[i], a, b); h[i] = a; l[i] = b; }
}
__global__ __launch_bounds__(256) void tsplit_kernel(const float* __restrict__ in,
                                                     __nv_bfloat16* __restrict__ h,
                                                     __nv_bfloat16* __restrict__ l,
                                                     int K, int N)
{
    int i = blockIdx.x * 256 + threadIdx.x;
    if (i < K * N) {
        int k = i / N, n = i - k * N;
        __nv_bfloat16 a, b; split2(in[i], a, b);
        h[(size_t)n * K + k] = a; l[(size_t)n * K + k] = b;
    }
}
// transpose + tf32-round (fp32 out)
__global__ __launch_bounds__(256) void ttf32_kernel(const float* __restrict__ in,
                                                    float* __restrict__ out, int K, int N)
{
    int i = blockIdx.x * 256 + threadIdx.x;
    if (i < K * N) {
        int k = i / N, n = i - k * N;
        out[(size_t)n * K + k] = tf32f(in[i]);
    }
}

// ---------------------------------------------------------------------------
// bf16x3 GEMM (QKV projection): BK=32, 3-stage cp.async, 2 CTAs/SM.
// ---------------------------------------------------------------------------
#define G_AH 0
#define G_AL 8192
#define G_BH 16384
#define G_BL 24576
#define G_STAGE 32768
#define G_SMEM_SZ (3 * G_STAGE)

__device__ __forceinline__ void gemm_load_stage(uint32_t sbase,
    const __nv_bfloat16* Ah, const __nv_bfloat16* Al,
    const __nv_bfloat16* Bh, const __nv_bfloat16* Bl,
    int Kdim, int m0, int n0, int k0)
{
    const int tid = threadIdx.x;
    #pragma unroll
    for (int i = 0; i < 2; i++) {
        int idx = tid + i * 256;
        int row = idx >> 2, q = idx & 3;
        uint32_t so = gsw(row, q << 4);
        size_t asrc = (size_t)(m0 + row) * Kdim + k0 + q * 8;
        size_t bsrc = (size_t)(n0 + row) * Kdim + k0 + q * 8;
        cp16(sbase + G_AH + so, Ah + asrc);
        cp16(sbase + G_AL + so, Al + asrc);
        cp16(sbase + G_BH + so, Bh + bsrc);
        cp16(sbase + G_BL + so, Bl + bsrc);
    }
}

__device__ __forceinline__ void gemm_compute_stage(uint32_t sbase, int warp, int lane,
                                                   float acc[2][8][4])
{
    const int wm = warp & 3, wn = warp >> 2;
    #pragma unroll
    for (int kk = 0; kk < 2; kk++) {
        uint32_t ah[2][4], al[2][4];
        #pragma unroll
        for (int mi = 0; mi < 2; mi++) {
            ldsm4(ga_addr(sbase + G_AH, wm * 32 + mi * 16, kk, lane),
                  ah[mi][0], ah[mi][1], ah[mi][2], ah[mi][3]);
            ldsm4(ga_addr(sbase + G_AL, wm * 32 + mi * 16, kk, lane),
                  al[mi][0], al[mi][1], al[mi][2], al[mi][3]);
        }
        #pragma unroll
        for (int njp = 0; njp < 4; njp++) {
            uint32_t bh[4], bl[4];
            ldsm4(gb_addr(sbase + G_BH, wn * 64 + njp * 16, kk, lane),
                  bh[0], bh[1], bh[2], bh[3]);
            ldsm4(gb_addr(sbase + G_BL, wn * 64 + njp * 16, kk, lane),
                  bl[0], bl[1], bl[2], bl[3]);
            #pragma unroll
            for (int mi = 0; mi < 2; mi++) {
                float* c0 = acc[mi][2 * njp];
                float* c1 = acc[mi][2 * njp + 1];
                mma16816(c0, ah[mi][0], ah[mi][1], ah[mi][2], ah[mi][3], bh[0], bh[1]);
                mma16816(c0, al[mi][0], al[mi][1], al[mi][2], al[mi][3], bh[0], bh[1]);
                mma16816(c0, ah[mi][0], ah[mi][1], ah[mi][2], ah[mi][3], bl[0], bl[1]);
                mma16816(c1, ah[mi][0], ah[mi][1], ah[mi][2], ah[mi][3], bh[2], bh[3]);
                mma16816(c1, al[mi][0], al[mi][1], al[mi][2], al[mi][3], bh[2], bh[3]);
                mma16816(c1, ah[mi][0], ah[mi][1], ah[mi][2], ah[mi][3], bl[2], bl[3]);
            }
        }
    }
}

__global__ __launch_bounds__(256, 2) void gemm_qkv_tc()
{
    extern __shared__ char smem[];
    uint32_t sb = smem_u32(smem);
    const int warp = threadIdx.x >> 5, lane = threadIdx.x & 31;
    const int wm = warp & 3, wn = warp >> 2;
    const int m0 = blockIdx.y * 128, n0 = blockIdx.x * 128;

    float acc[2][8][4];
    #pragma unroll
    for (int a = 0; a < 2; a++)
        #pragma unroll
        for (int b = 0; b < 8; b++)
            #pragma unroll
            for (int c = 0; c < 4; c++) acc[a][b][c] = 0.f;

    const int nk = KD / 32;
    gemm_load_stage(sb,           g_Xh, g_Xl, g_Wqh, g_Wql, KD, m0, n0, 0);
    CP_COMMIT();
    gemm_load_stage(sb + G_STAGE, g_Xh, g_Xl, g_Wqh, g_Wql, KD, m0, n0, 32);
    CP_COMMIT();
    for (int kc = 0; kc < nk; kc++) {
        if (kc + 1 < nk) { CP_WAIT(1); } else { CP_WAIT(0); }
        __syncthreads();
        if (kc + 2 < nk) {
            gemm_load_stage(sb + ((kc + 2) % 3) * G_STAGE, g_Xh, g_Xl, g_Wqh, g_Wql,
                            KD, m0, n0, (kc + 2) * 32);
            CP_COMMIT();
        }
        gemm_compute_stage(sb + (kc % 3) * G_STAGE, warp, lane, acc);
    }

    const int region = n0 >> 9;  // 0=Q 1=K 2=V
    #pragma unroll
    for (int mi = 0; mi < 2; mi++) {
        #pragma unroll
        for (int ri = 0; ri < 2; ri++) {
            int r = m0 + wm * 32 + mi * 16 + (lane >> 2) + ri * 8;
            int b = r >> 11, s = r & 2047;
            #pragma unroll
            for (int nj = 0; nj < 8; nj++) {
                int c = n0 + wn * 64 + nj * 8 + (lane & 3) * 2;
                int within = c & 511;
                int h = within >> 6, dd = within & 63;
                float v0 = acc[mi][nj][ri * 2 + 0];
                float v1 = acc[mi][nj][ri * 2 + 1];
                if (region == 0) { v0 *= ATT_SCALE; v1 *= ATT_SCALE; }
                if (region < 2) {
                    __nv_bfloat16 h0, l0, h1, l1;
                    split2(v0, h0, l0); split2(v1, h1, l1);
                    __nv_bfloat16* H = region == 0 ? g_Qh : g_Kh;
                    __nv_bfloat16* L = region == 0 ? g_Ql : g_Kl;
                    size_t idx = (((size_t)(b * NHEAD + h) * SEQ + s) * HDIM + dd);
                    *(uint32_t*)(H + idx) = pack2(h0, h1);
                    *(uint32_t*)(L + idx) = pack2(l0, l1);
                } else {
                    size_t base = ((size_t)(b * NHEAD + h) * HDIM + dd) * SEQ + s;
                    g_Vt[base]       = tf32f(v0);
                    g_Vt[base + SEQ] = tf32f(v1);
                }
            }
        }
    }
}

// ---------------------------------------------------------------------------
// Out projection (tf32): out[4096,512] = g_A @ g_WoT^T + bias. grid (4, 32)
// fp32 operands, stride 144B rows (32 fp32 + pad), 3-stage cp.async, 2 CTAs/SM
// ---------------------------------------------------------------------------
#define O_STR 144
#define O_A 0
#define O_B 18432
#define O_STAGE 36864
#define O_SMEM_SZ (3 * O_STAGE)

__global__ __launch_bounds__(256, 2) void gemm_out_tc(const float* __restrict__ bias,
                                                      float* __restrict__ out)
{
    extern __shared__ char smem[];
    uint32_t sb = smem_u32(smem);
    const int tid = threadIdx.x;
    const int warp = tid >> 5, lane = tid & 31;
    const int wm = warp & 3, wn = warp >> 2;
    const int m0 = blockIdx.y * 128, n0 = blockIdx.x * 128;

    float acc[2][8][4];
    #pragma unroll
    for (int a = 0; a < 2; a++)
        #pragma unroll
        for (int b = 0; b < 8; b++)
            #pragma unroll
            for (int c = 0; c < 4; c++) acc[a][b][c] = 0.f;

    auto load_stage = [&](uint32_t sbase, int k0) {
        #pragma unroll
        for (int i = 0; i < 4; i++) {
            int idx = tid + i * 256;          // 0..1023: 128 rows x 8 quads (128B data)
            int row = idx >> 3, q = idx & 7;
            uint32_t so = (uint32_t)row * O_STR + q * 16;
            cp16(sbase + O_A + so, g_A   + (size_t)(m0 + row) * EMB + k0 + q * 4);
            cp16(sbase + O_B + so, g_WoT + (size_t)(n0 + row) * EMB + k0 + q * 4);
        }
    };

    const int nk = EMB / 32;
    load_stage(sb,           0);  CP_COMMIT();
    load_stage(sb + O_STAGE, 32); CP_COMMIT();
    for (int kc = 0; kc < nk; kc++) {
        if (kc + 1 < nk) { CP_WAIT(1); } else { CP_WAIT(0); }
        __syncthreads();
        if (kc + 2 < nk) { load_stage(sb + ((kc + 2) % 3) * O_STAGE, (kc + 2) * 32); CP_COMMIT(); }
        const uint32_t st = sb + (kc % 3) * O_STAGE;

        #pragma unroll
        for (int kk = 0; kk < 4; kk++) {          // k8 steps (32B each)
            uint32_t a4[2][4];
            #pragma unroll
            for (int mi = 0; mi < 2; mi++)
                ldsm4(a32_addr(st + O_A, wm * 32 + mi * 16, kk * 32, lane, O_STR),
                      a4[mi][0], a4[mi][1], a4[mi][2], a4[mi][3]);
            #pragma unroll
            for (int njp = 0; njp < 4; njp++) {
                uint32_t b4[4];
                ldsm4(b32_addr(st + O_B, wn * 64 + njp * 16, kk * 32, lane, O_STR),
                      b4[0], b4[1], b4[2], b4[3]);
                #pragma unroll
                for (int mi = 0; mi < 2; mi++) {
                    mma_tf32(acc[mi][2 * njp],     a4[mi][0], a4[mi][1], a4[mi][2], a4[mi][3], b4[0], b4[1]);
                    mma_tf32(acc[mi][2 * njp + 1], a4[mi][0], a4[mi][1], a4[mi][2], a4[mi][3], b4[2], b4[3]);
                }
            }
        }
    }

    #pragma unroll
    for (int mi = 0; mi < 2; mi++) {
        #pragma unroll
        for (int ri = 0; ri < 2; ri++) {
            int r = m0 + wm * 32 + mi * 16 + (lane >> 2) + ri * 8;
            #pragma unroll
            for (int nj = 0; nj < 8; nj++) {
                int c = n0 + wn * 64 + nj * 8 + (lane & 3) * 2;
                float2 v;
                v.x = acc[mi][nj][ri * 2 + 0] + bias[c];
                v.y = acc[mi][nj][ri * 2 + 1] + bias[c + 1];
                *(float2*)(out + (size_t)r * EMB + c) = v;
            }
        }
    }
}

// ---------------------------------------------------------------------------
// Flash attention. grid (16 qtiles, 16 bh), 256 threads, 2 CTAs/SM.
// QK^T bf16x3; P·V single tf32 (A-frags built from S C-frags via quad shfl).
// smem stage: KH/KL [64x72 bf16, 144B], V [64 d x 64 keys fp32, 272B] = 35840B
// ---------------------------------------------------------------------------
#define ASTR 144
#define VSTR32 272
#define A_KH 0
#define A_KL 9216
#define A_V  18432
#define A_STAGE 35840
#define A_SMEM_SZ (3 * A_STAGE)

__device__ __forceinline__ void attn_load_stage(uint32_t sbase, size_t qk_base,
                                                size_t v_base, int t)
{
    const int tid = threadIdx.x;
    #pragma unroll
    for (int i = 0; i < 2; i++) {
        int idx = tid + i * 256;          // K: 64 rows x 8 quads
        int row = idx >> 3, q = idx & 7;
        uint32_t so = (uint32_t)row * ASTR + q * 16;
        size_t src = qk_base + (size_t)(t * 64 + row) * HDIM + q * 8;
        cp16(sbase + A_KH + so, g_Kh + src);
        cp16(sbase + A_KL + so, g_Kl + src);
    }
    #pragma unroll
    for (int i = 0; i < 4; i++) {
        int idx = tid + i * 256;          // V: 64 d-rows x 16 quads (256B data)
        int row = idx >> 4, q = idx & 15;
        uint32_t so = (uint32_t)row * VSTR32 + q * 16;
        size_t src = v_base + (size_t)row * SEQ + t * 64 + q * 4;
        cp16(sbase + A_V + so, g_Vt + src);
    }
}

__global__ __launch_bounds__(256, 2) void attn_tc()
{
    extern __shared__ char smem[];
    uint32_t sb = smem_u32(smem);
    const int tid = threadIdx.x;
    const int warp = tid >> 5, lane = tid & 31;
    const int bh = blockIdx.y;
    const int q0 = blockIdx.x * 128;
    const size_t qk_base = (size_t)bh * SEQ * HDIM;
    const size_t v_base  = (size_t)bh * HDIM * SEQ;

    // Stage Q (hi/lo) into scratch region, hoist frags, then free.
    #pragma unroll
    for (int i = 0; i < 4; i++) {
        int idx = tid + i * 256;          // 128 rows x 8 quads
        int row = idx >> 3, q = idx & 7;
        uint32_t so = (uint32_t)row * ASTR + q * 16;
        size_t src = qk_base + (size_t)(q0 + row) * HDIM + q * 8;
        *(uint4*)(smem + so)         = *(const uint4*)(g_Qh + src);
        *(uint4*)(smem + 18432 + so) = *(const uint4*)(g_Ql + src);
    }
    __syncthreads();
    uint32_t qh[4][4], ql[4][4];
    #pragma unroll
    for (int kk = 0; kk < 4; kk++) {
        ldsm4(a_addr(sb,         warp * 16, kk * 16, lane, ASTR),
              qh[kk][0], qh[kk][1], qh[kk][2], qh[kk][3]);
        ldsm4(a_addr(sb + 18432, warp * 16, kk * 16, lane, ASTR),
              ql[kk][0], ql[kk][1], ql[kk][2], ql[kk][3]);
    }
    __syncthreads();

    float o[8][4];
    #pragma unroll
    for (int a = 0; a < 8; a++)
        #pragma unroll
        for (int c = 0; c < 4; c++) o[a][c] = 0.f;
    float m[2] = {-1e30f, -1e30f};
    float lsum[2] = {0.f, 0.f};

    const int NT = SEQ / 64;
    attn_load_stage(sb,           qk_base, v_base, 0); CP_COMMIT();
    attn_load_stage(sb + A_STAGE, qk_base, v_base, 1); CP_COMMIT();

    // shfl source lanes for tf32 A-frag build (col c = lane&3)
    const int src_lo = (lane & ~3) | ((lane >> 1) & 1);
    const int src_hi = src_lo | 2;
    const bool oddc = lane & 1;

    for (int t = 0; t < NT; t++) {
        if (t + 1 < NT) { CP_WAIT(1); } else { CP_WAIT(0); }
        __syncthreads();
        if (t + 2 < NT) {
            attn_load_stage(sb + ((t + 2) % 3) * A_STAGE, qk_base, v_base, t + 2);
            CP_COMMIT();
        }
        const uint32_t st = sb + (t % 3) * A_STAGE;

        // S = Q K^T (bf16x3): rows warp*16..+15, 64 key cols
        float sc[8][4];
        #pragma unroll
        for (int a = 0; a < 8; a++)
            #pragma unroll
            for (int c = 0; c < 4; c++) sc[a][c] = 0.f;

        #pragma unroll
        for (int kk = 0; kk < 4; kk++) {
            #pragma unroll
            for (int njp = 0; njp < 4; njp++) {
                uint32_t bh4[4], bl4[4];
                ldsm4(b_addr(st + A_KH, njp * 16, kk * 16, lane, ASTR), bh4[0], bh4[1], bh4[2], bh4[3]);
                ldsm4(b_addr(st + A_KL, njp * 16, kk * 16, lane, ASTR), bl4[0], bl4[1], bl4[2], bl4[3]);
                float* c0 = sc[2 * njp];
                float* c1 = sc[2 * njp + 1];
                mma16816(c0, qh[kk][0], qh[kk][1], qh[kk][2], qh[kk][3], bh4[0], bh4[1]);
                mma16816(c0, ql[kk][0], ql[kk][1], ql[kk][2], ql[kk][3], bh4[0], bh4[1]);
                mma16816(c0, qh[kk][0], qh[kk][1], qh[kk][2], qh[kk][3], bl4[0], bl4[1]);
                mma16816(c1, qh[kk][0], qh[kk][1], qh[kk][2], qh[kk][3], bh4[2], bh4[3]);
                mma16816(c1, ql[kk][0], ql[kk][1], ql[kk][2], ql[kk][3], bh4[2], bh4[3]);
                mma16816(c1, qh[kk][0], qh[kk][1], qh[kk][2], qh[kk][3], bl4[2], bl4[3]);
            }
        }

        // online softmax; rows r = lane>>2 (ri=0) and r+8 (ri=1)
        float mx[2] = {-1e30f, -1e30f};
        #pragma unroll
        for (int nj = 0; nj < 8; nj++) {
            mx[0] = fmaxf(mx[0], fmaxf(sc[nj][0], sc[nj][1]));
            mx[1] = fmaxf(mx[1], fmaxf(sc[nj][2], sc[nj][3]));
        }
        #pragma unroll
        for (int ri = 0; ri < 2; ri++) {
            mx[ri] = fmaxf(mx[ri], __shfl_xor_sync(0xffffffff, mx[ri], 1));
            mx[ri] = fmaxf(mx[ri], __shfl_xor_sync(0xffffffff, mx[ri], 2));
        }
        float corr[2];
        #pragma unroll
        for (int ri = 0; ri < 2; ri++) {
            float nm = fmaxf(m[ri], mx[ri]);
            corr[ri] = __expf(m[ri] - nm);
            m[ri] = nm;
        }

        // exp in place (sc becomes P) + row-sum
        float ls[2] = {0.f, 0.f};
        #pragma unroll
        for (int nj = 0; nj < 8; nj++) {
            sc[nj][0] = __expf(sc[nj][0] - m[0]);
            sc[nj][1] = __expf(sc[nj][1] - m[0]);
            sc[nj][2] = __expf(sc[nj][2] - m[1]);
            sc[nj][3] = __expf(sc[nj][3] - m[1]);
            ls[0] += sc[nj][0] + sc[nj][1];
            ls[1] += sc[nj][2] + sc[nj][3];
        }
        #pragma unroll
        for (int ri = 0; ri < 2; ri++) {
            ls[ri] += __shfl_xor_sync(0xffffffff, ls[ri], 1);
            ls[ri] += __shfl_xor_sync(0xffffffff, ls[ri], 2);
        }
        lsum[0] = lsum[0] * corr[0] + ls[0];
        lsum[1] = lsum[1] * corr[1] + ls[1];
        #pragma unroll
        for (int nj = 0; nj < 8; nj++) {
            o[nj][0] *= corr[0]; o[nj][1] *= corr[0];
            o[nj][2] *= corr[1]; o[nj][3] *= corr[1];
        }

        // O += P V: single tf32 MMA per k8 step. A-frags from C-frags via shfl.
        #pragma unroll
        for (int kk = 0; kk < 8; kk++) {
            float g0a = __shfl_sync(0xffffffff, sc[kk][0], src_lo);
            float g0b = __shfl_sync(0xffffffff, sc[kk][1], src_lo);
            float h0a = __shfl_sync(0xffffffff, sc[kk][2], src_lo);
            float h0b = __shfl_sync(0xffffffff, sc[kk][3], src_lo);
            float g4a = __shfl_sync(0xffffffff, sc[kk][0], src_hi);
            float g4b = __shfl_sync(0xffffffff, sc[kk][1], src_hi);
            float h4a = __shfl_sync(0xffffffff, sc[kk][2], src_hi);
            float h4b = __shfl_sync(0xffffffff, sc[kk][3], src_hi);
            uint32_t a0 = tf32r(oddc ? g0b : g0a);   // P[g][8kk+c]
            uint32_t a1 = tf32r(oddc ? h0b : h0a);   // P[g+8][8kk+c]
            uint32_t a2 = tf32r(oddc ? g4b : g4a);   // P[g][8kk+c+4]
            uint32_t a3 = tf32r(oddc ? h4b : h4a);   // P[g+8][8kk+c+4]
            #pragma unroll
            for (int njp = 0; njp < 4; njp++) {
                uint32_t b4[4];
                ldsm4(b32_addr(st + A_V, njp * 16, kk * 32, lane, VSTR32),
                      b4[0], b4[1], b4[2], b4[3]);
                mma_tf32(o[2 * njp],     a0, a1, a2, a3, b4[0], b4[1]);
                mma_tf32(o[2 * njp + 1], a0, a1, a2, a3, b4[2], b4[3]);
            }
        }
    }

    // epilogue: normalize + tf32-rounded fp32 write to g_A
    const int b = bh >> 3, h = bh & 7;
    float inv[2] = {1.f / lsum[0], 1.f / lsum[1]};
    #pragma unroll
    for (int ri = 0; ri < 2; ri++) {
        int r = q0 + warp * 16 + (lane >> 2) + ri * 8;
        size_t R = (size_t)(b * SEQ + r) * EMB + h * HDIM;
        #pragma unroll
        for (int nj = 0; nj < 8; nj++) {
            int dd = nj * 8 + (lane & 3) * 2;
            float2 v;
            v.x = tf32f(o[nj][ri * 2 + 0] * inv[ri]);
            v.y = tf32f(o[nj][ri * 2 + 1] * inv[ri]);
            *(float2*)(g_A + R + dd) = v;
        }
    }
}

// ---------------------------------------------------------------------------
extern "C" void kernel_launch(void* const* d_in, const int* in_sizes, int n_in,
                              void* d_out, int out_size)
{
    const float* x     = (const float*)d_in[0];
    const float* w_qkv = (const float*)d_in[1];
    const float* w_o   = (const float*)d_in[2];
    const float* b_o   = (const float*)d_in[3];
    float* out = (float*)d_out;

    cudaFuncSetAttribute(gemm_qkv_tc, cudaFuncAttributeMaxDynamicSharedMemorySize, G_SMEM_SZ);
    cudaFuncSetAttribute(gemm_out_tc, cudaFuncAttributeMaxDynamicSharedMemorySize, O_SMEM_SZ);
    cudaFuncSetAttribute(attn_tc,     cudaFuncAttributeMaxDynamicSharedMemorySize, A_SMEM_SZ);

    __nv_bfloat16 *xh, *xl, *wqh, *wql;
    float* wot;
    cudaGetSymbolAddress((void**)&xh,  g_Xh);  cudaGetSymbolAddress((void**)&xl,  g_Xl);
    cudaGetSymbolAddress((void**)&wqh, g_Wqh); cudaGetSymbolAddress((void**)&wql, g_Wql);
    cudaGetSymbolAddress((void**)&wot, g_WoT);

    split_kernel<<<(M1 * KD + 255) / 256, 256>>>(x, xh, xl, M1 * KD);
    tsplit_kernel<<<(KD * N1 + 255) / 256, 256>>>(w_qkv, wqh, wql, KD, N1);
    ttf32_kernel<<<(KD * EMB + 255) / 256, 256>>>(w_o, wot, KD, EMB);

    gemm_qkv_tc<<<dim3(N1 / 128, M1 / 128), 256, G_SMEM_SZ>>>();
    attn_tc<<<dim3(SEQ / 128, BATCH * NHEAD), 256, A_SMEM_SZ>>>();
    gemm_out_tc<<<dim3(EMB / 128, M1 / 128), 256, O_SMEM_SZ>>>(b_o, out);
}

// round 12
// speedup vs baseline: 1.1731x; 1.0336x over previous
#include <cuda_runtime.h>
#include <cuda_bf16.h>
#include <cstdint>

#define BATCH 2
#define SEQ   2048
#define EMB   512
#define NHEAD 8
#define HDIM  64
#define M1    (BATCH * SEQ)     // 4096
#define N1    (3 * EMB)         // 1536
#define KD    EMB               // 512
#define ATT_SCALE 0.125f
#define LOG2E 1.4426950408889634f

// ---------------------------------------------------------------------------
// helpers
// ---------------------------------------------------------------------------
__device__ __forceinline__ uint32_t smem_u32(const void* p) {
    uint32_t a;
    asm("{ .reg .u64 t; cvta.to.shared.u64 t, %1; cvt.u32.u64 %0, t; }" : "=r"(a) : "l"(p));
    return a;
}
__device__ __forceinline__ void ldsm4(uint32_t addr, uint32_t& r0, uint32_t& r1,
                                      uint32_t& r2, uint32_t& r3) {
    asm volatile("ldmatrix.sync.aligned.m8n8.x4.shared.b16 {%0,%1,%2,%3}, [%4];"
                 : "=r"(r0), "=r"(r1), "=r"(r2), "=r"(r3) : "r"(addr));
}
__device__ __forceinline__ void mma16816(float* c, uint32_t a0, uint32_t a1,
                                         uint32_t a2, uint32_t a3,
                                         uint32_t b0, uint32_t b1) {
    asm volatile("mma.sync.aligned.m16n8k16.row.col.f32.bf16.bf16.f32 "
                 "{%0,%1,%2,%3}, {%4,%5,%6,%7}, {%8,%9}, {%0,%1,%2,%3};"
                 : "+f"(c[0]), "+f"(c[1]), "+f"(c[2]), "+f"(c[3])
                 : "r"(a0), "r"(a1), "r"(a2), "r"(a3), "r"(b0), "r"(b1));
}
__device__ __forceinline__ void mma_tf32(float* c, uint32_t a0, uint32_t a1,
                                         uint32_t a2, uint32_t a3,
                                         uint32_t b0, uint32_t b1) {
    asm volatile("mma.sync.aligned.m16n8k8.row.col.f32.tf32.tf32.f32 "
                 "{%0,%1,%2,%3}, {%4,%5,%6,%7}, {%8,%9}, {%0,%1,%2,%3};"
                 : "+f"(c[0]), "+f"(c[1]), "+f"(c[2]), "+f"(c[3])
                 : "r"(a0), "r"(a1), "r"(a2), "r"(a3), "r"(b0), "r"(b1));
}
__device__ __forceinline__ void cp16(uint32_t dst, const void* src) {
    asm volatile("cp.async.cg.shared.global [%0], [%1], 16;" :: "r"(dst), "l"(src));
}
#define CP_COMMIT() asm volatile("cp.async.commit_group;" ::: "memory")
#define CP_WAIT(n)  asm volatile("cp.async.wait_group %0;" :: "n"(n) : "memory")

__device__ __forceinline__ float fexp2(float x) {
    float r;
    asm("ex2.approx.f32 %0, %1;" : "=f"(r) : "f"(x));
    return r;
}
__device__ __forceinline__ void split2(float v, __nv_bfloat16& h, __nv_bfloat16& l) {
    h = __float2bfloat16(v);
    l = __float2bfloat16(v - __bfloat162float(h));
}
__device__ __forceinline__ uint32_t pack2(__nv_bfloat16 x, __nv_bfloat16 y) {
    __nv_bfloat162 t; t.x = x; t.y = y;
    return *(uint32_t*)&t;
}
__device__ __forceinline__ uint32_t tf32r(float x) {
    uint32_t r;
    asm("cvt.rna.tf32.f32 %0, %1;" : "=r"(r) : "f"(x));
    return r;
}
__device__ __forceinline__ float tf32f(float x) { return __uint_as_float(tf32r(x)); }

// padded-layout ldmatrix addresses (stride bytes)
__device__ __forceinline__ uint32_t a_addr(uint32_t base, int r0, int c0, int lane, int stride) {
    return base + (uint32_t)(r0 + (lane & 15)) * stride + (uint32_t)(c0 + ((lane >> 4) << 3)) * 2;
}
__device__ __forceinline__ uint32_t b_addr(uint32_t base, int n0, int c0, int lane, int stride) {
    int n = n0 + (lane & 7) + ((lane >> 4) << 3);
    int k = c0 + (((lane >> 3) & 1) << 3);
    return base + (uint32_t)n * stride + (uint32_t)k * 2;
}
// fp32 (tf32) variants: k offsets in BYTES
__device__ __forceinline__ uint32_t a32_addr(uint32_t base, int r0, int kbyte, int lane, int stride) {
    return base + (uint32_t)(r0 + (lane & 15)) * stride + (uint32_t)(kbyte + ((lane >> 4) << 4));
}
__device__ __forceinline__ uint32_t b32_addr(uint32_t base, int n0, int kbyte, int lane, int stride) {
    int n = n0 + (lane & 7) + ((lane >> 4) << 3);
    return base + (uint32_t)n * stride + (uint32_t)(kbyte + (((lane >> 3) & 1) << 4));
}
// GEMM bf16 swizzled layout: 64B rows, quad q placed at q ^ ((row>>1)&3)
__device__ __forceinline__ uint32_t gsw(int row, int qb) {
    return (uint32_t)row * 64 + (uint32_t)((((qb >> 4) ^ ((row >> 1) & 3)) << 4));
}
__device__ __forceinline__ uint32_t ga_addr(uint32_t base, int r0, int kk, int lane) {
    int r  = r0 + (lane & 15);
    int qb = kk * 32 + ((lane >> 4) << 4);
    return base + gsw(r, qb);
}
__device__ __forceinline__ uint32_t gb_addr(uint32_t base, int n0, int kk, int lane) {
    int n  = n0 + (lane & 7) + ((lane >> 4) << 3);
    int qb = kk * 32 + (((lane >> 3) & 1) << 4);
    return base + gsw(n, qb);
}

// ---------------------------------------------------------------------------
// Scratch
// ---------------------------------------------------------------------------
__device__ __nv_bfloat16 g_Xh[M1 * KD],  g_Xl[M1 * KD];
__device__ __nv_bfloat16 g_Wqh[N1 * KD], g_Wql[N1 * KD];       // w_qkv^T [N,K]
__device__ __nv_bfloat16 g_Qh[BATCH*NHEAD*SEQ*HDIM], g_Ql[BATCH*NHEAD*SEQ*HDIM];
__device__ __nv_bfloat16 g_Kh[BATCH*NHEAD*SEQ*HDIM], g_Kl[BATCH*NHEAD*SEQ*HDIM];
__device__ float g_Vt[BATCH*NHEAD*HDIM*SEQ];   // V^T fp32 (tf32-rounded)
__device__ float g_A[M1 * EMB];                // attention out fp32 (tf32-rounded)
__device__ float g_WoT[EMB * EMB];             // w_o^T fp32 (tf32-rounded)

// ---------------------------------------------------------------------------
// Fused prep: split x | transpose+split w_qkv | transpose+tf32 w_o
// ---------------------------------------------------------------------------
#define PREP_T1 (M1 * KD)
#define PREP_T2 (KD * N1)
#define PREP_T3 (KD * EMB)
__global__ __launch_bounds__(256) void prep_kernel(const float* __restrict__ x,
                                                   const float* __restrict__ w_qkv,
                                                   const float* __restrict__ w_o)
{
    int i = blockIdx.x * 256 + threadIdx.x;
    if (i < PREP_T1) {
        __nv_bfloat16 a, b; split2(x[i], a, b);
        g_Xh[i] = a; g_Xl[i] = b;
    } else if (i < PREP_T1 + PREP_T2) {
        int j = i - PREP_T1;
        int k = j / N1, n = j - k * N1;
        __nv_bfloat16 a, b; split2(w_qkv[j], a, b);
        g_Wqh[(size_t)n * KD + k] = a; g_Wql[(size_t)n * KD + k] = b;
    } else if (i < PREP_T1 + PREP_T2 + PREP_T3) {
        int j = i - PREP_T1 - PREP_T2;
        int k = j / EMB, n = j - k * EMB;
        g_WoT[(size_t)n * EMB + k] = tf32f(w_o[j]);
    }
}

// ---------------------------------------------------------------------------
// bf16x3 GEMM (QKV projection): BK=32, 3-stage cp.async, 2 CTAs/SM.
// ---------------------------------------------------------------------------
#define G_AH 0
#define G_AL 8192
#define G_BH 16384
#define G_BL 24576
#define G_STAGE 32768
#define G_SMEM_SZ (3 * G_STAGE)

__device__ __forceinline__ void gemm_load_stage(uint32_t sbase,
    const __nv_bfloat16* Ah, const __nv_bfloat16* Al,
    const __nv_bfloat16* Bh, const __nv_bfloat16* Bl,
    int Kdim, int m0, int n0, int k0)
{
    const int tid = threadIdx.x;
    #pragma unroll
    for (int i = 0; i < 2; i++) {
        int idx = tid + i * 256;
        int row = idx >> 2, q = idx & 3;
        uint32_t so = gsw(row, q << 4);
        size_t asrc = (size_t)(m0 + row) * Kdim + k0 + q * 8;
        size_t bsrc = (size_t)(n0 + row) * Kdim + k0 + q * 8;
        cp16(sbase + G_AH + so, Ah + asrc);
        cp16(sbase + G_AL + so, Al + asrc);
        cp16(sbase + G_BH + so, Bh + bsrc);
        cp16(sbase + G_BL + so, Bl + bsrc);
    }
}

__device__ __forceinline__ void gemm_compute_stage(uint32_t sbase, int warp, int lane,
                                                   float acc[2][8][4])
{
    const int wm = warp & 3, wn = warp >> 2;
    #pragma unroll
    for (int kk = 0; kk < 2; kk++) {
        uint32_t ah[2][4], al[2][4];
        #pragma unroll
        for (int mi = 0; mi < 2; mi++) {
            ldsm4(ga_addr(sbase + G_AH, wm * 32 + mi * 16, kk, lane),
                  ah[mi][0], ah[mi][1], ah[mi][2], ah[mi][3]);
            ldsm4(ga_addr(sbase + G_AL, wm * 32 + mi * 16, kk, lane),
                  al[mi][0], al[mi][1], al[mi][2], al[mi][3]);
        }
        #pragma unroll
        for (int njp = 0; njp < 4; njp++) {
            uint32_t bh[4], bl[4];
            ldsm4(gb_addr(sbase + G_BH, wn * 64 + njp * 16, kk, lane),
                  bh[0], bh[1], bh[2], bh[3]);
            ldsm4(gb_addr(sbase + G_BL, wn * 64 + njp * 16, kk, lane),
                  bl[0], bl[1], bl[2], bl[3]);
            #pragma unroll
            for (int mi = 0; mi < 2; mi++) {
                float* c0 = acc[mi][2 * njp];
                float* c1 = acc[mi][2 * njp + 1];
                mma16816(c0, ah[mi][0], ah[mi][1], ah[mi][2], ah[mi][3], bh[0], bh[1]);
                mma16816(c0, al[mi][0], al[mi][1], al[mi][2], al[mi][3], bh[0], bh[1]);
                mma16816(c0, ah[mi][0], ah[mi][1], ah[mi][2], ah[mi][3], bl[0], bl[1]);
                mma16816(c1, ah[mi][0], ah[mi][1], ah[mi][2], ah[mi][3], bh[2], bh[3]);
                mma16816(c1, al[mi][0], al[mi][1], al[mi][2], al[mi][3], bh[2], bh[3]);
                mma16816(c1, ah[mi][0], ah[mi][1], ah[mi][2], ah[mi][3], bl[2], bl[3]);
            }
        }
    }
}

__global__ __launch_bounds__(256, 2) void gemm_qkv_tc()
{
    extern __shared__ char smem[];
    uint32_t sb = smem_u32(smem);
    const int warp = threadIdx.x >> 5, lane = threadIdx.x & 31;
    const int wm = warp & 3, wn = warp >> 2;
    const int m0 = blockIdx.y * 128, n0 = blockIdx.x * 128;

    float acc[2][8][4];
    #pragma unroll
    for (int a = 0; a < 2; a++)
        #pragma unroll
        for (int b = 0; b < 8; b++)
            #pragma unroll
            for (int c = 0; c < 4; c++) acc[a][b][c] = 0.f;

    const int nk = KD / 32;
    gemm_load_stage(sb,           g_Xh, g_Xl, g_Wqh, g_Wql, KD, m0, n0, 0);
    CP_COMMIT();
    gemm_load_stage(sb + G_STAGE, g_Xh, g_Xl, g_Wqh, g_Wql, KD, m0, n0, 32);
    CP_COMMIT();
    for (int kc = 0; kc < nk; kc++) {
        if (kc + 1 < nk) { CP_WAIT(1); } else { CP_WAIT(0); }
        __syncthreads();
        if (kc + 2 < nk) {
            gemm_load_stage(sb + ((kc + 2) % 3) * G_STAGE, g_Xh, g_Xl, g_Wqh, g_Wql,
                            KD, m0, n0, (kc + 2) * 32);
            CP_COMMIT();
        }
        gemm_compute_stage(sb + (kc % 3) * G_STAGE, warp, lane, acc);
    }

    const int region = n0 >> 9;  // 0=Q 1=K 2=V
    // Q gets ATT_SCALE * log2(e) so softmax can run in exp2 domain.
    const float qscale = ATT_SCALE * LOG2E;
    #pragma unroll
    for (int mi = 0; mi < 2; mi++) {
        #pragma unroll
        for (int ri = 0; ri < 2; ri++) {
            int r = m0 + wm * 32 + mi * 16 + (lane >> 2) + ri * 8;
            int b = r >> 11, s = r & 2047;
            #pragma unroll
            for (int nj = 0; nj < 8; nj++) {
                int c = n0 + wn * 64 + nj * 8 + (lane & 3) * 2;
                int within = c & 511;
                int h = within >> 6, dd = within & 63;
                float v0 = acc[mi][nj][ri * 2 + 0];
                float v1 = acc[mi][nj][ri * 2 + 1];
                if (region == 0) { v0 *= qscale; v1 *= qscale; }
                if (region < 2) {
                    __nv_bfloat16 h0, l0, h1, l1;
                    split2(v0, h0, l0); split2(v1, h1, l1);
                    __nv_bfloat16* H = region == 0 ? g_Qh : g_Kh;
                    __nv_bfloat16* L = region == 0 ? g_Ql : g_Kl;
                    size_t idx = (((size_t)(b * NHEAD + h) * SEQ + s) * HDIM + dd);
                    *(uint32_t*)(H + idx) = pack2(h0, h1);
                    *(uint32_t*)(L + idx) = pack2(l0, l1);
                } else {
                    size_t base = ((size_t)(b * NHEAD + h) * HDIM + dd) * SEQ + s;
                    g_Vt[base]       = tf32f(v0);
                    g_Vt[base + SEQ] = tf32f(v1);
                }
            }
        }
    }
}

// ---------------------------------------------------------------------------
// Out projection (tf32): out = g_A @ g_WoT^T + bias. Tiles 128m x 64n,
// grid (8, 32) = 256 CTAs (full wave). Warp tile 32x32. 3-stage, 2 CTAs/SM.
// ---------------------------------------------------------------------------
#define O_STR 144
#define O_A 0
#define O_B 18432
#define O_STAGE 27648
#define O_SMEM_SZ (3 * O_STAGE)

__global__ __launch_bounds__(256, 2) void gemm_out_tc(const float* __restrict__ bias,
                                                      float* __restrict__ out)
{
    extern __shared__ char smem[];
    uint32_t sb = smem_u32(smem);
    const int tid = threadIdx.x;
    const int warp = tid >> 5, lane = tid & 31;
    const int wm = warp & 3, wn = warp >> 2;
    const int m0 = blockIdx.y * 128, n0 = blockIdx.x * 64;

    float acc[2][4][4];
    #pragma unroll
    for (int a = 0; a < 2; a++)
        #pragma unroll
        for (int b = 0; b < 4; b++)
            #pragma unroll
            for (int c = 0; c < 4; c++) acc[a][b][c] = 0.f;

    auto load_stage = [&](uint32_t sbase, int k0) {
        #pragma unroll
        for (int i = 0; i < 4; i++) {
            int idx = tid + i * 256;          // A: 128 rows x 8 quads
            int row = idx >> 3, q = idx & 7;
            uint32_t so = (uint32_t)row * O_STR + q * 16;
            cp16(sbase + O_A + so, g_A + (size_t)(m0 + row) * EMB + k0 + q * 4);
        }
        #pragma unroll
        for (int i = 0; i < 2; i++) {
            int idx = tid + i * 256;          // B: 64 rows x 8 quads
            int row = idx >> 3, q = idx & 7;
            uint32_t so = (uint32_t)row * O_STR + q * 16;
            cp16(sbase + O_B + so, g_WoT + (size_t)(n0 + row) * EMB + k0 + q * 4);
        }
    };

    const int nk = EMB / 32;
    load_stage(sb,           0);  CP_COMMIT();
    load_stage(sb + O_STAGE, 32); CP_COMMIT();
    for (int kc = 0; kc < nk; kc++) {
        if (kc + 1 < nk) { CP_WAIT(1); } else { CP_WAIT(0); }
        __syncthreads();
        if (kc + 2 < nk) { load_stage(sb + ((kc + 2) % 3) * O_STAGE, (kc + 2) * 32); CP_COMMIT(); }
        const uint32_t st = sb + (kc % 3) * O_STAGE;

        #pragma unroll
        for (int kk = 0; kk < 4; kk++) {          // k8 steps
            uint32_t a4[2][4];
            #pragma unroll
            for (int mi = 0; mi < 2; mi++)
                ldsm4(a32_addr(st + O_A, wm * 32 + mi * 16, kk * 32, lane, O_STR),
                      a4[mi][0], a4[mi][1], a4[mi][2], a4[mi][3]);
            #pragma unroll
            for (int njp = 0; njp < 2; njp++) {   // each covers 2 n8 tiles
                uint32_t b4[4];
                ldsm4(b32_addr(st + O_B, wn * 32 + njp * 16, kk * 32, lane, O_STR),
                      b4[0], b4[1], b4[2], b4[3]);
                #pragma unroll
                for (int mi = 0; mi < 2; mi++) {
                    mma_tf32(acc[mi][2 * njp],     a4[mi][0], a4[mi][1], a4[mi][2], a4[mi][3], b4[0], b4[1]);
                    mma_tf32(acc[mi][2 * njp + 1], a4[mi][0], a4[mi][1], a4[mi][2], a4[mi][3], b4[2], b4[3]);
                }
            }
        }
    }

    #pragma unroll
    for (int mi = 0; mi < 2; mi++) {
        #pragma unroll
        for (int ri = 0; ri < 2; ri++) {
            int r = m0 + wm * 32 + mi * 16 + (lane >> 2) + ri * 8;
            #pragma unroll
            for (int nj = 0; nj < 4; nj++) {
                int c = n0 + wn * 32 + nj * 8 + (lane & 3) * 2;
                float2 v;
                v.x = acc[mi][nj][ri * 2 + 0] + bias[c];
                v.y = acc[mi][nj][ri * 2 + 1] + bias[c + 1];
                *(float2*)(out + (size_t)r * EMB + c) = v;
            }
        }
    }
}

// ---------------------------------------------------------------------------
// Flash attention (exp2 domain). grid (16, 16), 256 threads, 2 CTAs/SM.
// QK^T bf16x3; P·V single tf32 (A-frags from S C-frags via quad shfl).
// ---------------------------------------------------------------------------
#define ASTR 144
#define VSTR32 272
#define A_KH 0
#define A_KL 9216
#define A_V  18432
#define A_STAGE 35840
#define A_SMEM_SZ (3 * A_STAGE)

__device__ __forceinline__ void attn_load_stage(uint32_t sbase, size_t qk_base,
                                                size_t v_base, int t)
{
    const int tid = threadIdx.x;
    #pragma unroll
    for (int i = 0; i < 2; i++) {
        int idx = tid + i * 256;
        int row = idx >> 3, q = idx & 7;
        uint32_t so = (uint32_t)row * ASTR + q * 16;
        size_t src = qk_base + (size_t)(t * 64 + row) * HDIM + q * 8;
        cp16(sbase + A_KH + so, g_Kh + src);
        cp16(sbase + A_KL + so, g_Kl + src);
    }
    #pragma unroll
    for (int i = 0; i < 4; i++) {
        int idx = tid + i * 256;
        int row = idx >> 4, q = idx & 15;
        uint32_t so = (uint32_t)row * VSTR32 + q * 16;
        size_t src = v_base + (size_t)row * SEQ + t * 64 + q * 4;
        cp16(sbase + A_V + so, g_Vt + src);
    }
}

__global__ __launch_bounds__(256, 2) void attn_tc()
{
    extern __shared__ char smem[];
    uint32_t sb = smem_u32(smem);
    const int tid = threadIdx.x;
    const int warp = tid >> 5, lane = tid & 31;
    const int bh = blockIdx.y;
    const int q0 = blockIdx.x * 128;
    const size_t qk_base = (size_t)bh * SEQ * HDIM;
    const size_t v_base  = (size_t)bh * HDIM * SEQ;

    #pragma unroll
    for (int i = 0; i < 4; i++) {
        int idx = tid + i * 256;
        int row = idx >> 3, q = idx & 7;
        uint32_t so = (uint32_t)row * ASTR + q * 16;
        size_t src = qk_base + (size_t)(q0 + row) * HDIM + q * 8;
        *(uint4*)(smem + so)         = *(const uint4*)(g_Qh + src);
        *(uint4*)(smem + 18432 + so) = *(const uint4*)(g_Ql + src);
    }
    __syncthreads();
    uint32_t qh[4][4], ql[4][4];
    #pragma unroll
    for (int kk = 0; kk < 4; kk++) {
        ldsm4(a_addr(sb,         warp * 16, kk * 16, lane, ASTR),
              qh[kk][0], qh[kk][1], qh[kk][2], qh[kk][3]);
        ldsm4(a_addr(sb + 18432, warp * 16, kk * 16, lane, ASTR),
              ql[kk][0], ql[kk][1], ql[kk][2], ql[kk][3]);
    }
    __syncthreads();

    float o[8][4];
    #pragma unroll
    for (int a = 0; a < 8; a++)
        #pragma unroll
        for (int c = 0; c < 4; c++) o[a][c] = 0.f;
    float m[2] = {-1e30f, -1e30f};
    float lsum[2] = {0.f, 0.f};

    const int NT = SEQ / 64;
    attn_load_stage(sb,           qk_base, v_base, 0); CP_COMMIT();
    attn_load_stage(sb + A_STAGE, qk_base, v_base, 1); CP_COMMIT();

    const int src_lo = (lane & ~3) | ((lane >> 1) & 1);
    const int src_hi = src_lo | 2;
    const bool oddc = lane & 1;

    for (int t = 0; t < NT; t++) {
        if (t + 1 < NT) { CP_WAIT(1); } else { CP_WAIT(0); }
        __syncthreads();
        if (t + 2 < NT) {
            attn_load_stage(sb + ((t + 2) % 3) * A_STAGE, qk_base, v_base, t + 2);
            CP_COMMIT();
        }
        const uint32_t st = sb + (t % 3) * A_STAGE;

        // S' = (Q*log2e*scale) K^T  (bf16x3)
        float sc[8][4];
        #pragma unroll
        for (int a = 0; a < 8; a++)
            #pragma unroll
            for (int c = 0; c < 4; c++) sc[a][c] = 0.f;

        #pragma unroll
        for (int kk = 0; kk < 4; kk++) {
            #pragma unroll
            for (int njp = 0; njp < 4; njp++) {
                uint32_t bh4[4], bl4[4];
                ldsm4(b_addr(st + A_KH, njp * 16, kk * 16, lane, ASTR), bh4[0], bh4[1], bh4[2], bh4[3]);
                ldsm4(b_addr(st + A_KL, njp * 16, kk * 16, lane, ASTR), bl4[0], bl4[1], bl4[2], bl4[3]);
                float* c0 = sc[2 * njp];
                float* c1 = sc[2 * njp + 1];
                mma16816(c0, qh[kk][0], qh[kk][1], qh[kk][2], qh[kk][3], bh4[0], bh4[1]);
                mma16816(c0, ql[kk][0], ql[kk][1], ql[kk][2], ql[kk][3], bh4[0], bh4[1]);
                mma16816(c0, qh[kk][0], qh[kk][1], qh[kk][2], qh[kk][3], bl4[0], bl4[1]);
                mma16816(c1, qh[kk][0], qh[kk][1], qh[kk][2], qh[kk][3], bh4[2], bh4[3]);
                mma16816(c1, ql[kk][0], ql[kk][1], ql[kk][2], ql[kk][3], bh4[2], bh4[3]);
                mma16816(c1, qh[kk][0], qh[kk][1], qh[kk][2], qh[kk][3], bl4[2], bl4[3]);
            }
        }

        // online softmax in exp2 domain
        float mx[2] = {-1e30f, -1e30f};
        #pragma unroll
        for (int nj = 0; nj < 8; nj++) {
            mx[0] = fmaxf(mx[0], fmaxf(sc[nj][0], sc[nj][1]));
            mx[1] = fmaxf(mx[1], fmaxf(sc[nj][2], sc[nj][3]));
        }
        #pragma unroll
        for (int ri = 0; ri < 2; ri++) {
            mx[ri] = fmaxf(mx[ri], __shfl_xor_sync(0xffffffff, mx[ri], 1));
            mx[ri] = fmaxf(mx[ri], __shfl_xor_sync(0xffffffff, mx[ri], 2));
        }
        float corr[2];
        #pragma unroll
        for (int ri = 0; ri < 2; ri++) {
            float nm = fmaxf(m[ri], mx[ri]);
            corr[ri] = fexp2(m[ri] - nm);
            m[ri] = nm;
        }

        float ls[2] = {0.f, 0.f};
        #pragma unroll
        for (int nj = 0; nj < 8; nj++) {
            sc[nj][0] = fexp2(sc[nj][0] - m[0]);
            sc[nj][1] = fexp2(sc[nj][1] - m[0]);
            sc[nj][2] = fexp2(sc[nj][2] - m[1]);
            sc[nj][3] = fexp2(sc[nj][3] - m[1]);
            ls[0] += sc[nj][0] + sc[nj][1];
            ls[1] += sc[nj][2] + sc[nj][3];
        }
        #pragma unroll
        for (int ri = 0; ri < 2; ri++) {
            ls[ri] += __shfl_xor_sync(0xffffffff, ls[ri], 1);
            ls[ri] += __shfl_xor_sync(0xffffffff, ls[ri], 2);
        }
        lsum[0] = lsum[0] * corr[0] + ls[0];
        lsum[1] = lsum[1] * corr[1] + ls[1];
        #pragma unroll
        for (int nj = 0; nj < 8; nj++) {
            o[nj][0] *= corr[0]; o[nj][1] *= corr[0];
            o[nj][2] *= corr[1]; o[nj][3] *= corr[1];
        }

        // O += P V (tf32). A-frags from C-frags via quad shfl.
        #pragma unroll
        for (int kk = 0; kk < 8; kk++) {
            float g0a = __shfl_sync(0xffffffff, sc[kk][0], src_lo);
            float g0b = __shfl_sync(0xffffffff, sc[kk][1], src_lo);
            float h0a = __shfl_sync(0xffffffff, sc[kk][2], src_lo);
            float h0b = __shfl_sync(0xffffffff, sc[kk][3], src_lo);
            float g4a = __shfl_sync(0xffffffff, sc[kk][0], src_hi);
            float g4b = __shfl_sync(0xffffffff, sc[kk][1], src_hi);
            float h4a = __shfl_sync(0xffffffff, sc[kk][2], src_hi);
            float h4b = __shfl_sync(0xffffffff, sc[kk][3], src_hi);
            uint32_t a0 = tf32r(oddc ? g0b : g0a);
            uint32_t a1 = tf32r(oddc ? h0b : h0a);
            uint32_t a2 = tf32r(oddc ? g4b : g4a);
            uint32_t a3 = tf32r(oddc ? h4b : h4a);
            #pragma unroll
            for (int njp = 0; njp < 4; njp++) {
                uint32_t b4[4];
                ldsm4(b32_addr(st + A_V, njp * 16, kk * 32, lane, VSTR32),
                      b4[0], b4[1], b4[2], b4[3]);
                mma_tf32(o[2 * njp],     a0, a1, a2, a3, b4[0], b4[1]);
                mma_tf32(o[2 * njp + 1], a0, a1, a2, a3, b4[2], b4[3]);
            }
        }
    }

    // epilogue
    const int b = bh >> 3, h = bh & 7;
    float inv[2] = {1.f / lsum[0], 1.f / lsum[1]};
    #pragma unroll
    for (int ri = 0; ri < 2; ri++) {
        int r = q0 + warp * 16 + (lane >> 2) + ri * 8;
        size_t R = (size_t)(b * SEQ + r) * EMB + h * HDIM;
        #pragma unroll
        for (int nj = 0; nj < 8; nj++) {
            int dd = nj * 8 + (lane & 3) * 2;
            float2 v;
            v.x = tf32f(o[nj][ri * 2 + 0] * inv[ri]);
            v.y = tf32f(o[nj][ri * 2 + 1] * inv[ri]);
            *(float2*)(g_A + R + dd) = v;
        }
    }
}

// ---------------------------------------------------------------------------
extern "C" void kernel_launch(void* const* d_in, const int* in_sizes, int n_in,
                              void* d_out, int out_size)
{
    const float* x     = (const float*)d_in[0];
    const float* w_qkv = (const float*)d_in[1];
    const float* w_o   = (const float*)d_in[2];
    const float* b_o   = (const float*)d_in[3];
    float* out = (float*)d_out;

    cudaFuncSetAttribute(gemm_qkv_tc, cudaFuncAttributeMaxDynamicSharedMemorySize, G_SMEM_SZ);
    cudaFuncSetAttribute(gemm_out_tc, cudaFuncAttributeMaxDynamicSharedMemorySize, O_SMEM_SZ);
    cudaFuncSetAttribute(attn_tc,     cudaFuncAttributeMaxDynamicSharedMemorySize, A_SMEM_SZ);

    const int prep_total = PREP_T1 + PREP_T2 + PREP_T3;
    prep_kernel<<<(prep_total + 255) / 256, 256>>>(x, w_qkv, w_o);

    gemm_qkv_tc<<<dim3(N1 / 128, M1 / 128), 256, G_SMEM_SZ>>>();
    attn_tc<<<dim3(SEQ / 128, BATCH * NHEAD), 256, A_SMEM_SZ>>>();
    gemm_out_tc<<<dim3(EMB / 64, M1 / 128), 256, O_SMEM_SZ>>>(b_o, out);
}

// round 13
// speedup vs baseline: 1.4299x; 1.2189x over previous
#include <cuda_runtime.h>
#include <cuda_bf16.h>
#include <cuda_fp16.h>
#include <cstdint>

#define BATCH 2
#define SEQ   2048
#define EMB   512
#define NHEAD 8
#define HDIM  64
#define M1    (BATCH * SEQ)     // 4096
#define N1    (3 * EMB)         // 1536
#define KD    EMB               // 512
#define ATT_SCALE 0.125f
#define LOG2E 1.4426950408889634f

// ---------------------------------------------------------------------------
// helpers
// ---------------------------------------------------------------------------
__device__ __forceinline__ uint32_t smem_u32(const void* p) {
    uint32_t a;
    asm("{ .reg .u64 t; cvta.to.shared.u64 t, %1; cvt.u32.u64 %0, t; }" : "=r"(a) : "l"(p));
    return a;
}
__device__ __forceinline__ void ldsm4(uint32_t addr, uint32_t& r0, uint32_t& r1,
                                      uint32_t& r2, uint32_t& r3) {
    asm volatile("ldmatrix.sync.aligned.m8n8.x4.shared.b16 {%0,%1,%2,%3}, [%4];"
                 : "=r"(r0), "=r"(r1), "=r"(r2), "=r"(r3) : "r"(addr));
}
__device__ __forceinline__ void mma16816(float* c, uint32_t a0, uint32_t a1,
                                         uint32_t a2, uint32_t a3,
                                         uint32_t b0, uint32_t b1) {
    asm volatile("mma.sync.aligned.m16n8k16.row.col.f32.bf16.bf16.f32 "
                 "{%0,%1,%2,%3}, {%4,%5,%6,%7}, {%8,%9}, {%0,%1,%2,%3};"
                 : "+f"(c[0]), "+f"(c[1]), "+f"(c[2]), "+f"(c[3])
                 : "r"(a0), "r"(a1), "r"(a2), "r"(a3), "r"(b0), "r"(b1));
}
__device__ __forceinline__ void mma16816f(float* c, uint32_t a0, uint32_t a1,
                                          uint32_t a2, uint32_t a3,
                                          uint32_t b0, uint32_t b1) {
    asm volatile("mma.sync.aligned.m16n8k16.row.col.f32.f16.f16.f32 "
                 "{%0,%1,%2,%3}, {%4,%5,%6,%7}, {%8,%9}, {%0,%1,%2,%3};"
                 : "+f"(c[0]), "+f"(c[1]), "+f"(c[2]), "+f"(c[3])
                 : "r"(a0), "r"(a1), "r"(a2), "r"(a3), "r"(b0), "r"(b1));
}
__device__ __forceinline__ void cp16(uint32_t dst, const void* src) {
    asm volatile("cp.async.cg.shared.global [%0], [%1], 16;" :: "r"(dst), "l"(src));
}
#define CP_COMMIT() asm volatile("cp.async.commit_group;" ::: "memory")
#define CP_WAIT(n)  asm volatile("cp.async.wait_group %0;" :: "n"(n) : "memory")

__device__ __forceinline__ float fexp2(float x) {
    float r;
    asm("ex2.approx.f32 %0, %1;" : "=f"(r) : "f"(x));
    return r;
}
__device__ __forceinline__ void split2(float v, __nv_bfloat16& h, __nv_bfloat16& l) {
    h = __float2bfloat16(v);
    l = __float2bfloat16(v - __bfloat162float(h));
}
__device__ __forceinline__ uint32_t pack2(__nv_bfloat16 x, __nv_bfloat16 y) {
    __nv_bfloat162 t; t.x = x; t.y = y;
    return *(uint32_t*)&t;
}
__device__ __forceinline__ uint32_t h2pack(float x, float y) {
    __half2 t = __floats2half2_rn(x, y);   // .x (low) = x
    return *(uint32_t*)&t;
}

// padded-layout ldmatrix addresses (stride bytes, 16-bit elements)
__device__ __forceinline__ uint32_t a_addr(uint32_t base, int r0, int c0, int lane, int stride) {
    return base + (uint32_t)(r0 + (lane & 15)) * stride + (uint32_t)(c0 + ((lane >> 4) << 3)) * 2;
}
__device__ __forceinline__ uint32_t b_addr(uint32_t base, int n0, int c0, int lane, int stride) {
    int n = n0 + (lane & 7) + ((lane >> 4) << 3);
    int k = c0 + (((lane >> 3) & 1) << 3);
    return base + (uint32_t)n * stride + (uint32_t)k * 2;
}
// GEMM swizzled layout: 64B rows, quad q placed at q ^ ((row>>1)&3)
__device__ __forceinline__ uint32_t gsw(int row, int qb) {
    return (uint32_t)row * 64 + (uint32_t)((((qb >> 4) ^ ((row >> 1) & 3)) << 4));
}
__device__ __forceinline__ uint32_t ga_addr(uint32_t base, int r0, int kk, int lane) {
    int r  = r0 + (lane & 15);
    int qb = kk * 32 + ((lane >> 4) << 4);
    return base + gsw(r, qb);
}
__device__ __forceinline__ uint32_t gb_addr(uint32_t base, int n0, int kk, int lane) {
    int n  = n0 + (lane & 7) + ((lane >> 4) << 3);
    int qb = kk * 32 + (((lane >> 3) & 1) << 4);
    return base + gsw(n, qb);
}

// ---------------------------------------------------------------------------
// Scratch
// ---------------------------------------------------------------------------
__device__ __nv_bfloat16 g_Xh[M1 * KD],  g_Xl[M1 * KD];
__device__ __nv_bfloat16 g_Wqh[N1 * KD], g_Wql[N1 * KD];       // w_qkv^T [N,K]
__device__ __nv_bfloat16 g_Qh[BATCH*NHEAD*SEQ*HDIM], g_Ql[BATCH*NHEAD*SEQ*HDIM];
__device__ __nv_bfloat16 g_Kh[BATCH*NHEAD*SEQ*HDIM], g_Kl[BATCH*NHEAD*SEQ*HDIM];
__device__ __half g_Vh[BATCH*NHEAD*HDIM*SEQ];   // V^T fp16
__device__ __half g_A16[M1 * EMB];              // attention out fp16
__device__ __half g_Wo16[EMB * EMB];            // w_o^T fp16

// ---------------------------------------------------------------------------
// Fused prep
// ---------------------------------------------------------------------------
#define PREP_T1 (M1 * KD)
#define PREP_T2 (KD * N1)
#define PREP_T3 (KD * EMB)
__global__ __launch_bounds__(256) void prep_kernel(const float* __restrict__ x,
                                                   const float* __restrict__ w_qkv,
                                                   const float* __restrict__ w_o)
{
    int i = blockIdx.x * 256 + threadIdx.x;
    if (i < PREP_T1) {
        __nv_bfloat16 a, b; split2(x[i], a, b);
        g_Xh[i] = a; g_Xl[i] = b;
    } else if (i < PREP_T1 + PREP_T2) {
        int j = i - PREP_T1;
        int k = j / N1, n = j - k * N1;
        __nv_bfloat16 a, b; split2(w_qkv[j], a, b);
        g_Wqh[(size_t)n * KD + k] = a; g_Wql[(size_t)n * KD + k] = b;
    } else if (i < PREP_T1 + PREP_T2 + PREP_T3) {
        int j = i - PREP_T1 - PREP_T2;
        int k = j / EMB, n = j - k * EMB;
        g_Wo16[(size_t)n * EMB + k] = __float2half(w_o[j]);
    }
}

// ---------------------------------------------------------------------------
// bf16x3 GEMM (QKV projection): BK=32, 3-stage cp.async, 2 CTAs/SM.
// ---------------------------------------------------------------------------
#define G_AH 0
#define G_AL 8192
#define G_BH 16384
#define G_BL 24576
#define G_STAGE 32768
#define G_SMEM_SZ (3 * G_STAGE)

__device__ __forceinline__ void gemm_load_stage(uint32_t sbase,
    const __nv_bfloat16* Ah, const __nv_bfloat16* Al,
    const __nv_bfloat16* Bh, const __nv_bfloat16* Bl,
    int Kdim, int m0, int n0, int k0)
{
    const int tid = threadIdx.x;
    #pragma unroll
    for (int i = 0; i < 2; i++) {
        int idx = tid + i * 256;
        int row = idx >> 2, q = idx & 3;
        uint32_t so = gsw(row, q << 4);
        size_t asrc = (size_t)(m0 + row) * Kdim + k0 + q * 8;
        size_t bsrc = (size_t)(n0 + row) * Kdim + k0 + q * 8;
        cp16(sbase + G_AH + so, Ah + asrc);
        cp16(sbase + G_AL + so, Al + asrc);
        cp16(sbase + G_BH + so, Bh + bsrc);
        cp16(sbase + G_BL + so, Bl + bsrc);
    }
}

__device__ __forceinline__ void gemm_compute_stage(uint32_t sbase, int warp, int lane,
                                                   float acc[2][8][4])
{
    const int wm = warp & 3, wn = warp >> 2;
    #pragma unroll
    for (int kk = 0; kk < 2; kk++) {
        uint32_t ah[2][4], al[2][4];
        #pragma unroll
        for (int mi = 0; mi < 2; mi++) {
            ldsm4(ga_addr(sbase + G_AH, wm * 32 + mi * 16, kk, lane),
                  ah[mi][0], ah[mi][1], ah[mi][2], ah[mi][3]);
            ldsm4(ga_addr(sbase + G_AL, wm * 32 + mi * 16, kk, lane),
                  al[mi][0], al[mi][1], al[mi][2], al[mi][3]);
        }
        #pragma unroll
        for (int njp = 0; njp < 4; njp++) {
            uint32_t bh[4], bl[4];
            ldsm4(gb_addr(sbase + G_BH, wn * 64 + njp * 16, kk, lane),
                  bh[0], bh[1], bh[2], bh[3]);
            ldsm4(gb_addr(sbase + G_BL, wn * 64 + njp * 16, kk, lane),
                  bl[0], bl[1], bl[2], bl[3]);
            #pragma unroll
            for (int mi = 0; mi < 2; mi++) {
                float* c0 = acc[mi][2 * njp];
                float* c1 = acc[mi][2 * njp + 1];
                mma16816(c0, ah[mi][0], ah[mi][1], ah[mi][2], ah[mi][3], bh[0], bh[1]);
                mma16816(c0, al[mi][0], al[mi][1], al[mi][2], al[mi][3], bh[0], bh[1]);
                mma16816(c0, ah[mi][0], ah[mi][1], ah[mi][2], ah[mi][3], bl[0], bl[1]);
                mma16816(c1, ah[mi][0], ah[mi][1], ah[mi][2], ah[mi][3], bh[2], bh[3]);
                mma16816(c1, al[mi][0], al[mi][1], al[mi][2], al[mi][3], bh[2], bh[3]);
                mma16816(c1, ah[mi][0], ah[mi][1], ah[mi][2], ah[mi][3], bl[2], bl[3]);
            }
        }
    }
}

__global__ __launch_bounds__(256, 2) void gemm_qkv_tc()
{
    extern __shared__ char smem[];
    uint32_t sb = smem_u32(smem);
    const int warp = threadIdx.x >> 5, lane = threadIdx.x & 31;
    const int wm = warp & 3, wn = warp >> 2;
    const int m0 = blockIdx.y * 128, n0 = blockIdx.x * 128;

    float acc[2][8][4];
    #pragma unroll
    for (int a = 0; a < 2; a++)
        #pragma unroll
        for (int b = 0; b < 8; b++)
            #pragma unroll
            for (int c = 0; c < 4; c++) acc[a][b][c] = 0.f;

    const int nk = KD / 32;
    gemm_load_stage(sb,           g_Xh, g_Xl, g_Wqh, g_Wql, KD, m0, n0, 0);
    CP_COMMIT();
    gemm_load_stage(sb + G_STAGE, g_Xh, g_Xl, g_Wqh, g_Wql, KD, m0, n0, 32);
    CP_COMMIT();
    for (int kc = 0; kc < nk; kc++) {
        if (kc + 1 < nk) { CP_WAIT(1); } else { CP_WAIT(0); }
        __syncthreads();
        if (kc + 2 < nk) {
            gemm_load_stage(sb + ((kc + 2) % 3) * G_STAGE, g_Xh, g_Xl, g_Wqh, g_Wql,
                            KD, m0, n0, (kc + 2) * 32);
            CP_COMMIT();
        }
        gemm_compute_stage(sb + (kc % 3) * G_STAGE, warp, lane, acc);
    }

    const int region = n0 >> 9;  // 0=Q 1=K 2=V
    const float qscale = ATT_SCALE * LOG2E;   // exp2-domain softmax
    #pragma unroll
    for (int mi = 0; mi < 2; mi++) {
        #pragma unroll
        for (int ri = 0; ri < 2; ri++) {
            int r = m0 + wm * 32 + mi * 16 + (lane >> 2) + ri * 8;
            int b = r >> 11, s = r & 2047;
            #pragma unroll
            for (int nj = 0; nj < 8; nj++) {
                int c = n0 + wn * 64 + nj * 8 + (lane & 3) * 2;
                int within = c & 511;
                int h = within >> 6, dd = within & 63;
                float v0 = acc[mi][nj][ri * 2 + 0];
                float v1 = acc[mi][nj][ri * 2 + 1];
                if (region == 0) { v0 *= qscale; v1 *= qscale; }
                if (region < 2) {
                    __nv_bfloat16 h0, l0, h1, l1;
                    split2(v0, h0, l0); split2(v1, h1, l1);
                    __nv_bfloat16* H = region == 0 ? g_Qh : g_Kh;
                    __nv_bfloat16* L = region == 0 ? g_Ql : g_Kl;
                    size_t idx = (((size_t)(b * NHEAD + h) * SEQ + s) * HDIM + dd);
                    *(uint32_t*)(H + idx) = pack2(h0, h1);
                    *(uint32_t*)(L + idx) = pack2(l0, l1);
                } else {
                    size_t base = ((size_t)(b * NHEAD + h) * HDIM + dd) * SEQ + s;
                    g_Vh[base]       = __float2half(v0);
                    g_Vh[base + SEQ] = __float2half(v1);
                }
            }
        }
    }
}

// ---------------------------------------------------------------------------
// Out projection (fp16): out = g_A16 @ g_Wo16^T + bias. Tiles 128m x 64n,
// grid (8, 32) = 256 CTAs. Warp tile 32x32. BK=32, 3-stage, 2 CTAs/SM.
// ---------------------------------------------------------------------------
#define O_A 0
#define O_B 8192
#define O_STAGE 12288
#define O_SMEM_SZ (3 * O_STAGE)

__global__ __launch_bounds__(256, 2) void gemm_out_tc(const float* __restrict__ bias,
                                                      float* __restrict__ out)
{
    extern __shared__ char smem[];
    uint32_t sb = smem_u32(smem);
    const int tid = threadIdx.x;
    const int warp = tid >> 5, lane = tid & 31;
    const int wm = warp & 3, wn = warp >> 2;
    const int m0 = blockIdx.y * 128, n0 = blockIdx.x * 64;

    float acc[2][4][4];
    #pragma unroll
    for (int a = 0; a < 2; a++)
        #pragma unroll
        for (int b = 0; b < 4; b++)
            #pragma unroll
            for (int c = 0; c < 4; c++) acc[a][b][c] = 0.f;

    auto load_stage = [&](uint32_t sbase, int k0) {
        #pragma unroll
        for (int i = 0; i < 2; i++) {
            int idx = tid + i * 256;          // A: 128 rows x 4 quads (64B rows)
            int row = idx >> 2, q = idx & 3;
            cp16(sbase + O_A + gsw(row, q << 4),
                 g_A16 + (size_t)(m0 + row) * EMB + k0 + q * 8);
        }
        {
            int idx = tid;                    // B: 64 rows x 4 quads
            int row = idx >> 2, q = idx & 3;
            cp16(sbase + O_B + gsw(row, q << 4),
                 g_Wo16 + (size_t)(n0 + row) * EMB + k0 + q * 8);
        }
    };

    const int nk = EMB / 32;
    load_stage(sb,           0);  CP_COMMIT();
    load_stage(sb + O_STAGE, 32); CP_COMMIT();
    for (int kc = 0; kc < nk; kc++) {
        if (kc + 1 < nk) { CP_WAIT(1); } else { CP_WAIT(0); }
        __syncthreads();
        if (kc + 2 < nk) { load_stage(sb + ((kc + 2) % 3) * O_STAGE, (kc + 2) * 32); CP_COMMIT(); }
        const uint32_t st = sb + (kc % 3) * O_STAGE;

        #pragma unroll
        for (int kk = 0; kk < 2; kk++) {          // 2 k16 chunks
            uint32_t a4[2][4];
            #pragma unroll
            for (int mi = 0; mi < 2; mi++)
                ldsm4(ga_addr(st + O_A, wm * 32 + mi * 16, kk, lane),
                      a4[mi][0], a4[mi][1], a4[mi][2], a4[mi][3]);
            #pragma unroll
            for (int njp = 0; njp < 2; njp++) {
                uint32_t b4[4];
                ldsm4(gb_addr(st + O_B, wn * 32 + njp * 16, kk, lane),
                      b4[0], b4[1], b4[2], b4[3]);
                #pragma unroll
                for (int mi = 0; mi < 2; mi++) {
                    mma16816f(acc[mi][2 * njp],     a4[mi][0], a4[mi][1], a4[mi][2], a4[mi][3], b4[0], b4[1]);
                    mma16816f(acc[mi][2 * njp + 1], a4[mi][0], a4[mi][1], a4[mi][2], a4[mi][3], b4[2], b4[3]);
                }
            }
        }
    }

    #pragma unroll
    for (int mi = 0; mi < 2; mi++) {
        #pragma unroll
        for (int ri = 0; ri < 2; ri++) {
            int r = m0 + wm * 32 + mi * 16 + (lane >> 2) + ri * 8;
            #pragma unroll
            for (int nj = 0; nj < 4; nj++) {
                int c = n0 + wn * 32 + nj * 8 + (lane & 3) * 2;
                float2 v;
                v.x = acc[mi][nj][ri * 2 + 0] + bias[c];
                v.y = acc[mi][nj][ri * 2 + 1] + bias[c + 1];
                *(float2*)(out + (size_t)r * EMB + c) = v;
            }
        }
    }
}

// ---------------------------------------------------------------------------
// Flash attention (exp2). grid (16, 16), 256 threads, 2 CTAs/SM.
// QK^T bf16x3; P·V fp16 k16 with direct C->A fragment reuse (no shuffles).
// smem stage: KH/KL [64x72 bf16, 144B] + V [64x72 fp16, 144B] = 27648B.
// ---------------------------------------------------------------------------
#define ASTR 144
#define A_KH 0
#define A_KL 9216
#define A_V  18432
#define A_STAGE 27648
#define A_SMEM_SZ (3 * A_STAGE)

__device__ __forceinline__ void attn_load_stage(uint32_t sbase, size_t qk_base,
                                                size_t v_base, int t)
{
    const int tid = threadIdx.x;
    #pragma unroll
    for (int i = 0; i < 2; i++) {
        int idx = tid + i * 256;
        int row = idx >> 3, q = idx & 7;
        uint32_t so = (uint32_t)row * ASTR + q * 16;
        { size_t src = qk_base + (size_t)(t * 64 + row) * HDIM + q * 8;
          cp16(sbase + A_KH + so, g_Kh + src);
          cp16(sbase + A_KL + so, g_Kl + src); }
        { size_t src = v_base + (size_t)row * SEQ + t * 64 + q * 8;
          cp16(sbase + A_V + so, g_Vh + src); }
    }
}

__global__ __launch_bounds__(256, 2) void attn_tc()
{
    extern __shared__ char smem[];
    uint32_t sb = smem_u32(smem);
    const int tid = threadIdx.x;
    const int warp = tid >> 5, lane = tid & 31;
    const int bh = blockIdx.y;
    const int q0 = blockIdx.x * 128;
    const size_t qk_base = (size_t)bh * SEQ * HDIM;
    const size_t v_base  = (size_t)bh * HDIM * SEQ;

    // Stage Q (hi/lo), hoist fragments, then the region is reused by stages.
    #pragma unroll
    for (int i = 0; i < 4; i++) {
        int idx = tid + i * 256;
        int row = idx >> 3, q = idx & 7;
        uint32_t so = (uint32_t)row * ASTR + q * 16;
        size_t src = qk_base + (size_t)(q0 + row) * HDIM + q * 8;
        *(uint4*)(smem + so)         = *(const uint4*)(g_Qh + src);
        *(uint4*)(smem + 18432 + so) = *(const uint4*)(g_Ql + src);
    }
    __syncthreads();
    uint32_t qh[4][4], ql[4][4];
    #pragma unroll
    for (int kk = 0; kk < 4; kk++) {
        ldsm4(a_addr(sb,         warp * 16, kk * 16, lane, ASTR),
              qh[kk][0], qh[kk][1], qh[kk][2], qh[kk][3]);
        ldsm4(a_addr(sb + 18432, warp * 16, kk * 16, lane, ASTR),
              ql[kk][0], ql[kk][1], ql[kk][2], ql[kk][3]);
    }
    __syncthreads();

    float o[8][4];
    #pragma unroll
    for (int a = 0; a < 8; a++)
        #pragma unroll
        for (int c = 0; c < 4; c++) o[a][c] = 0.f;
    float m[2] = {-1e30f, -1e30f};
    float lsum[2] = {0.f, 0.f};

    const int NT = SEQ / 64;
    attn_load_stage(sb,           qk_base, v_base, 0); CP_COMMIT();
    attn_load_stage(sb + A_STAGE, qk_base, v_base, 1); CP_COMMIT();

    for (int t = 0; t < NT; t++) {
        if (t + 1 < NT) { CP_WAIT(1); } else { CP_WAIT(0); }
        __syncthreads();
        if (t + 2 < NT) {
            attn_load_stage(sb + ((t + 2) % 3) * A_STAGE, qk_base, v_base, t + 2);
            CP_COMMIT();
        }
        const uint32_t st = sb + (t % 3) * A_STAGE;

        // S' = (Q*scale*log2e) K^T  (bf16x3)
        float sc[8][4];
        #pragma unroll
        for (int a = 0; a < 8; a++)
            #pragma unroll
            for (int c = 0; c < 4; c++) sc[a][c] = 0.f;

        #pragma unroll
        for (int kk = 0; kk < 4; kk++) {
            #pragma unroll
            for (int njp = 0; njp < 4; njp++) {
                uint32_t bh4[4], bl4[4];
                ldsm4(b_addr(st + A_KH, njp * 16, kk * 16, lane, ASTR), bh4[0], bh4[1], bh4[2], bh4[3]);
                ldsm4(b_addr(st + A_KL, njp * 16, kk * 16, lane, ASTR), bl4[0], bl4[1], bl4[2], bl4[3]);
                float* c0 = sc[2 * njp];
                float* c1 = sc[2 * njp + 1];
                mma16816(c0, qh[kk][0], qh[kk][1], qh[kk][2], qh[kk][3], bh4[0], bh4[1]);
                mma16816(c0, ql[kk][0], ql[kk][1], ql[kk][2], ql[kk][3], bh4[0], bh4[1]);
                mma16816(c0, qh[kk][0], qh[kk][1], qh[kk][2], qh[kk][3], bl4[0], bl4[1]);
                mma16816(c1, qh[kk][0], qh[kk][1], qh[kk][2], qh[kk][3], bh4[2], bh4[3]);
                mma16816(c1, ql[kk][0], ql[kk][1], ql[kk][2], ql[kk][3], bh4[2], bh4[3]);
                mma16816(c1, qh[kk][0], qh[kk][1], qh[kk][2], qh[kk][3], bl4[2], bl4[3]);
            }
        }

        // online softmax (exp2 domain); rows r = lane>>2 (ri=0) and r+8 (ri=1)
        float mx[2] = {-1e30f, -1e30f};
        #pragma unroll
        for (int nj = 0; nj < 8; nj++) {
            mx[0] = fmaxf(mx[0], fmaxf(sc[nj][0], sc[nj][1]));
            mx[1] = fmaxf(mx[1], fmaxf(sc[nj][2], sc[nj][3]));
        }
        #pragma unroll
        for (int ri = 0; ri < 2; ri++) {
            mx[ri] = fmaxf(mx[ri], __shfl_xor_sync(0xffffffff, mx[ri], 1));
            mx[ri] = fmaxf(mx[ri], __shfl_xor_sync(0xffffffff, mx[ri], 2));
        }
        float corr[2];
        #pragma unroll
        for (int ri = 0; ri < 2; ri++) {
            float nm = fmaxf(m[ri], mx[ri]);
            corr[ri] = fexp2(m[ri] - nm);
            m[ri] = nm;
        }

        float ls[2] = {0.f, 0.f};
        uint32_t pa[4][4];   // fp16 A-frags: [kk][a0..a3]
        #pragma unroll
        for (int nj = 0; nj < 8; nj++) {
            sc[nj][0] = fexp2(sc[nj][0] - m[0]);
            sc[nj][1] = fexp2(sc[nj][1] - m[0]);
            sc[nj][2] = fexp2(sc[nj][2] - m[1]);
            sc[nj][3] = fexp2(sc[nj][3] - m[1]);
            ls[0] += sc[nj][0] + sc[nj][1];
            ls[1] += sc[nj][2] + sc[nj][3];
        }
        #pragma unroll
        for (int kk = 0; kk < 4; kk++) {
            pa[kk][0] = h2pack(sc[2 * kk][0],     sc[2 * kk][1]);       // row g
            pa[kk][1] = h2pack(sc[2 * kk][2],     sc[2 * kk][3]);       // row g+8
            pa[kk][2] = h2pack(sc[2 * kk + 1][0], sc[2 * kk + 1][1]);   // row g, k+8
            pa[kk][3] = h2pack(sc[2 * kk + 1][2], sc[2 * kk + 1][3]);   // row g+8, k+8
        }
        #pragma unroll
        for (int ri = 0; ri < 2; ri++) {
            ls[ri] += __shfl_xor_sync(0xffffffff, ls[ri], 1);
            ls[ri] += __shfl_xor_sync(0xffffffff, ls[ri], 2);
        }
        lsum[0] = lsum[0] * corr[0] + ls[0];
        lsum[1] = lsum[1] * corr[1] + ls[1];
        #pragma unroll
        for (int nj = 0; nj < 8; nj++) {
            o[nj][0] *= corr[0]; o[nj][1] *= corr[0];
            o[nj][2] *= corr[1]; o[nj][3] *= corr[1];
        }

        // O += P V (fp16 k16), A-frags direct from registers
        #pragma unroll
        for (int kk = 0; kk < 4; kk++) {
            #pragma unroll
            for (int njp = 0; njp < 4; njp++) {
                uint32_t b4[4];
                ldsm4(b_addr(st + A_V, njp * 16, kk * 16, lane, ASTR),
                      b4[0], b4[1], b4[2], b4[3]);
                mma16816f(o[2 * njp],     pa[kk][0], pa[kk][1], pa[kk][2], pa[kk][3], b4[0], b4[1]);
                mma16816f(o[2 * njp + 1], pa[kk][0], pa[kk][1], pa[kk][2], pa[kk][3], b4[2], b4[3]);
            }
        }
    }

    // epilogue: normalize + fp16 write to g_A16
    const int b = bh >> 3, h = bh & 7;
    float inv[2] = {1.f / lsum[0], 1.f / lsum[1]};
    #pragma unroll
    for (int ri = 0; ri < 2; ri++) {
        int r = q0 + warp * 16 + (lane >> 2) + ri * 8;
        size_t R = (size_t)(b * SEQ + r) * EMB + h * HDIM;
        #pragma unroll
        for (int nj = 0; nj < 8; nj++) {
            int dd = nj * 8 + (lane & 3) * 2;
            *(uint32_t*)(g_A16 + R + dd) =
                h2pack(o[nj][ri * 2 + 0] * inv[ri], o[nj][ri * 2 + 1] * inv[ri]);
        }
    }
}

// ---------------------------------------------------------------------------
extern "C" void kernel_launch(void* const* d_in, const int* in_sizes, int n_in,
                              void* d_out, int out_size)
{
    const float* x     = (const float*)d_in[0];
    const float* w_qkv = (const float*)d_in[1];
    const float* w_o   = (const float*)d_in[2];
    const float* b_o   = (const float*)d_in[3];
    float* out = (float*)d_out;

    cudaFuncSetAttribute(gemm_qkv_tc, cudaFuncAttributeMaxDynamicSharedMemorySize, G_SMEM_SZ);
    cudaFuncSetAttribute(gemm_out_tc, cudaFuncAttributeMaxDynamicSharedMemorySize, O_SMEM_SZ);
    cudaFuncSetAttribute(attn_tc,     cudaFuncAttributeMaxDynamicSharedMemorySize, A_SMEM_SZ);

    const int prep_total = PREP_T1 + PREP_T2 + PREP_T3;
    prep_kernel<<<(prep_total + 255) / 256, 256>>>(x, w_qkv, w_o);

    gemm_qkv_tc<<<dim3(N1 / 128, M1 / 128), 256, G_SMEM_SZ>>>();
    attn_tc<<<dim3(SEQ / 128, BATCH * NHEAD), 256, A_SMEM_SZ>>>();
    gemm_out_tc<<<dim3(EMB / 64, M1 / 128), 256, O_SMEM_SZ>>>(b_o, out);
}

// round 14
// speedup vs baseline: 1.5056x; 1.0529x over previous
#include <cuda_runtime.h>
#include <cuda_bf16.h>
#include <cuda_fp16.h>
#include <cstdint>

#define BATCH 2
#define SEQ   2048
#define EMB   512
#define NHEAD 8
#define HDIM  64
#define M1    (BATCH * SEQ)     // 4096
#define N1    (3 * EMB)         // 1536
#define KD    EMB               // 512
#define ATT_SCALE 0.125f
#define LOG2E 1.4426950408889634f

// ---------------------------------------------------------------------------
// helpers
// ---------------------------------------------------------------------------
__device__ __forceinline__ uint32_t smem_u32(const void* p) {
    uint32_t a;
    asm("{ .reg .u64 t; cvta.to.shared.u64 t, %1; cvt.u32.u64 %0, t; }" : "=r"(a) : "l"(p));
    return a;
}
__device__ __forceinline__ void ldsm4(uint32_t addr, uint32_t& r0, uint32_t& r1,
                                      uint32_t& r2, uint32_t& r3) {
    asm volatile("ldmatrix.sync.aligned.m8n8.x4.shared.b16 {%0,%1,%2,%3}, [%4];"
                 : "=r"(r0), "=r"(r1), "=r"(r2), "=r"(r3) : "r"(addr));
}
__device__ __forceinline__ void mma16816(float* c, uint32_t a0, uint32_t a1,
                                         uint32_t a2, uint32_t a3,
                                         uint32_t b0, uint32_t b1) {
    asm volatile("mma.sync.aligned.m16n8k16.row.col.f32.bf16.bf16.f32 "
                 "{%0,%1,%2,%3}, {%4,%5,%6,%7}, {%8,%9}, {%0,%1,%2,%3};"
                 : "+f"(c[0]), "+f"(c[1]), "+f"(c[2]), "+f"(c[3])
                 : "r"(a0), "r"(a1), "r"(a2), "r"(a3), "r"(b0), "r"(b1));
}
__device__ __forceinline__ void mma16816f(float* c, uint32_t a0, uint32_t a1,
                                          uint32_t a2, uint32_t a3,
                                          uint32_t b0, uint32_t b1) {
    asm volatile("mma.sync.aligned.m16n8k16.row.col.f32.f16.f16.f32 "
                 "{%0,%1,%2,%3}, {%4,%5,%6,%7}, {%8,%9}, {%0,%1,%2,%3};"
                 : "+f"(c[0]), "+f"(c[1]), "+f"(c[2]), "+f"(c[3])
                 : "r"(a0), "r"(a1), "r"(a2), "r"(a3), "r"(b0), "r"(b1));
}
__device__ __forceinline__ void cp16(uint32_t dst, const void* src) {
    asm volatile("cp.async.cg.shared.global [%0], [%1], 16;" :: "r"(dst), "l"(src));
}
#define CP_COMMIT() asm volatile("cp.async.commit_group;" ::: "memory")
#define CP_WAIT(n)  asm volatile("cp.async.wait_group %0;" :: "n"(n) : "memory")

__device__ __forceinline__ float fexp2(float x) {
    float r;
    asm("ex2.approx.f32 %0, %1;" : "=f"(r) : "f"(x));
    return r;
}
__device__ __forceinline__ void split2(float v, __nv_bfloat16& h, __nv_bfloat16& l) {
    h = __float2bfloat16(v);
    l = __float2bfloat16(v - __bfloat162float(h));
}
__device__ __forceinline__ uint32_t pack2(__nv_bfloat16 x, __nv_bfloat16 y) {
    __nv_bfloat162 t; t.x = x; t.y = y;
    return *(uint32_t*)&t;
}
__device__ __forceinline__ uint32_t h2pack(float x, float y) {
    __half2 t = __floats2half2_rn(x, y);
    return *(uint32_t*)&t;
}

// padded-layout ldmatrix addresses (stride bytes, 16-bit elements)
__device__ __forceinline__ uint32_t a_addr(uint32_t base, int r0, int c0, int lane, int stride) {
    return base + (uint32_t)(r0 + (lane & 15)) * stride + (uint32_t)(c0 + ((lane >> 4) << 3)) * 2;
}
__device__ __forceinline__ uint32_t b_addr(uint32_t base, int n0, int c0, int lane, int stride) {
    int n = n0 + (lane & 7) + ((lane >> 4) << 3);
    int k = c0 + (((lane >> 3) & 1) << 3);
    return base + (uint32_t)n * stride + (uint32_t)k * 2;
}
// GEMM swizzled layout: 64B rows, quad q placed at q ^ ((row>>1)&3)
__device__ __forceinline__ uint32_t gsw(int row, int qb) {
    return (uint32_t)row * 64 + (uint32_t)((((qb >> 4) ^ ((row >> 1) & 3)) << 4));
}
__device__ __forceinline__ uint32_t ga_addr(uint32_t base, int r0, int kk, int lane) {
    int r  = r0 + (lane & 15);
    int qb = kk * 32 + ((lane >> 4) << 4);
    return base + gsw(r, qb);
}
__device__ __forceinline__ uint32_t gb_addr(uint32_t base, int n0, int kk, int lane) {
    int n  = n0 + (lane & 7) + ((lane >> 4) << 3);
    int qb = kk * 32 + (((lane >> 3) & 1) << 4);
    return base + gsw(n, qb);
}

// ---------------------------------------------------------------------------
// Scratch
// ---------------------------------------------------------------------------
__device__ __nv_bfloat16 g_Xh[M1 * KD],  g_Xl[M1 * KD];
__device__ __nv_bfloat16 g_Wqh[N1 * KD], g_Wql[N1 * KD];       // w_qkv^T [N,K]
__device__ __nv_bfloat16 g_Qh[BATCH*NHEAD*SEQ*HDIM], g_Ql[BATCH*NHEAD*SEQ*HDIM];
__device__ __nv_bfloat16 g_Kh[BATCH*NHEAD*SEQ*HDIM], g_Kl[BATCH*NHEAD*SEQ*HDIM];
__device__ __half g_Vh[BATCH*NHEAD*HDIM*SEQ];   // V^T fp16
__device__ __half g_A16[M1 * EMB];              // attention out fp16
__device__ __half g_Wo16[EMB * EMB];            // w_o^T fp16

// ---------------------------------------------------------------------------
// Prep: x split (coalesced) + tiled transposes for w_qkv (bf16 hi/lo)
// and w_o (fp16). Transposes use 32x32 smem tiles -> coalesced writes.
// ---------------------------------------------------------------------------
__global__ __launch_bounds__(256) void split_x_kernel(const float* __restrict__ x)
{
    int i = blockIdx.x * 256 + threadIdx.x;
    if (i < M1 * KD) {
        __nv_bfloat16 a, b; split2(x[i], a, b);
        g_Xh[i] = a; g_Xl[i] = b;
    }
}
// in: [K, N] row-major. out hi/lo at [n*K + k]. grid (N/32, K/32), block 256 (32x8).
__global__ __launch_bounds__(256) void t_wqkv_kernel(const float* __restrict__ in)
{
    __shared__ float tile[32][33];
    const int tx = threadIdx.x & 31, ty = threadIdx.x >> 5;   // 32 x 8
    const int nb = blockIdx.x * 32, kb = blockIdx.y * 32;
    #pragma unroll
    for (int i = 0; i < 4; i++) {
        int k = kb + ty + i * 8;
        tile[ty + i * 8][tx] = in[(size_t)k * N1 + nb + tx];
    }
    __syncthreads();
    #pragma unroll
    for (int i = 0; i < 4; i++) {
        int n = nb + ty + i * 8;
        float v = tile[tx][ty + i * 8];
        __nv_bfloat16 a, b; split2(v, a, b);
        g_Wqh[(size_t)n * KD + kb + tx] = a;
        g_Wql[(size_t)n * KD + kb + tx] = b;
    }
}
__global__ __launch_bounds__(256) void t_wo_kernel(const float* __restrict__ in)
{
    __shared__ float tile[32][33];
    const int tx = threadIdx.x & 31, ty = threadIdx.x >> 5;
    const int nb = blockIdx.x * 32, kb = blockIdx.y * 32;
    #pragma unroll
    for (int i = 0; i < 4; i++) {
        int k = kb + ty + i * 8;
        tile[ty + i * 8][tx] = in[(size_t)k * EMB + nb + tx];
    }
    __syncthreads();
    #pragma unroll
    for (int i = 0; i < 4; i++) {
        int n = nb + ty + i * 8;
        g_Wo16[(size_t)n * EMB + kb + tx] = __float2half(tile[tx][ty + i * 8]);
    }
}

// ---------------------------------------------------------------------------
// bf16x3 GEMM (QKV projection): BK=32, 3-stage cp.async, 2 CTAs/SM.
// ---------------------------------------------------------------------------
#define G_AH 0
#define G_AL 8192
#define G_BH 16384
#define G_BL 24576
#define G_STAGE 32768
#define G_SMEM_SZ (3 * G_STAGE)

__device__ __forceinline__ void gemm_load_stage(uint32_t sbase,
    const __nv_bfloat16* Ah, const __nv_bfloat16* Al,
    const __nv_bfloat16* Bh, const __nv_bfloat16* Bl,
    int Kdim, int m0, int n0, int k0)
{
    const int tid = threadIdx.x;
    #pragma unroll
    for (int i = 0; i < 2; i++) {
        int idx = tid + i * 256;
        int row = idx >> 2, q = idx & 3;
        uint32_t so = gsw(row, q << 4);
        size_t asrc = (size_t)(m0 + row) * Kdim + k0 + q * 8;
        size_t bsrc = (size_t)(n0 + row) * Kdim + k0 + q * 8;
        cp16(sbase + G_AH + so, Ah + asrc);
        cp16(sbase + G_AL + so, Al + asrc);
        cp16(sbase + G_BH + so, Bh + bsrc);
        cp16(sbase + G_BL + so, Bl + bsrc);
    }
}

__device__ __forceinline__ void gemm_compute_stage(uint32_t sbase, int warp, int lane,
                                                   float acc[2][8][4])
{
    const int wm = warp & 3, wn = warp >> 2;
    #pragma unroll
    for (int kk = 0; kk < 2; kk++) {
        uint32_t ah[2][4], al[2][4];
        #pragma unroll
        for (int mi = 0; mi < 2; mi++) {
            ldsm4(ga_addr(sbase + G_AH, wm * 32 + mi * 16, kk, lane),
                  ah[mi][0], ah[mi][1], ah[mi][2], ah[mi][3]);
            ldsm4(ga_addr(sbase + G_AL, wm * 32 + mi * 16, kk, lane),
                  al[mi][0], al[mi][1], al[mi][2], al[mi][3]);
        }
        #pragma unroll
        for (int njp = 0; njp < 4; njp++) {
            uint32_t bh[4], bl[4];
            ldsm4(gb_addr(sbase + G_BH, wn * 64 + njp * 16, kk, lane),
                  bh[0], bh[1], bh[2], bh[3]);
            ldsm4(gb_addr(sbase + G_BL, wn * 64 + njp * 16, kk, lane),
                  bl[0], bl[1], bl[2], bl[3]);
            #pragma unroll
            for (int mi = 0; mi < 2; mi++) {
                float* c0 = acc[mi][2 * njp];
                float* c1 = acc[mi][2 * njp + 1];
                mma16816(c0, ah[mi][0], ah[mi][1], ah[mi][2], ah[mi][3], bh[0], bh[1]);
                mma16816(c0, al[mi][0], al[mi][1], al[mi][2], al[mi][3], bh[0], bh[1]);
                mma16816(c0, ah[mi][0], ah[mi][1], ah[mi][2], ah[mi][3], bl[0], bl[1]);
                mma16816(c1, ah[mi][0], ah[mi][1], ah[mi][2], ah[mi][3], bh[2], bh[3]);
                mma16816(c1, al[mi][0], al[mi][1], al[mi][2], al[mi][3], bh[2], bh[3]);
                mma16816(c1, ah[mi][0], ah[mi][1], ah[mi][2], ah[mi][3], bl[2], bl[3]);
            }
        }
    }
}

__global__ __launch_bounds__(256, 2) void gemm_qkv_tc()
{
    extern __shared__ char smem[];
    uint32_t sb = smem_u32(smem);
    const int warp = threadIdx.x >> 5, lane = threadIdx.x & 31;
    const int wm = warp & 3, wn = warp >> 2;
    const int m0 = blockIdx.y * 128, n0 = blockIdx.x * 128;

    float acc[2][8][4];
    #pragma unroll
    for (int a = 0; a < 2; a++)
        #pragma unroll
        for (int b = 0; b < 8; b++)
            #pragma unroll
            for (int c = 0; c < 4; c++) acc[a][b][c] = 0.f;

    const int nk = KD / 32;
    gemm_load_stage(sb,           g_Xh, g_Xl, g_Wqh, g_Wql, KD, m0, n0, 0);
    CP_COMMIT();
    gemm_load_stage(sb + G_STAGE, g_Xh, g_Xl, g_Wqh, g_Wql, KD, m0, n0, 32);
    CP_COMMIT();
    for (int kc = 0; kc < nk; kc++) {
        if (kc + 1 < nk) { CP_WAIT(1); } else { CP_WAIT(0); }
        __syncthreads();
        if (kc + 2 < nk) {
            gemm_load_stage(sb + ((kc + 2) % 3) * G_STAGE, g_Xh, g_Xl, g_Wqh, g_Wql,
                            KD, m0, n0, (kc + 2) * 32);
            CP_COMMIT();
        }
        gemm_compute_stage(sb + (kc % 3) * G_STAGE, warp, lane, acc);
    }

    const int region = n0 >> 9;  // 0=Q 1=K 2=V
    const float qscale = ATT_SCALE * LOG2E;
    #pragma unroll
    for (int mi = 0; mi < 2; mi++) {
        #pragma unroll
        for (int ri = 0; ri < 2; ri++) {
            int r = m0 + wm * 32 + mi * 16 + (lane >> 2) + ri * 8;
            int b = r >> 11, s = r & 2047;
            #pragma unroll
            for (int nj = 0; nj < 8; nj++) {
                int c = n0 + wn * 64 + nj * 8 + (lane & 3) * 2;
                int within = c & 511;
                int h = within >> 6, dd = within & 63;
                float v0 = acc[mi][nj][ri * 2 + 0];
                float v1 = acc[mi][nj][ri * 2 + 1];
                if (region == 0) { v0 *= qscale; v1 *= qscale; }
                if (region < 2) {
                    __nv_bfloat16 h0, l0, h1, l1;
                    split2(v0, h0, l0); split2(v1, h1, l1);
                    __nv_bfloat16* H = region == 0 ? g_Qh : g_Kh;
                    __nv_bfloat16* L = region == 0 ? g_Ql : g_Kl;
                    size_t idx = (((size_t)(b * NHEAD + h) * SEQ + s) * HDIM + dd);
                    *(uint32_t*)(H + idx) = pack2(h0, h1);
                    *(uint32_t*)(L + idx) = pack2(l0, l1);
                } else {
                    size_t base = ((size_t)(b * NHEAD + h) * HDIM + dd) * SEQ + s;
                    g_Vh[base]       = __float2half(v0);
                    g_Vh[base + SEQ] = __float2half(v1);
                }
            }
        }
    }
}

// ---------------------------------------------------------------------------
// Out projection (fp16): out = g_A16 @ g_Wo16^T + bias. Tiles 128m x 64n,
// BK=64 (144B padded rows), grid (8, 32). 3-stage, 2 CTAs/SM.
// ---------------------------------------------------------------------------
#define O_STR 144
#define O_A 0
#define O_B 18432
#define O_STAGE 27648
#define O_SMEM_SZ (3 * O_STAGE)

__global__ __launch_bounds__(256, 2) void gemm_out_tc(const float* __restrict__ bias,
                                                      float* __restrict__ out)
{
    extern __shared__ char smem[];
    uint32_t sb = smem_u32(smem);
    const int tid = threadIdx.x;
    const int warp = tid >> 5, lane = tid & 31;
    const int wm = warp & 3, wn = warp >> 2;
    const int m0 = blockIdx.y * 128, n0 = blockIdx.x * 64;

    float acc[2][4][4];
    #pragma unroll
    for (int a = 0; a < 2; a++)
        #pragma unroll
        for (int b = 0; b < 4; b++)
            #pragma unroll
            for (int c = 0; c < 4; c++) acc[a][b][c] = 0.f;

    auto load_stage = [&](uint32_t sbase, int k0) {
        #pragma unroll
        for (int i = 0; i < 4; i++) {
            int idx = tid + i * 256;          // A: 128 rows x 8 quads (128B data)
            int row = idx >> 3, q = idx & 7;
            cp16(sbase + O_A + (uint32_t)row * O_STR + q * 16,
                 g_A16 + (size_t)(m0 + row) * EMB + k0 + q * 8);
        }
        #pragma unroll
        for (int i = 0; i < 2; i++) {
            int idx = tid + i * 256;          // B: 64 rows x 8 quads
            int row = idx >> 3, q = idx & 7;
            cp16(sbase + O_B + (uint32_t)row * O_STR + q * 16,
                 g_Wo16 + (size_t)(n0 + row) * EMB + k0 + q * 8);
        }
    };

    const int nk = EMB / 64;
    load_stage(sb,           0);  CP_COMMIT();
    load_stage(sb + O_STAGE, 64); CP_COMMIT();
    for (int kc = 0; kc < nk; kc++) {
        if (kc + 1 < nk) { CP_WAIT(1); } else { CP_WAIT(0); }
        __syncthreads();
        if (kc + 2 < nk) { load_stage(sb + ((kc + 2) % 3) * O_STAGE, (kc + 2) * 64); CP_COMMIT(); }
        const uint32_t st = sb + (kc % 3) * O_STAGE;

        #pragma unroll
        for (int kk = 0; kk < 4; kk++) {          // 4 k16 chunks
            uint32_t a4[2][4];
            #pragma unroll
            for (int mi = 0; mi < 2; mi++)
                ldsm4(a_addr(st + O_A, wm * 32 + mi * 16, kk * 16, lane, O_STR),
                      a4[mi][0], a4[mi][1], a4[mi][2], a4[mi][3]);
            #pragma unroll
            for (int njp = 0; njp < 2; njp++) {
                uint32_t b4[4];
                ldsm4(b_addr(st + O_B, wn * 32 + njp * 16, kk * 16, lane, O_STR),
                      b4[0], b4[1], b4[2], b4[3]);
                #pragma unroll
                for (int mi = 0; mi < 2; mi++) {
                    mma16816f(acc[mi][2 * njp],     a4[mi][0], a4[mi][1], a4[mi][2], a4[mi][3], b4[0], b4[1]);
                    mma16816f(acc[mi][2 * njp + 1], a4[mi][0], a4[mi][1], a4[mi][2], a4[mi][3], b4[2], b4[3]);
                }
            }
        }
    }

    #pragma unroll
    for (int mi = 0; mi < 2; mi++) {
        #pragma unroll
        for (int ri = 0; ri < 2; ri++) {
            int r = m0 + wm * 32 + mi * 16 + (lane >> 2) + ri * 8;
            #pragma unroll
            for (int nj = 0; nj < 4; nj++) {
                int c = n0 + wn * 32 + nj * 8 + (lane & 3) * 2;
                float2 v;
                v.x = acc[mi][nj][ri * 2 + 0] + bias[c];
                v.y = acc[mi][nj][ri * 2 + 1] + bias[c + 1];
                *(float2*)(out + (size_t)r * EMB + c) = v;
            }
        }
    }
}

// ---------------------------------------------------------------------------
// Flash attention (exp2). grid (16, 16), 256 threads, 2 CTAs/SM.
// QK^T bf16x3; P·V fp16 k16 with direct C->A reuse. 4-stage cp.async.
// smem stage: KH/KL [64x72 bf16, 144B] + V [64x72 fp16, 144B] = 27648B.
// ---------------------------------------------------------------------------
#define ASTR 144
#define A_KH 0
#define A_KL 9216
#define A_V  18432
#define A_STAGE 27648
#define A_SMEM_SZ (4 * A_STAGE)

__device__ __forceinline__ void attn_load_stage(uint32_t sbase, size_t qk_base,
                                                size_t v_base, int t)
{
    const int tid = threadIdx.x;
    #pragma unroll
    for (int i = 0; i < 2; i++) {
        int idx = tid + i * 256;
        int row = idx >> 3, q = idx & 7;
        uint32_t so = (uint32_t)row * ASTR + q * 16;
        { size_t src = qk_base + (size_t)(t * 64 + row) * HDIM + q * 8;
          cp16(sbase + A_KH + so, g_Kh + src);
          cp16(sbase + A_KL + so, g_Kl + src); }
        { size_t src = v_base + (size_t)row * SEQ + t * 64 + q * 8;
          cp16(sbase + A_V + so, g_Vh + src); }
    }
}

__global__ __launch_bounds__(256, 2) void attn_tc()
{
    extern __shared__ char smem[];
    uint32_t sb = smem_u32(smem);
    const int tid = threadIdx.x;
    const int warp = tid >> 5, lane = tid & 31;
    const int bh = blockIdx.y;
    const int q0 = blockIdx.x * 128;
    const size_t qk_base = (size_t)bh * SEQ * HDIM;
    const size_t v_base  = (size_t)bh * HDIM * SEQ;

    // Stage Q (hi/lo), hoist fragments, then region is reused by the pipeline.
    #pragma unroll
    for (int i = 0; i < 4; i++) {
        int idx = tid + i * 256;
        int row = idx >> 3, q = idx & 7;
        uint32_t so = (uint32_t)row * ASTR + q * 16;
        size_t src = qk_base + (size_t)(q0 + row) * HDIM + q * 8;
        *(uint4*)(smem + so)         = *(const uint4*)(g_Qh + src);
        *(uint4*)(smem + 18432 + so) = *(const uint4*)(g_Ql + src);
    }
    __syncthreads();
    uint32_t qh[4][4], ql[4][4];
    #pragma unroll
    for (int kk = 0; kk < 4; kk++) {
        ldsm4(a_addr(sb,         warp * 16, kk * 16, lane, ASTR),
              qh[kk][0], qh[kk][1], qh[kk][2], qh[kk][3]);
        ldsm4(a_addr(sb + 18432, warp * 16, kk * 16, lane, ASTR),
              ql[kk][0], ql[kk][1], ql[kk][2], ql[kk][3]);
    }
    __syncthreads();

    float o[8][4];
    #pragma unroll
    for (int a = 0; a < 8; a++)
        #pragma unroll
        for (int c = 0; c < 4; c++) o[a][c] = 0.f;
    float m[2] = {-1e30f, -1e30f};
    float lsum[2] = {0.f, 0.f};

    const int NT = SEQ / 64;
    attn_load_stage(sb,               qk_base, v_base, 0); CP_COMMIT();
    attn_load_stage(sb + A_STAGE,     qk_base, v_base, 1); CP_COMMIT();
    attn_load_stage(sb + 2 * A_STAGE, qk_base, v_base, 2); CP_COMMIT();

    for (int t = 0; t < NT; t++) {
        if (t + 2 < NT) { CP_WAIT(2); } else if (t + 1 < NT) { CP_WAIT(1); } else { CP_WAIT(0); }
        __syncthreads();
        if (t + 3 < NT) {
            attn_load_stage(sb + ((t + 3) & 3) * A_STAGE, qk_base, v_base, t + 3);
            CP_COMMIT();
        }
        const uint32_t st = sb + (t & 3) * A_STAGE;

        // S' = (Q*scale*log2e) K^T  (bf16x3)
        float sc[8][4];
        #pragma unroll
        for (int a = 0; a < 8; a++)
            #pragma unroll
            for (int c = 0; c < 4; c++) sc[a][c] = 0.f;

        #pragma unroll
        for (int kk = 0; kk < 4; kk++) {
            #pragma unroll
            for (int njp = 0; njp < 4; njp++) {
                uint32_t bh4[4], bl4[4];
                ldsm4(b_addr(st + A_KH, njp * 16, kk * 16, lane, ASTR), bh4[0], bh4[1], bh4[2], bh4[3]);
                ldsm4(b_addr(st + A_KL, njp * 16, kk * 16, lane, ASTR), bl4[0], bl4[1], bl4[2], bl4[3]);
                float* c0 = sc[2 * njp];
                float* c1 = sc[2 * njp + 1];
                mma16816(c0, qh[kk][0], qh[kk][1], qh[kk][2], qh[kk][3], bh4[0], bh4[1]);
                mma16816(c0, ql[kk][0], ql[kk][1], ql[kk][2], ql[kk][3], bh4[0], bh4[1]);
                mma16816(c0, qh[kk][0], qh[kk][1], qh[kk][2], qh[kk][3], bl4[0], bl4[1]);
                mma16816(c1, qh[kk][0], qh[kk][1], qh[kk][2], qh[kk][3], bh4[2], bh4[3]);
                mma16816(c1, ql[kk][0], ql[kk][1], ql[kk][2], ql[kk][3], bh4[2], bh4[3]);
                mma16816(c1, qh[kk][0], qh[kk][1], qh[kk][2], qh[kk][3], bl4[2], bl4[3]);
            }
        }

        // online softmax (exp2); rows r = lane>>2 (ri=0) and r+8 (ri=1)
        float mx[2] = {-1e30f, -1e30f};
        #pragma unroll
        for (int nj = 0; nj < 8; nj++) {
            mx[0] = fmaxf(mx[0], fmaxf(sc[nj][0], sc[nj][1]));
            mx[1] = fmaxf(mx[1], fmaxf(sc[nj][2], sc[nj][3]));
        }
        #pragma unroll
        for (int ri = 0; ri < 2; ri++) {
            mx[ri] = fmaxf(mx[ri], __shfl_xor_sync(0xffffffff, mx[ri], 1));
            mx[ri] = fmaxf(mx[ri], __shfl_xor_sync(0xffffffff, mx[ri], 2));
        }
        float corr[2];
        #pragma unroll
        for (int ri = 0; ri < 2; ri++) {
            float nm = fmaxf(m[ri], mx[ri]);
            corr[ri] = fexp2(m[ri] - nm);
            m[ri] = nm;
        }

        float ls[2] = {0.f, 0.f};
        uint32_t pa[4][4];
        #pragma unroll
        for (int nj = 0; nj < 8; nj++) {
            sc[nj][0] = fexp2(sc[nj][0] - m[0]);
            sc[nj][1] = fexp2(sc[nj][1] - m[0]);
            sc[nj][2] = fexp2(sc[nj][2] - m[1]);
            sc[nj][3] = fexp2(sc[nj][3] - m[1]);
            ls[0] += sc[nj][0] + sc[nj][1];
            ls[1] += sc[nj][2] + sc[nj][3];
        }
        #pragma unroll
        for (int kk = 0; kk < 4; kk++) {
            pa[kk][0] = h2pack(sc[2 * kk][0],     sc[2 * kk][1]);
            pa[kk][1] = h2pack(sc[2 * kk][2],     sc[2 * kk][3]);
            pa[kk][2] = h2pack(sc[2 * kk + 1][0], sc[2 * kk + 1][1]);
            pa[kk][3] = h2pack(sc[2 * kk + 1][2], sc[2 * kk + 1][3]);
        }
        #pragma unroll
        for (int ri = 0; ri < 2; ri++) {
            ls[ri] += __shfl_xor_sync(0xffffffff, ls[ri], 1);
            ls[ri] += __shfl_xor_sync(0xffffffff, ls[ri], 2);
        }
        lsum[0] = lsum[0] * corr[0] + ls[0];
        lsum[1] = lsum[1] * corr[1] + ls[1];
        #pragma unroll
        for (int nj = 0; nj < 8; nj++) {
            o[nj][0] *= corr[0]; o[nj][1] *= corr[0];
            o[nj][2] *= corr[1]; o[nj][3] *= corr[1];
        }

        // O += P V (fp16 k16)
        #pragma unroll
        for (int kk = 0; kk < 4; kk++) {
            #pragma unroll
            for (int njp = 0; njp < 4; njp++) {
                uint32_t b4[4];
                ldsm4(b_addr(st + A_V, njp * 16, kk * 16, lane, ASTR),
                      b4[0], b4[1], b4[2], b4[3]);
                mma16816f(o[2 * njp],     pa[kk][0], pa[kk][1], pa[kk][2], pa[kk][3], b4[0], b4[1]);
                mma16816f(o[2 * njp + 1], pa[kk][0], pa[kk][1], pa[kk][2], pa[kk][3], b4[2], b4[3]);
            }
        }
    }

    // epilogue
    const int b = bh >> 3, h = bh & 7;
    float inv[2] = {1.f / lsum[0], 1.f / lsum[1]};
    #pragma unroll
    for (int ri = 0; ri < 2; ri++) {
        int r = q0 + warp * 16 + (lane >> 2) + ri * 8;
        size_t R = (size_t)(b * SEQ + r) * EMB + h * HDIM;
        #pragma unroll
        for (int nj = 0; nj < 8; nj++) {
            int dd = nj * 8 + (lane & 3) * 2;
            *(uint32_t*)(g_A16 + R + dd) =
                h2pack(o[nj][ri * 2 + 0] * inv[ri], o[nj][ri * 2 + 1] * inv[ri]);
        }
    }
}

// ---------------------------------------------------------------------------
extern "C" void kernel_launch(void* const* d_in, const int* in_sizes, int n_in,
                              void* d_out, int out_size)
{
    const float* x     = (const float*)d_in[0];
    const float* w_qkv = (const float*)d_in[1];
    const float* w_o   = (const float*)d_in[2];
    const float* b_o   = (const float*)d_in[3];
    float* out = (float*)d_out;

    cudaFuncSetAttribute(gemm_qkv_tc, cudaFuncAttributeMaxDynamicSharedMemorySize, G_SMEM_SZ);
    cudaFuncSetAttribute(gemm_out_tc, cudaFuncAttributeMaxDynamicSharedMemorySize, O_SMEM_SZ);
    cudaFuncSetAttribute(attn_tc,     cudaFuncAttributeMaxDynamicSharedMemorySize, A_SMEM_SZ);

    split_x_kernel<<<(M1 * KD + 255) / 256, 256>>>(x);
    t_wqkv_kernel<<<dim3(N1 / 32, KD / 32), 256>>>(w_qkv);
    t_wo_kernel<<<dim3(EMB / 32, KD / 32), 256>>>(w_o);

    gemm_qkv_tc<<<dim3(N1 / 128, M1 / 128), 256, G_SMEM_SZ>>>();
    attn_tc<<<dim3(SEQ / 128, BATCH * NHEAD), 256, A_SMEM_SZ>>>();
    gemm_out_tc<<<dim3(EMB / 64, M1 / 128), 256, O_SMEM_SZ>>>(b_o, out);
}

// round 15
// speedup vs baseline: 1.7336x; 1.1514x over previous
#include <cuda_runtime.h>
#include <cuda_bf16.h>
#include <cuda_fp16.h>
#include <cstdint>

#define BATCH 2
#define SEQ   2048
#define EMB   512
#define NHEAD 8
#define HDIM  64
#define M1    (BATCH * SEQ)     // 4096
#define N1    (3 * EMB)         // 1536
#define KD    EMB               // 512
#define ATT_SCALE 0.125f
#define LOG2E 1.4426950408889634f

// ---------------------------------------------------------------------------
// helpers
// ---------------------------------------------------------------------------
__device__ __forceinline__ uint32_t smem_u32(const void* p) {
    uint32_t a;
    asm("{ .reg .u64 t; cvta.to.shared.u64 t, %1; cvt.u32.u64 %0, t; }" : "=r"(a) : "l"(p));
    return a;
}
__device__ __forceinline__ void ldsm4(uint32_t addr, uint32_t& r0, uint32_t& r1,
                                      uint32_t& r2, uint32_t& r3) {
    asm volatile("ldmatrix.sync.aligned.m8n8.x4.shared.b16 {%0,%1,%2,%3}, [%4];"
                 : "=r"(r0), "=r"(r1), "=r"(r2), "=r"(r3) : "r"(addr));
}
__device__ __forceinline__ void mma16816(float* c, uint32_t a0, uint32_t a1,
                                         uint32_t a2, uint32_t a3,
                                         uint32_t b0, uint32_t b1) {
    asm volatile("mma.sync.aligned.m16n8k16.row.col.f32.bf16.bf16.f32 "
                 "{%0,%1,%2,%3}, {%4,%5,%6,%7}, {%8,%9}, {%0,%1,%2,%3};"
                 : "+f"(c[0]), "+f"(c[1]), "+f"(c[2]), "+f"(c[3])
                 : "r"(a0), "r"(a1), "r"(a2), "r"(a3), "r"(b0), "r"(b1));
}
__device__ __forceinline__ void mma16816f(float* c, uint32_t a0, uint32_t a1,
                                          uint32_t a2, uint32_t a3,
                                          uint32_t b0, uint32_t b1) {
    asm volatile("mma.sync.aligned.m16n8k16.row.col.f32.f16.f16.f32 "
                 "{%0,%1,%2,%3}, {%4,%5,%6,%7}, {%8,%9}, {%0,%1,%2,%3};"
                 : "+f"(c[0]), "+f"(c[1]), "+f"(c[2]), "+f"(c[3])
                 : "r"(a0), "r"(a1), "r"(a2), "r"(a3), "r"(b0), "r"(b1));
}
__device__ __forceinline__ void cp16(uint32_t dst, const void* src) {
    asm volatile("cp.async.cg.shared.global [%0], [%1], 16;" :: "r"(dst), "l"(src));
}
#define CP_COMMIT() asm volatile("cp.async.commit_group;" ::: "memory")
#define CP_WAIT(n)  asm volatile("cp.async.wait_group %0;" :: "n"(n) : "memory")

__device__ __forceinline__ float fexp2(float x) {
    float r;
    asm("ex2.approx.f32 %0, %1;" : "=f"(r) : "f"(x));
    return r;
}
__device__ __forceinline__ void split2(float v, __nv_bfloat16& h, __nv_bfloat16& l) {
    h = __float2bfloat16(v);
    l = __float2bfloat16(v - __bfloat162float(h));
}
__device__ __forceinline__ void splith(float v, __half& h, __half& l) {
    h = __float2half(v);
    l = __float2half(v - __half2float(h));
}
__device__ __forceinline__ uint32_t pack2(__nv_bfloat16 x, __nv_bfloat16 y) {
    __nv_bfloat162 t; t.x = x; t.y = y;
    return *(uint32_t*)&t;
}
__device__ __forceinline__ uint32_t packh(__half x, __half y) {
    __half2 t; t.x = x; t.y = y;
    return *(uint32_t*)&t;
}
__device__ __forceinline__ uint32_t h2pack(float x, float y) {
    __half2 t = __floats2half2_rn(x, y);
    return *(uint32_t*)&t;
}

// padded-layout ldmatrix addresses (stride bytes, 16-bit elements)
__device__ __forceinline__ uint32_t a_addr(uint32_t base, int r0, int c0, int lane, int stride) {
    return base + (uint32_t)(r0 + (lane & 15)) * stride + (uint32_t)(c0 + ((lane >> 4) << 3)) * 2;
}
__device__ __forceinline__ uint32_t b_addr(uint32_t base, int n0, int c0, int lane, int stride) {
    int n = n0 + (lane & 7) + ((lane >> 4) << 3);
    int k = c0 + (((lane >> 3) & 1) << 3);
    return base + (uint32_t)n * stride + (uint32_t)k * 2;
}
// GEMM swizzled layout: 64B rows, quad q placed at q ^ ((row>>1)&3)
__device__ __forceinline__ uint32_t gsw(int row, int qb) {
    return (uint32_t)row * 64 + (uint32_t)((((qb >> 4) ^ ((row >> 1) & 3)) << 4));
}
__device__ __forceinline__ uint32_t ga_addr(uint32_t base, int r0, int kk, int lane) {
    int r  = r0 + (lane & 15);
    int qb = kk * 32 + ((lane >> 4) << 4);
    return base + gsw(r, qb);
}
__device__ __forceinline__ uint32_t gb_addr(uint32_t base, int n0, int kk, int lane) {
    int n  = n0 + (lane & 7) + ((lane >> 4) << 3);
    int qb = kk * 32 + (((lane >> 3) & 1) << 4);
    return base + gsw(n, qb);
}

// ---------------------------------------------------------------------------
// Scratch
// ---------------------------------------------------------------------------
__device__ __nv_bfloat16 g_Xh[M1 * KD],  g_Xl[M1 * KD];
__device__ __nv_bfloat16 g_Wqh[N1 * KD], g_Wql[N1 * KD];       // w_qkv^T [N,K]
__device__ __half g_Q16h[BATCH*NHEAD*SEQ*HDIM], g_Q16l[BATCH*NHEAD*SEQ*HDIM]; // Q fp16 hi/lo
__device__ __half g_K16[BATCH*NHEAD*SEQ*HDIM];  // K fp16 (single)
__device__ __half g_Vh[BATCH*NHEAD*HDIM*SEQ];   // V^T fp16
__device__ __half g_A16[M1 * EMB];              // attention out fp16
__device__ __half g_Wo16[EMB * EMB];            // w_o^T fp16

// ---------------------------------------------------------------------------
// Prep: x split (coalesced) + tiled transposes for w_qkv / w_o
// ---------------------------------------------------------------------------
__global__ __launch_bounds__(256) void split_x_kernel(const float* __restrict__ x)
{
    int i = blockIdx.x * 256 + threadIdx.x;
    if (i < M1 * KD) {
        __nv_bfloat16 a, b; split2(x[i], a, b);
        g_Xh[i] = a; g_Xl[i] = b;
    }
}
__global__ __launch_bounds__(256) void t_wqkv_kernel(const float* __restrict__ in)
{
    __shared__ float tile[32][33];
    const int tx = threadIdx.x & 31, ty = threadIdx.x >> 5;
    const int nb = blockIdx.x * 32, kb = blockIdx.y * 32;
    #pragma unroll
    for (int i = 0; i < 4; i++) {
        int k = kb + ty + i * 8;
        tile[ty + i * 8][tx] = in[(size_t)k * N1 + nb + tx];
    }
    __syncthreads();
    #pragma unroll
    for (int i = 0; i < 4; i++) {
        int n = nb + ty + i * 8;
        float v = tile[tx][ty + i * 8];
        __nv_bfloat16 a, b; split2(v, a, b);
        g_Wqh[(size_t)n * KD + kb + tx] = a;
        g_Wql[(size_t)n * KD + kb + tx] = b;
    }
}
__global__ __launch_bounds__(256) void t_wo_kernel(const float* __restrict__ in)
{
    __shared__ float tile[32][33];
    const int tx = threadIdx.x & 31, ty = threadIdx.x >> 5;
    const int nb = blockIdx.x * 32, kb = blockIdx.y * 32;
    #pragma unroll
    for (int i = 0; i < 4; i++) {
        int k = kb + ty + i * 8;
        tile[ty + i * 8][tx] = in[(size_t)k * EMB + nb + tx];
    }
    __syncthreads();
    #pragma unroll
    for (int i = 0; i < 4; i++) {
        int n = nb + ty + i * 8;
        g_Wo16[(size_t)n * EMB + kb + tx] = __float2half(tile[tx][ty + i * 8]);
    }
}

// ---------------------------------------------------------------------------
// bf16x3 GEMM (QKV projection): BK=32, 3-stage cp.async, 2 CTAs/SM.
// ---------------------------------------------------------------------------
#define G_AH 0
#define G_AL 8192
#define G_BH 16384
#define G_BL 24576
#define G_STAGE 32768
#define G_SMEM_SZ (3 * G_STAGE)

__device__ __forceinline__ void gemm_load_stage(uint32_t sbase,
    const __nv_bfloat16* Ah, const __nv_bfloat16* Al,
    const __nv_bfloat16* Bh, const __nv_bfloat16* Bl,
    int Kdim, int m0, int n0, int k0)
{
    const int tid = threadIdx.x;
    #pragma unroll
    for (int i = 0; i < 2; i++) {
        int idx = tid + i * 256;
        int row = idx >> 2, q = idx & 3;
        uint32_t so = gsw(row, q << 4);
        size_t asrc = (size_t)(m0 + row) * Kdim + k0 + q * 8;
        size_t bsrc = (size_t)(n0 + row) * Kdim + k0 + q * 8;
        cp16(sbase + G_AH + so, Ah + asrc);
        cp16(sbase + G_AL + so, Al + asrc);
        cp16(sbase + G_BH + so, Bh + bsrc);
        cp16(sbase + G_BL + so, Bl + bsrc);
    }
}

__device__ __forceinline__ void gemm_compute_stage(uint32_t sbase, int warp, int lane,
                                                   float acc[2][8][4])
{
    const int wm = warp & 3, wn = warp >> 2;
    #pragma unroll
    for (int kk = 0; kk < 2; kk++) {
        uint32_t ah[2][4], al[2][4];
        #pragma unroll
        for (int mi = 0; mi < 2; mi++) {
            ldsm4(ga_addr(sbase + G_AH, wm * 32 + mi * 16, kk, lane),
                  ah[mi][0], ah[mi][1], ah[mi][2], ah[mi][3]);
            ldsm4(ga_addr(sbase + G_AL, wm * 32 + mi * 16, kk, lane),
                  al[mi][0], al[mi][1], al[mi][2], al[mi][3]);
        }
        #pragma unroll
        for (int njp = 0; njp < 4; njp++) {
            uint32_t bh[4], bl[4];
            ldsm4(gb_addr(sbase + G_BH, wn * 64 + njp * 16, kk, lane),
                  bh[0], bh[1], bh[2], bh[3]);
            ldsm4(gb_addr(sbase + G_BL, wn * 64 + njp * 16, kk, lane),
                  bl[0], bl[1], bl[2], bl[3]);
            #pragma unroll
            for (int mi = 0; mi < 2; mi++) {
                float* c0 = acc[mi][2 * njp];
                float* c1 = acc[mi][2 * njp + 1];
                mma16816(c0, ah[mi][0], ah[mi][1], ah[mi][2], ah[mi][3], bh[0], bh[1]);
                mma16816(c0, al[mi][0], al[mi][1], al[mi][2], al[mi][3], bh[0], bh[1]);
                mma16816(c0, ah[mi][0], ah[mi][1], ah[mi][2], ah[mi][3], bl[0], bl[1]);
                mma16816(c1, ah[mi][0], ah[mi][1], ah[mi][2], ah[mi][3], bh[2], bh[3]);
                mma16816(c1, al[mi][0], al[mi][1], al[mi][2], al[mi][3], bh[2], bh[3]);
                mma16816(c1, ah[mi][0], ah[mi][1], ah[mi][2], ah[mi][3], bl[2], bl[3]);
            }
        }
    }
}

__global__ __launch_bounds__(256, 2) void gemm_qkv_tc()
{
    extern __shared__ char smem[];
    uint32_t sb = smem_u32(smem);
    const int warp = threadIdx.x >> 5, lane = threadIdx.x & 31;
    const int wm = warp & 3, wn = warp >> 2;
    const int m0 = blockIdx.y * 128, n0 = blockIdx.x * 128;

    float acc[2][8][4];
    #pragma unroll
    for (int a = 0; a < 2; a++)
        #pragma unroll
        for (int b = 0; b < 8; b++)
            #pragma unroll
            for (int c = 0; c < 4; c++) acc[a][b][c] = 0.f;

    const int nk = KD / 32;
    gemm_load_stage(sb,           g_Xh, g_Xl, g_Wqh, g_Wql, KD, m0, n0, 0);
    CP_COMMIT();
    gemm_load_stage(sb + G_STAGE, g_Xh, g_Xl, g_Wqh, g_Wql, KD, m0, n0, 32);
    CP_COMMIT();
    for (int kc = 0; kc < nk; kc++) {
        if (kc + 1 < nk) { CP_WAIT(1); } else { CP_WAIT(0); }
        __syncthreads();
        if (kc + 2 < nk) {
            gemm_load_stage(sb + ((kc + 2) % 3) * G_STAGE, g_Xh, g_Xl, g_Wqh, g_Wql,
                            KD, m0, n0, (kc + 2) * 32);
            CP_COMMIT();
        }
        gemm_compute_stage(sb + (kc % 3) * G_STAGE, warp, lane, acc);
    }

    const int region = n0 >> 9;  // 0=Q 1=K 2=V
    const float qscale = ATT_SCALE * LOG2E;
    #pragma unroll
    for (int mi = 0; mi < 2; mi++) {
        #pragma unroll
        for (int ri = 0; ri < 2; ri++) {
            int r = m0 + wm * 32 + mi * 16 + (lane >> 2) + ri * 8;
            int b = r >> 11, s = r & 2047;
            #pragma unroll
            for (int nj = 0; nj < 8; nj++) {
                int c = n0 + wn * 64 + nj * 8 + (lane & 3) * 2;
                int within = c & 511;
                int h = within >> 6, dd = within & 63;
                float v0 = acc[mi][nj][ri * 2 + 0];
                float v1 = acc[mi][nj][ri * 2 + 1];
                if (region == 0) {
                    v0 *= qscale; v1 *= qscale;
                    __half h0, l0, h1, l1;
                    splith(v0, h0, l0); splith(v1, h1, l1);
                    size_t idx = (((size_t)(b * NHEAD + h) * SEQ + s) * HDIM + dd);
                    *(uint32_t*)(g_Q16h + idx) = packh(h0, h1);
                    *(uint32_t*)(g_Q16l + idx) = packh(l0, l1);
                } else if (region == 1) {
                    size_t idx = (((size_t)(b * NHEAD + h) * SEQ + s) * HDIM + dd);
                    *(uint32_t*)(g_K16 + idx) = h2pack(v0, v1);
                } else {
                    size_t base = ((size_t)(b * NHEAD + h) * HDIM + dd) * SEQ + s;
                    g_Vh[base]       = __float2half(v0);
                    g_Vh[base + SEQ] = __float2half(v1);
                }
            }
        }
    }
}

// ---------------------------------------------------------------------------
// Out projection (fp16): out = g_A16 @ g_Wo16^T + bias. Tiles 128m x 64n,
// BK=64 (144B padded rows), grid (8, 32). 3-stage, 2 CTAs/SM.
// ---------------------------------------------------------------------------
#define O_STR 144
#define O_A 0
#define O_B 18432
#define O_STAGE 27648
#define O_SMEM_SZ (3 * O_STAGE)

__global__ __launch_bounds__(256, 2) void gemm_out_tc(const float* __restrict__ bias,
                                                      float* __restrict__ out)
{
    extern __shared__ char smem[];
    uint32_t sb = smem_u32(smem);
    const int tid = threadIdx.x;
    const int warp = tid >> 5, lane = tid & 31;
    const int wm = warp & 3, wn = warp >> 2;
    const int m0 = blockIdx.y * 128, n0 = blockIdx.x * 64;

    float acc[2][4][4];
    #pragma unroll
    for (int a = 0; a < 2; a++)
        #pragma unroll
        for (int b = 0; b < 4; b++)
            #pragma unroll
            for (int c = 0; c < 4; c++) acc[a][b][c] = 0.f;

    auto load_stage = [&](uint32_t sbase, int k0) {
        #pragma unroll
        for (int i = 0; i < 4; i++) {
            int idx = tid + i * 256;
            int row = idx >> 3, q = idx & 7;
            cp16(sbase + O_A + (uint32_t)row * O_STR + q * 16,
                 g_A16 + (size_t)(m0 + row) * EMB + k0 + q * 8);
        }
        #pragma unroll
        for (int i = 0; i < 2; i++) {
            int idx = tid + i * 256;
            int row = idx >> 3, q = idx & 7;
            cp16(sbase + O_B + (uint32_t)row * O_STR + q * 16,
                 g_Wo16 + (size_t)(n0 + row) * EMB + k0 + q * 8);
        }
    };

    const int nk = EMB / 64;
    load_stage(sb,           0);  CP_COMMIT();
    load_stage(sb + O_STAGE, 64); CP_COMMIT();
    for (int kc = 0; kc < nk; kc++) {
        if (kc + 1 < nk) { CP_WAIT(1); } else { CP_WAIT(0); }
        __syncthreads();
        if (kc + 2 < nk) { load_stage(sb + ((kc + 2) % 3) * O_STAGE, (kc + 2) * 64); CP_COMMIT(); }
        const uint32_t st = sb + (kc % 3) * O_STAGE;

        #pragma unroll
        for (int kk = 0; kk < 4; kk++) {
            uint32_t a4[2][4];
            #pragma unroll
            for (int mi = 0; mi < 2; mi++)
                ldsm4(a_addr(st + O_A, wm * 32 + mi * 16, kk * 16, lane, O_STR),
                      a4[mi][0], a4[mi][1], a4[mi][2], a4[mi][3]);
            #pragma unroll
            for (int njp = 0; njp < 2; njp++) {
                uint32_t b4[4];
                ldsm4(b_addr(st + O_B, wn * 32 + njp * 16, kk * 16, lane, O_STR),
                      b4[0], b4[1], b4[2], b4[3]);
                #pragma unroll
                for (int mi = 0; mi < 2; mi++) {
                    mma16816f(acc[mi][2 * njp],     a4[mi][0], a4[mi][1], a4[mi][2], a4[mi][3], b4[0], b4[1]);
                    mma16816f(acc[mi][2 * njp + 1], a4[mi][0], a4[mi][1], a4[mi][2], a4[mi][3], b4[2], b4[3]);
                }
            }
        }
    }

    #pragma unroll
    for (int mi = 0; mi < 2; mi++) {
        #pragma unroll
        for (int ri = 0; ri < 2; ri++) {
            int r = m0 + wm * 32 + mi * 16 + (lane >> 2) + ri * 8;
            #pragma unroll
            for (int nj = 0; nj < 4; nj++) {
                int c = n0 + wn * 32 + nj * 8 + (lane & 3) * 2;
                float2 v;
                v.x = acc[mi][nj][ri * 2 + 0] + bias[c];
                v.y = acc[mi][nj][ri * 2 + 1] + bias[c + 1];
                *(float2*)(out + (size_t)r * EMB + c) = v;
            }
        }
    }
}

// ---------------------------------------------------------------------------
// Flash attention (exp2). grid (16, 16), 256 threads, 2 CTAs/SM.
// QK^T fp16x2: Q hi/lo in regs, K single fp16 in smem (no K-lo at all).
// P·V fp16 k16, direct C->A reuse. 4-stage cp.async.
// smem stage: K [64x72 fp16, 144B] + V [64x72 fp16, 144B] = 18432B.
// ---------------------------------------------------------------------------
#define ASTR 144
#define A_K 0
#define A_V 9216
#define A_STAGE 18432
#define A_SMEM_SZ (4 * A_STAGE)

__device__ __forceinline__ void attn_load_stage(uint32_t sbase, size_t qk_base,
                                                size_t v_base, int t)
{
    const int tid = threadIdx.x;
    #pragma unroll
    for (int i = 0; i < 2; i++) {
        int idx = tid + i * 256;          // 64 rows x 8 quads (128B rows)
        int row = idx >> 3, q = idx & 7;
        uint32_t so = (uint32_t)row * ASTR + q * 16;
        { size_t src = qk_base + (size_t)(t * 64 + row) * HDIM + q * 8;
          cp16(sbase + A_K + so, g_K16 + src); }
        { size_t src = v_base + (size_t)row * SEQ + t * 64 + q * 8;
          cp16(sbase + A_V + so, g_Vh + src); }
    }
}

__global__ __launch_bounds__(256, 2) void attn_tc()
{
    extern __shared__ char smem[];
    uint32_t sb = smem_u32(smem);
    const int tid = threadIdx.x;
    const int warp = tid >> 5, lane = tid & 31;
    const int bh = blockIdx.y;
    const int q0 = blockIdx.x * 128;
    const size_t qk_base = (size_t)bh * SEQ * HDIM;
    const size_t v_base  = (size_t)bh * HDIM * SEQ;

    // Stage Q hi/lo (fp16) into stage0/stage1 regions, hoist frags, then free.
    #pragma unroll
    for (int i = 0; i < 4; i++) {
        int idx = tid + i * 256;          // 128 rows x 8 quads
        int row = idx >> 3, q = idx & 7;
        uint32_t so = (uint32_t)row * ASTR + q * 16;
        size_t src = qk_base + (size_t)(q0 + row) * HDIM + q * 8;
        *(uint4*)(smem + so)             = *(const uint4*)(g_Q16h + src);
        *(uint4*)(smem + A_STAGE + so)   = *(const uint4*)(g_Q16l + src);
    }
    __syncthreads();
    uint32_t qh[4][4], ql[4][4];
    #pragma unroll
    for (int kk = 0; kk < 4; kk++) {
        ldsm4(a_addr(sb,           warp * 16, kk * 16, lane, ASTR),
              qh[kk][0], qh[kk][1], qh[kk][2], qh[kk][3]);
        ldsm4(a_addr(sb + A_STAGE, warp * 16, kk * 16, lane, ASTR),
              ql[kk][0], ql[kk][1], ql[kk][2], ql[kk][3]);
    }
    __syncthreads();

    float o[8][4];
    #pragma unroll
    for (int a = 0; a < 8; a++)
        #pragma unroll
        for (int c = 0; c < 4; c++) o[a][c] = 0.f;
    float m[2] = {-1e30f, -1e30f};
    float lsum[2] = {0.f, 0.f};

    const int NT = SEQ / 64;
    attn_load_stage(sb,               qk_base, v_base, 0); CP_COMMIT();
    attn_load_stage(sb + A_STAGE,     qk_base, v_base, 1); CP_COMMIT();
    attn_load_stage(sb + 2 * A_STAGE, qk_base, v_base, 2); CP_COMMIT();

    for (int t = 0; t < NT; t++) {
        if (t + 2 < NT) { CP_WAIT(2); } else if (t + 1 < NT) { CP_WAIT(1); } else { CP_WAIT(0); }
        __syncthreads();
        if (t + 3 < NT) {
            attn_load_stage(sb + ((t + 3) & 3) * A_STAGE, qk_base, v_base, t + 3);
            CP_COMMIT();
        }
        const uint32_t st = sb + (t & 3) * A_STAGE;

        // S' = (Qh+Ql) K16^T  (fp16x2: 4 MMAs per njp per kk)
        float sc[8][4];
        #pragma unroll
        for (int a = 0; a < 8; a++)
            #pragma unroll
            for (int c = 0; c < 4; c++) sc[a][c] = 0.f;

        #pragma unroll
        for (int kk = 0; kk < 4; kk++) {
            #pragma unroll
            for (int njp = 0; njp < 4; njp++) {
                uint32_t k4[4];
                ldsm4(b_addr(st + A_K, njp * 16, kk * 16, lane, ASTR),
                      k4[0], k4[1], k4[2], k4[3]);
                float* c0 = sc[2 * njp];
                float* c1 = sc[2 * njp + 1];
                mma16816f(c0, qh[kk][0], qh[kk][1], qh[kk][2], qh[kk][3], k4[0], k4[1]);
                mma16816f(c0, ql[kk][0], ql[kk][1], ql[kk][2], ql[kk][3], k4[0], k4[1]);
                mma16816f(c1, qh[kk][0], qh[kk][1], qh[kk][2], qh[kk][3], k4[2], k4[3]);
                mma16816f(c1, ql[kk][0], ql[kk][1], ql[kk][2], ql[kk][3], k4[2], k4[3]);
            }
        }

        // online softmax (exp2); rows r = lane>>2 (ri=0) and r+8 (ri=1)
        float mx[2] = {-1e30f, -1e30f};
        #pragma unroll
        for (int nj = 0; nj < 8; nj++) {
            mx[0] = fmaxf(mx[0], fmaxf(sc[nj][0], sc[nj][1]));
            mx[1] = fmaxf(mx[1], fmaxf(sc[nj][2], sc[nj][3]));
        }
        #pragma unroll
        for (int ri = 0; ri < 2; ri++) {
            mx[ri] = fmaxf(mx[ri], __shfl_xor_sync(0xffffffff, mx[ri], 1));
            mx[ri] = fmaxf(mx[ri], __shfl_xor_sync(0xffffffff, mx[ri], 2));
        }
        float corr[2];
        #pragma unroll
        for (int ri = 0; ri < 2; ri++) {
            float nm = fmaxf(m[ri], mx[ri]);
            corr[ri] = fexp2(m[ri] - nm);
            m[ri] = nm;
        }

        float ls[2] = {0.f, 0.f};
        uint32_t pa[4][4];
        #pragma unroll
        for (int nj = 0; nj < 8; nj++) {
            sc[nj][0] = fexp2(sc[nj][0] - m[0]);
            sc[nj][1] = fexp2(sc[nj][1] - m[0]);
            sc[nj][2] = fexp2(sc[nj][2] - m[1]);
            sc[nj][3] = fexp2(sc[nj][3] - m[1]);
            ls[0] += sc[nj][0] + sc[nj][1];
            ls[1] += sc[nj][2] + sc[nj][3];
        }
        #pragma unroll
        for (int kk = 0; kk < 4; kk++) {
            pa[kk][0] = h2pack(sc[2 * kk][0],     sc[2 * kk][1]);
            pa[kk][1] = h2pack(sc[2 * kk][2],     sc[2 * kk][3]);
            pa[kk][2] = h2pack(sc[2 * kk + 1][0], sc[2 * kk + 1][1]);
            pa[kk][3] = h2pack(sc[2 * kk + 1][2], sc[2 * kk + 1][3]);
        }
        #pragma unroll
        for (int ri = 0; ri < 2; ri++) {
            ls[ri] += __shfl_xor_sync(0xffffffff, ls[ri], 1);
            ls[ri] += __shfl_xor_sync(0xffffffff, ls[ri], 2);
        }
        lsum[0] = lsum[0] * corr[0] + ls[0];
        lsum[1] = lsum[1] * corr[1] + ls[1];
        #pragma unroll
        for (int nj = 0; nj < 8; nj++) {
            o[nj][0] *= corr[0]; o[nj][1] *= corr[0];
            o[nj][2] *= corr[1]; o[nj][3] *= corr[1];
        }

        // O += P V (fp16 k16)
        #pragma unroll
        for (int kk = 0; kk < 4; kk++) {
            #pragma unroll
            for (int njp = 0; njp < 4; njp++) {
                uint32_t b4[4];
                ldsm4(b_addr(st + A_V, njp * 16, kk * 16, lane, ASTR),
                      b4[0], b4[1], b4[2], b4[3]);
                mma16816f(o[2 * njp],     pa[kk][0], pa[kk][1], pa[kk][2], pa[kk][3], b4[0], b4[1]);
                mma16816f(o[2 * njp + 1], pa[kk][0], pa[kk][1], pa[kk][2], pa[kk][3], b4[2], b4[3]);
            }
        }
    }

    // epilogue
    const int b = bh >> 3, h = bh & 7;
    float inv[2] = {1.f / lsum[0], 1.f / lsum[1]};
    #pragma unroll
    for (int ri = 0; ri < 2; ri++) {
        int r = q0 + warp * 16 + (lane >> 2) + ri * 8;
        size_t R = (size_t)(b * SEQ + r) * EMB + h * HDIM;
        #pragma unroll
        for (int nj = 0; nj < 8; nj++) {
            int dd = nj * 8 + (lane & 3) * 2;
            *(uint32_t*)(g_A16 + R + dd) =
                h2pack(o[nj][ri * 2 + 0] * inv[ri], o[nj][ri * 2 + 1] * inv[ri]);
        }
    }
}

// ---------------------------------------------------------------------------
extern "C" void kernel_launch(void* const* d_in, const int* in_sizes, int n_in,
                              void* d_out, int out_size)
{
    const float* x     = (const float*)d_in[0];
    const float* w_qkv = (const float*)d_in[1];
    const float* w_o   = (const float*)d_in[2];
    const float* b_o   = (const float*)d_in[3];
    float* out = (float*)d_out;

    cudaFuncSetAttribute(gemm_qkv_tc, cudaFuncAttributeMaxDynamicSharedMemorySize, G_SMEM_SZ);
    cudaFuncSetAttribute(gemm_out_tc, cudaFuncAttributeMaxDynamicSharedMemorySize, O_SMEM_SZ);
    cudaFuncSetAttribute(attn_tc,     cudaFuncAttributeMaxDynamicSharedMemorySize, A_SMEM_SZ);

    split_x_kernel<<<(M1 * KD + 255) / 256, 256>>>(x);
    t_wqkv_kernel<<<dim3(N1 / 32, KD / 32), 256>>>(w_qkv);
    t_wo_kernel<<<dim3(EMB / 32, KD / 32), 256>>>(w_o);

    gemm_qkv_tc<<<dim3(N1 / 128, M1 / 128), 256, G_SMEM_SZ>>>();
    attn_tc<<<dim3(SEQ / 128, BATCH * NHEAD), 256, A_SMEM_SZ>>>();
    gemm_out_tc<<<dim3(EMB / 64, M1 / 128), 256, O_SMEM_SZ>>>(b_o, out);
}

// round 16
// speedup vs baseline: 1.9283x; 1.1123x over previous
#include <cuda_runtime.h>
#include <cuda_bf16.h>
#include <cuda_fp16.h>
#include <cstdint>

#define BATCH 2
#define SEQ   2048
#define EMB   512
#define NHEAD 8
#define HDIM  64
#define M1    (BATCH * SEQ)     // 4096
#define N1    (3 * EMB)         // 1536
#define KD    EMB               // 512
#define ATT_SCALE 0.125f
#define LOG2E 1.4426950408889634f

// ---------------------------------------------------------------------------
// helpers
// ---------------------------------------------------------------------------
__device__ __forceinline__ uint32_t smem_u32(const void* p) {
    uint32_t a;
    asm("{ .reg .u64 t; cvta.to.shared.u64 t, %1; cvt.u32.u64 %0, t; }" : "=r"(a) : "l"(p));
    return a;
}
__device__ __forceinline__ void ldsm4(uint32_t addr, uint32_t& r0, uint32_t& r1,
                                      uint32_t& r2, uint32_t& r3) {
    asm volatile("ldmatrix.sync.aligned.m8n8.x4.shared.b16 {%0,%1,%2,%3}, [%4];"
                 : "=r"(r0), "=r"(r1), "=r"(r2), "=r"(r3) : "r"(addr));
}
__device__ __forceinline__ void mma16816f(float* c, uint32_t a0, uint32_t a1,
                                          uint32_t a2, uint32_t a3,
                                          uint32_t b0, uint32_t b1) {
    asm volatile("mma.sync.aligned.m16n8k16.row.col.f32.f16.f16.f32 "
                 "{%0,%1,%2,%3}, {%4,%5,%6,%7}, {%8,%9}, {%0,%1,%2,%3};"
                 : "+f"(c[0]), "+f"(c[1]), "+f"(c[2]), "+f"(c[3])
                 : "r"(a0), "r"(a1), "r"(a2), "r"(a3), "r"(b0), "r"(b1));
}
__device__ __forceinline__ void cp16(uint32_t dst, const void* src) {
    asm volatile("cp.async.cg.shared.global [%0], [%1], 16;" :: "r"(dst), "l"(src));
}
#define CP_COMMIT() asm volatile("cp.async.commit_group;" ::: "memory")
#define CP_WAIT(n)  asm volatile("cp.async.wait_group %0;" :: "n"(n) : "memory")

__device__ __forceinline__ float fexp2(float x) {
    float r;
    asm("ex2.approx.f32 %0, %1;" : "=f"(r) : "f"(x));
    return r;
}
__device__ __forceinline__ void splith(float v, __half& h, __half& l) {
    h = __float2half(v);
    l = __float2half(v - __half2float(h));
}
__device__ __forceinline__ uint32_t packh(__half x, __half y) {
    __half2 t; t.x = x; t.y = y;
    return *(uint32_t*)&t;
}
__device__ __forceinline__ uint32_t h2pack(float x, float y) {
    __half2 t = __floats2half2_rn(x, y);
    return *(uint32_t*)&t;
}

// padded-layout ldmatrix addresses (stride bytes, 16-bit elements)
__device__ __forceinline__ uint32_t a_addr(uint32_t base, int r0, int c0, int lane, int stride) {
    return base + (uint32_t)(r0 + (lane & 15)) * stride + (uint32_t)(c0 + ((lane >> 4) << 3)) * 2;
}
__device__ __forceinline__ uint32_t b_addr(uint32_t base, int n0, int c0, int lane, int stride) {
    int n = n0 + (lane & 7) + ((lane >> 4) << 3);
    int k = c0 + (((lane >> 3) & 1) << 3);
    return base + (uint32_t)n * stride + (uint32_t)k * 2;
}
// GEMM swizzled layout: 64B rows, quad q placed at q ^ ((row>>1)&3)
__device__ __forceinline__ uint32_t gsw(int row, int qb) {
    return (uint32_t)row * 64 + (uint32_t)((((qb >> 4) ^ ((row >> 1) & 3)) << 4));
}
__device__ __forceinline__ uint32_t ga_addr(uint32_t base, int r0, int kk, int lane) {
    int r  = r0 + (lane & 15);
    int qb = kk * 32 + ((lane >> 4) << 4);
    return base + gsw(r, qb);
}
__device__ __forceinline__ uint32_t gb_addr(uint32_t base, int n0, int kk, int lane) {
    int n  = n0 + (lane & 7) + ((lane >> 4) << 3);
    int qb = kk * 32 + (((lane >> 3) & 1) << 4);
    return base + gsw(n, qb);
}

// ---------------------------------------------------------------------------
// Scratch (fp16 throughout now)
// ---------------------------------------------------------------------------
__device__ __half g_Xh[M1 * KD],  g_Xl[M1 * KD];   // x fp16 hi/lo
__device__ __half g_Wq16[N1 * KD];                 // w_qkv^T fp16
__device__ __half g_Q16h[BATCH*NHEAD*SEQ*HDIM], g_Q16l[BATCH*NHEAD*SEQ*HDIM];
__device__ __half g_K16[BATCH*NHEAD*SEQ*HDIM];
__device__ __half g_Vh[BATCH*NHEAD*HDIM*SEQ];
__device__ __half g_A16[M1 * EMB];
__device__ __half g_Wo16[EMB * EMB];

// ---------------------------------------------------------------------------
// Prep
// ---------------------------------------------------------------------------
__global__ __launch_bounds__(256) void split_x_kernel(const float* __restrict__ x)
{
    int i = blockIdx.x * 256 + threadIdx.x;
    if (i < M1 * KD) {
        __half a, b; splith(x[i], a, b);
        g_Xh[i] = a; g_Xl[i] = b;
    }
}
__global__ __launch_bounds__(256) void t_wqkv_kernel(const float* __restrict__ in)
{
    __shared__ float tile[32][33];
    const int tx = threadIdx.x & 31, ty = threadIdx.x >> 5;
    const int nb = blockIdx.x * 32, kb = blockIdx.y * 32;
    #pragma unroll
    for (int i = 0; i < 4; i++) {
        int k = kb + ty + i * 8;
        tile[ty + i * 8][tx] = in[(size_t)k * N1 + nb + tx];
    }
    __syncthreads();
    #pragma unroll
    for (int i = 0; i < 4; i++) {
        int n = nb + ty + i * 8;
        g_Wq16[(size_t)n * KD + kb + tx] = __float2half(tile[tx][ty + i * 8]);
    }
}
__global__ __launch_bounds__(256) void t_wo_kernel(const float* __restrict__ in)
{
    __shared__ float tile[32][33];
    const int tx = threadIdx.x & 31, ty = threadIdx.x >> 5;
    const int nb = blockIdx.x * 32, kb = blockIdx.y * 32;
    #pragma unroll
    for (int i = 0; i < 4; i++) {
        int k = kb + ty + i * 8;
        tile[ty + i * 8][tx] = in[(size_t)k * EMB + nb + tx];
    }
    __syncthreads();
    #pragma unroll
    for (int i = 0; i < 4; i++) {
        int n = nb + ty + i * 8;
        g_Wo16[(size_t)n * EMB + kb + tx] = __float2half(tile[tx][ty + i * 8]);
    }
}

// ---------------------------------------------------------------------------
// fp16x2 GEMM (QKV projection): X hi/lo fp16, W single fp16. BK=32,
// 4-stage cp.async, 2 CTAs/SM. Stage = 3 x 8192 = 24576B.
// ---------------------------------------------------------------------------
#define G_XH 0
#define G_XL 8192
#define G_W  16384
#define G_STAGE 24576
#define G_SMEM_SZ (4 * G_STAGE)

__device__ __forceinline__ void gemm_load_stage(uint32_t sbase, int m0, int n0, int k0)
{
    const int tid = threadIdx.x;
    #pragma unroll
    for (int i = 0; i < 2; i++) {
        int idx = tid + i * 256;
        int row = idx >> 2, q = idx & 3;
        uint32_t so = gsw(row, q << 4);
        size_t asrc = (size_t)(m0 + row) * KD + k0 + q * 8;
        size_t bsrc = (size_t)(n0 + row) * KD + k0 + q * 8;
        cp16(sbase + G_XH + so, g_Xh + asrc);
        cp16(sbase + G_XL + so, g_Xl + asrc);
        cp16(sbase + G_W  + so, g_Wq16 + bsrc);
    }
}

__device__ __forceinline__ void gemm_compute_stage(uint32_t sbase, int warp, int lane,
                                                   float acc[2][8][4])
{
    const int wm = warp & 3, wn = warp >> 2;
    #pragma unroll
    for (int kk = 0; kk < 2; kk++) {
        uint32_t xh[2][4], xl[2][4];
        #pragma unroll
        for (int mi = 0; mi < 2; mi++) {
            ldsm4(ga_addr(sbase + G_XH, wm * 32 + mi * 16, kk, lane),
                  xh[mi][0], xh[mi][1], xh[mi][2], xh[mi][3]);
            ldsm4(ga_addr(sbase + G_XL, wm * 32 + mi * 16, kk, lane),
                  xl[mi][0], xl[mi][1], xl[mi][2], xl[mi][3]);
        }
        #pragma unroll
        for (int njp = 0; njp < 4; njp++) {
            uint32_t w4[4];
            ldsm4(gb_addr(sbase + G_W, wn * 64 + njp * 16, kk, lane),
                  w4[0], w4[1], w4[2], w4[3]);
            #pragma unroll
            for (int mi = 0; mi < 2; mi++) {
                float* c0 = acc[mi][2 * njp];
                float* c1 = acc[mi][2 * njp + 1];
                mma16816f(c0, xh[mi][0], xh[mi][1], xh[mi][2], xh[mi][3], w4[0], w4[1]);
                mma16816f(c0, xl[mi][0], xl[mi][1], xl[mi][2], xl[mi][3], w4[0], w4[1]);
                mma16816f(c1, xh[mi][0], xh[mi][1], xh[mi][2], xh[mi][3], w4[2], w4[3]);
                mma16816f(c1, xl[mi][0], xl[mi][1], xl[mi][2], xl[mi][3], w4[2], w4[3]);
            }
        }
    }
}

__global__ __launch_bounds__(256, 2) void gemm_qkv_tc()
{
    extern __shared__ char smem[];
    uint32_t sb = smem_u32(smem);
    const int warp = threadIdx.x >> 5, lane = threadIdx.x & 31;
    const int wm = warp & 3, wn = warp >> 2;
    const int m0 = blockIdx.y * 128, n0 = blockIdx.x * 128;

    float acc[2][8][4];
    #pragma unroll
    for (int a = 0; a < 2; a++)
        #pragma unroll
        for (int b = 0; b < 8; b++)
            #pragma unroll
            for (int c = 0; c < 4; c++) acc[a][b][c] = 0.f;

    const int nk = KD / 32;
    gemm_load_stage(sb,               m0, n0, 0);  CP_COMMIT();
    gemm_load_stage(sb + G_STAGE,     m0, n0, 32); CP_COMMIT();
    gemm_load_stage(sb + 2 * G_STAGE, m0, n0, 64); CP_COMMIT();
    for (int kc = 0; kc < nk; kc++) {
        if (kc + 2 < nk) { CP_WAIT(2); } else if (kc + 1 < nk) { CP_WAIT(1); } else { CP_WAIT(0); }
        __syncthreads();
        if (kc + 3 < nk) {
            gemm_load_stage(sb + ((kc + 3) & 3) * G_STAGE, m0, n0, (kc + 3) * 32);
            CP_COMMIT();
        }
        gemm_compute_stage(sb + (kc & 3) * G_STAGE, warp, lane, acc);
    }

    const int region = n0 >> 9;  // 0=Q 1=K 2=V
    const float qscale = ATT_SCALE * LOG2E;
    #pragma unroll
    for (int mi = 0; mi < 2; mi++) {
        #pragma unroll
        for (int ri = 0; ri < 2; ri++) {
            int r = m0 + wm * 32 + mi * 16 + (lane >> 2) + ri * 8;
            int b = r >> 11, s = r & 2047;
            #pragma unroll
            for (int nj = 0; nj < 8; nj++) {
                int c = n0 + wn * 64 + nj * 8 + (lane & 3) * 2;
                int within = c & 511;
                int h = within >> 6, dd = within & 63;
                float v0 = acc[mi][nj][ri * 2 + 0];
                float v1 = acc[mi][nj][ri * 2 + 1];
                if (region == 0) {
                    v0 *= qscale; v1 *= qscale;
                    __half h0, l0, h1, l1;
                    splith(v0, h0, l0); splith(v1, h1, l1);
                    size_t idx = (((size_t)(b * NHEAD + h) * SEQ + s) * HDIM + dd);
                    *(uint32_t*)(g_Q16h + idx) = packh(h0, h1);
                    *(uint32_t*)(g_Q16l + idx) = packh(l0, l1);
                } else if (region == 1) {
                    size_t idx = (((size_t)(b * NHEAD + h) * SEQ + s) * HDIM + dd);
                    *(uint32_t*)(g_K16 + idx) = h2pack(v0, v1);
                } else {
                    size_t base = ((size_t)(b * NHEAD + h) * HDIM + dd) * SEQ + s;
                    g_Vh[base]       = __float2half(v0);
                    g_Vh[base + SEQ] = __float2half(v1);
                }
            }
        }
    }
}

// ---------------------------------------------------------------------------
// Out projection (fp16): out = g_A16 @ g_Wo16^T + bias. Tiles 128m x 64n,
// BK=64 (144B padded rows), grid (8, 32). 3-stage, 2 CTAs/SM.
// ---------------------------------------------------------------------------
#define O_STR 144
#define O_A 0
#define O_B 18432
#define O_STAGE 27648
#define O_SMEM_SZ (3 * O_STAGE)

__global__ __launch_bounds__(256, 2) void gemm_out_tc(const float* __restrict__ bias,
                                                      float* __restrict__ out)
{
    extern __shared__ char smem[];
    uint32_t sb = smem_u32(smem);
    const int tid = threadIdx.x;
    const int warp = tid >> 5, lane = tid & 31;
    const int wm = warp & 3, wn = warp >> 2;
    const int m0 = blockIdx.y * 128, n0 = blockIdx.x * 64;

    float acc[2][4][4];
    #pragma unroll
    for (int a = 0; a < 2; a++)
        #pragma unroll
        for (int b = 0; b < 4; b++)
            #pragma unroll
            for (int c = 0; c < 4; c++) acc[a][b][c] = 0.f;

    auto load_stage = [&](uint32_t sbase, int k0) {
        #pragma unroll
        for (int i = 0; i < 4; i++) {
            int idx = tid + i * 256;
            int row = idx >> 3, q = idx & 7;
            cp16(sbase + O_A + (uint32_t)row * O_STR + q * 16,
                 g_A16 + (size_t)(m0 + row) * EMB + k0 + q * 8);
        }
        #pragma unroll
        for (int i = 0; i < 2; i++) {
            int idx = tid + i * 256;
            int row = idx >> 3, q = idx & 7;
            cp16(sbase + O_B + (uint32_t)row * O_STR + q * 16,
                 g_Wo16 + (size_t)(n0 + row) * EMB + k0 + q * 8);
        }
    };

    const int nk = EMB / 64;
    load_stage(sb,           0);  CP_COMMIT();
    load_stage(sb + O_STAGE, 64); CP_COMMIT();
    for (int kc = 0; kc < nk; kc++) {
        if (kc + 1 < nk) { CP_WAIT(1); } else { CP_WAIT(0); }
        __syncthreads();
        if (kc + 2 < nk) { load_stage(sb + ((kc + 2) % 3) * O_STAGE, (kc + 2) * 64); CP_COMMIT(); }
        const uint32_t st = sb + (kc % 3) * O_STAGE;

        #pragma unroll
        for (int kk = 0; kk < 4; kk++) {
            uint32_t a4[2][4];
            #pragma unroll
            for (int mi = 0; mi < 2; mi++)
                ldsm4(a_addr(st + O_A, wm * 32 + mi * 16, kk * 16, lane, O_STR),
                      a4[mi][0], a4[mi][1], a4[mi][2], a4[mi][3]);
            #pragma unroll
            for (int njp = 0; njp < 2; njp++) {
                uint32_t b4[4];
                ldsm4(b_addr(st + O_B, wn * 32 + njp * 16, kk * 16, lane, O_STR),
                      b4[0], b4[1], b4[2], b4[3]);
                #pragma unroll
                for (int mi = 0; mi < 2; mi++) {
                    mma16816f(acc[mi][2 * njp],     a4[mi][0], a4[mi][1], a4[mi][2], a4[mi][3], b4[0], b4[1]);
                    mma16816f(acc[mi][2 * njp + 1], a4[mi][0], a4[mi][1], a4[mi][2], a4[mi][3], b4[2], b4[3]);
                }
            }
        }
    }

    #pragma unroll
    for (int mi = 0; mi < 2; mi++) {
        #pragma unroll
        for (int ri = 0; ri < 2; ri++) {
            int r = m0 + wm * 32 + mi * 16 + (lane >> 2) + ri * 8;
            #pragma unroll
            for (int nj = 0; nj < 4; nj++) {
                int c = n0 + wn * 32 + nj * 8 + (lane & 3) * 2;
                float2 v;
                v.x = acc[mi][nj][ri * 2 + 0] + bias[c];
                v.y = acc[mi][nj][ri * 2 + 1] + bias[c + 1];
                *(float2*)(out + (size_t)r * EMB + c) = v;
            }
        }
    }
}

// ---------------------------------------------------------------------------
// Flash attention (exp2). grid (16, 16), 256 threads, 2 CTAs/SM.
// QK^T fp16x2 (Q hi/lo regs, K single fp16); P·V fp16 k16, C->A reuse.
// 4-stage cp.async. Stage: K + V [64x72 fp16, 144B] each = 18432B.
// ---------------------------------------------------------------------------
#define ASTR 144
#define A_K 0
#define A_V 9216
#define A_STAGE 18432
#define A_SMEM_SZ (4 * A_STAGE)

__device__ __forceinline__ void attn_load_stage(uint32_t sbase, size_t qk_base,
                                                size_t v_base, int t)
{
    const int tid = threadIdx.x;
    #pragma unroll
    for (int i = 0; i < 2; i++) {
        int idx = tid + i * 256;
        int row = idx >> 3, q = idx & 7;
        uint32_t so = (uint32_t)row * ASTR + q * 16;
        { size_t src = qk_base + (size_t)(t * 64 + row) * HDIM + q * 8;
          cp16(sbase + A_K + so, g_K16 + src); }
        { size_t src = v_base + (size_t)row * SEQ + t * 64 + q * 8;
          cp16(sbase + A_V + so, g_Vh + src); }
    }
}

__global__ __launch_bounds__(256, 2) void attn_tc()
{
    extern __shared__ char smem[];
    uint32_t sb = smem_u32(smem);
    const int tid = threadIdx.x;
    const int warp = tid >> 5, lane = tid & 31;
    const int bh = blockIdx.y;
    const int q0 = blockIdx.x * 128;
    const size_t qk_base = (size_t)bh * SEQ * HDIM;
    const size_t v_base  = (size_t)bh * HDIM * SEQ;

    // Stage Q hi/lo, hoist fragments, then region is reused by pipeline.
    #pragma unroll
    for (int i = 0; i < 4; i++) {
        int idx = tid + i * 256;
        int row = idx >> 3, q = idx & 7;
        uint32_t so = (uint32_t)row * ASTR + q * 16;
        size_t src = qk_base + (size_t)(q0 + row) * HDIM + q * 8;
        *(uint4*)(smem + so)           = *(const uint4*)(g_Q16h + src);
        *(uint4*)(smem + A_STAGE + so) = *(const uint4*)(g_Q16l + src);
    }
    __syncthreads();
    uint32_t qh[4][4], ql[4][4];
    #pragma unroll
    for (int kk = 0; kk < 4; kk++) {
        ldsm4(a_addr(sb,           warp * 16, kk * 16, lane, ASTR),
              qh[kk][0], qh[kk][1], qh[kk][2], qh[kk][3]);
        ldsm4(a_addr(sb + A_STAGE, warp * 16, kk * 16, lane, ASTR),
              ql[kk][0], ql[kk][1], ql[kk][2], ql[kk][3]);
    }
    __syncthreads();

    float o[8][4];
    #pragma unroll
    for (int a = 0; a < 8; a++)
        #pragma unroll
        for (int c = 0; c < 4; c++) o[a][c] = 0.f;
    float m[2] = {-1e30f, -1e30f};
    float lsum[2] = {0.f, 0.f};

    const int NT = SEQ / 64;
    attn_load_stage(sb,               qk_base, v_base, 0); CP_COMMIT();
    attn_load_stage(sb + A_STAGE,     qk_base, v_base, 1); CP_COMMIT();
    attn_load_stage(sb + 2 * A_STAGE, qk_base, v_base, 2); CP_COMMIT();

    for (int t = 0; t < NT; t++) {
        if (t + 2 < NT) { CP_WAIT(2); } else if (t + 1 < NT) { CP_WAIT(1); } else { CP_WAIT(0); }
        __syncthreads();
        if (t + 3 < NT) {
            attn_load_stage(sb + ((t + 3) & 3) * A_STAGE, qk_base, v_base, t + 3);
            CP_COMMIT();
        }
        const uint32_t st = sb + (t & 3) * A_STAGE;

        // S' = (Qh+Ql) K16^T
        float sc[8][4];
        #pragma unroll
        for (int a = 0; a < 8; a++)
            #pragma unroll
            for (int c = 0; c < 4; c++) sc[a][c] = 0.f;

        #pragma unroll
        for (int kk = 0; kk < 4; kk++) {
            #pragma unroll
            for (int njp = 0; njp < 4; njp++) {
                uint32_t k4[4];
                ldsm4(b_addr(st + A_K, njp * 16, kk * 16, lane, ASTR),
                      k4[0], k4[1], k4[2], k4[3]);
                float* c0 = sc[2 * njp];
                float* c1 = sc[2 * njp + 1];
                mma16816f(c0, qh[kk][0], qh[kk][1], qh[kk][2], qh[kk][3], k4[0], k4[1]);
                mma16816f(c0, ql[kk][0], ql[kk][1], ql[kk][2], ql[kk][3], k4[0], k4[1]);
                mma16816f(c1, qh[kk][0], qh[kk][1], qh[kk][2], qh[kk][3], k4[2], k4[3]);
                mma16816f(c1, ql[kk][0], ql[kk][1], ql[kk][2], ql[kk][3], k4[2], k4[3]);
            }
        }

        // online softmax (exp2)
        float mx[2] = {-1e30f, -1e30f};
        #pragma unroll
        for (int nj = 0; nj < 8; nj++) {
            mx[0] = fmaxf(mx[0], fmaxf(sc[nj][0], sc[nj][1]));
            mx[1] = fmaxf(mx[1], fmaxf(sc[nj][2], sc[nj][3]));
        }
        #pragma unroll
        for (int ri = 0; ri < 2; ri++) {
            mx[ri] = fmaxf(mx[ri], __shfl_xor_sync(0xffffffff, mx[ri], 1));
            mx[ri] = fmaxf(mx[ri], __shfl_xor_sync(0xffffffff, mx[ri], 2));
        }
        float corr[2];
        #pragma unroll
        for (int ri = 0; ri < 2; ri++) {
            float nm = fmaxf(m[ri], mx[ri]);
            corr[ri] = fexp2(m[ri] - nm);
            m[ri] = nm;
        }

        float ls[2] = {0.f, 0.f};
        uint32_t pa[4][4];
        #pragma unroll
        for (int nj = 0; nj < 8; nj++) {
            sc[nj][0] = fexp2(sc[nj][0] - m[0]);
            sc[nj][1] = fexp2(sc[nj][1] - m[0]);
            sc[nj][2] = fexp2(sc[nj][2] - m[1]);
            sc[nj][3] = fexp2(sc[nj][3] - m[1]);
            ls[0] += sc[nj][0] + sc[nj][1];
            ls[1] += sc[nj][2] + sc[nj][3];
        }
        #pragma unroll
        for (int kk = 0; kk < 4; kk++) {
            pa[kk][0] = h2pack(sc[2 * kk][0],     sc[2 * kk][1]);
            pa[kk][1] = h2pack(sc[2 * kk][2],     sc[2 * kk][3]);
            pa[kk][2] = h2pack(sc[2 * kk + 1][0], sc[2 * kk + 1][1]);
            pa[kk][3] = h2pack(sc[2 * kk + 1][2], sc[2 * kk + 1][3]);
        }
        #pragma unroll
        for (int ri = 0; ri < 2; ri++) {
            ls[ri] += __shfl_xor_sync(0xffffffff, ls[ri], 1);
            ls[ri] += __shfl_xor_sync(0xffffffff, ls[ri], 2);
        }
        lsum[0] = lsum[0] * corr[0] + ls[0];
        lsum[1] = lsum[1] * corr[1] + ls[1];
        #pragma unroll
        for (int nj = 0; nj < 8; nj++) {
            o[nj][0] *= corr[0]; o[nj][1] *= corr[0];
            o[nj][2] *= corr[1]; o[nj][3] *= corr[1];
        }

        // O += P V (fp16 k16)
        #pragma unroll
        for (int kk = 0; kk < 4; kk++) {
            #pragma unroll
            for (int njp = 0; njp < 4; njp++) {
                uint32_t b4[4];
                ldsm4(b_addr(st + A_V, njp * 16, kk * 16, lane, ASTR),
                      b4[0], b4[1], b4[2], b4[3]);
                mma16816f(o[2 * njp],     pa[kk][0], pa[kk][1], pa[kk][2], pa[kk][3], b4[0], b4[1]);
                mma16816f(o[2 * njp + 1], pa[kk][0], pa[kk][1], pa[kk][2], pa[kk][3], b4[2], b4[3]);
            }
        }
    }

    // epilogue
    const int b = bh >> 3, h = bh & 7;
    float inv[2] = {1.f / lsum[0], 1.f / lsum[1]};
    #pragma unroll
    for (int ri = 0; ri < 2; ri++) {
        int r = q0 + warp * 16 + (lane >> 2) + ri * 8;
        size_t R = (size_t)(b * SEQ + r) * EMB + h * HDIM;
        #pragma unroll
        for (int nj = 0; nj < 8; nj++) {
            int dd = nj * 8 + (lane & 3) * 2;
            *(uint32_t*)(g_A16 + R + dd) =
                h2pack(o[nj][ri * 2 + 0] * inv[ri], o[nj][ri * 2 + 1] * inv[ri]);
        }
    }
}

// ---------------------------------------------------------------------------
extern "C" void kernel_launch(void* const* d_in, const int* in_sizes, int n_in,
                              void* d_out, int out_size)
{
    const float* x     = (const float*)d_in[0];
    const float* w_qkv = (const float*)d_in[1];
    const float* w_o   = (const float*)d_in[2];
    const float* b_o   = (const float*)d_in[3];
    float* out = (float*)d_out;

    cudaFuncSetAttribute(gemm_qkv_tc, cudaFuncAttributeMaxDynamicSharedMemorySize, G_SMEM_SZ);
    cudaFuncSetAttribute(gemm_out_tc, cudaFuncAttributeMaxDynamicSharedMemorySize, O_SMEM_SZ);
    cudaFuncSetAttribute(attn_tc,     cudaFuncAttributeMaxDynamicSharedMemorySize, A_SMEM_SZ);

    split_x_kernel<<<(M1 * KD + 255) / 256, 256>>>(x);
    t_wqkv_kernel<<<dim3(N1 / 32, KD / 32), 256>>>(w_qkv);
    t_wo_kernel<<<dim3(EMB / 32, KD / 32), 256>>>(w_o);

    gemm_qkv_tc<<<dim3(N1 / 128, M1 / 128), 256, G_SMEM_SZ>>>();
    attn_tc<<<dim3(SEQ / 128, BATCH * NHEAD), 256, A_SMEM_SZ>>>();
    gemm_out_tc<<<dim3(EMB / 64, M1 / 128), 256, O_SMEM_SZ>>>(b_o, out);
}

// round 17
// speedup vs baseline: 2.3140x; 1.2001x over previous
#include <cuda_runtime.h>
#include <cuda_fp16.h>
#include <cstdint>

#define BATCH 2
#define SEQ   2048
#define EMB   512
#define NHEAD 8
#define HDIM  64
#define M1    (BATCH * SEQ)     // 4096
#define N1    (3 * EMB)         // 1536
#define KD    EMB               // 512
#define ATT_SCALE 0.125f
#define LOG2E 1.4426950408889634f

// ---------------------------------------------------------------------------
// helpers
// ---------------------------------------------------------------------------
__device__ __forceinline__ uint32_t smem_u32(const void* p) {
    uint32_t a;
    asm("{ .reg .u64 t; cvta.to.shared.u64 t, %1; cvt.u32.u64 %0, t; }" : "=r"(a) : "l"(p));
    return a;
}
__device__ __forceinline__ void ldsm4(uint32_t addr, uint32_t& r0, uint32_t& r1,
                                      uint32_t& r2, uint32_t& r3) {
    asm volatile("ldmatrix.sync.aligned.m8n8.x4.shared.b16 {%0,%1,%2,%3}, [%4];"
                 : "=r"(r0), "=r"(r1), "=r"(r2), "=r"(r3) : "r"(addr));
}
__device__ __forceinline__ void mma16816f(float* c, uint32_t a0, uint32_t a1,
                                          uint32_t a2, uint32_t a3,
                                          uint32_t b0, uint32_t b1) {
    asm volatile("mma.sync.aligned.m16n8k16.row.col.f32.f16.f16.f32 "
                 "{%0,%1,%2,%3}, {%4,%5,%6,%7}, {%8,%9}, {%0,%1,%2,%3};"
                 : "+f"(c[0]), "+f"(c[1]), "+f"(c[2]), "+f"(c[3])
                 : "r"(a0), "r"(a1), "r"(a2), "r"(a3), "r"(b0), "r"(b1));
}
__device__ __forceinline__ void cp16(uint32_t dst, const void* src) {
    asm volatile("cp.async.cg.shared.global [%0], [%1], 16;" :: "r"(dst), "l"(src));
}
#define CP_COMMIT() asm volatile("cp.async.commit_group;" ::: "memory")
#define CP_WAIT(n)  asm volatile("cp.async.wait_group %0;" :: "n"(n) : "memory")

__device__ __forceinline__ float fexp2(float x) {
    float r;
    asm("ex2.approx.f32 %0, %1;" : "=f"(r) : "f"(x));
    return r;
}
__device__ __forceinline__ void splith(float v, __half& h, __half& l) {
    h = __float2half(v);
    l = __float2half(v - __half2float(h));
}
__device__ __forceinline__ uint32_t packh(__half x, __half y) {
    __half2 t; t.x = x; t.y = y;
    return *(uint32_t*)&t;
}
__device__ __forceinline__ uint32_t h2pack(float x, float y) {
    __half2 t = __floats2half2_rn(x, y);
    return *(uint32_t*)&t;
}

// padded-layout ldmatrix addresses (stride bytes, 16-bit elements)
__device__ __forceinline__ uint32_t a_addr(uint32_t base, int r0, int c0, int lane, int stride) {
    return base + (uint32_t)(r0 + (lane & 15)) * stride + (uint32_t)(c0 + ((lane >> 4) << 3)) * 2;
}
__device__ __forceinline__ uint32_t b_addr(uint32_t base, int n0, int c0, int lane, int stride) {
    int n = n0 + (lane & 7) + ((lane >> 4) << 3);
    int k = c0 + (((lane >> 3) & 1) << 3);
    return base + (uint32_t)n * stride + (uint32_t)k * 2;
}
// GEMM swizzled layout: 64B rows, quad q placed at q ^ ((row>>1)&3)
__device__ __forceinline__ uint32_t gsw(int row, int qb) {
    return (uint32_t)row * 64 + (uint32_t)((((qb >> 4) ^ ((row >> 1) & 3)) << 4));
}
__device__ __forceinline__ uint32_t ga_addr(uint32_t base, int r0, int kk, int lane) {
    int r  = r0 + (lane & 15);
    int qb = kk * 32 + ((lane >> 4) << 4);
    return base + gsw(r, qb);
}
__device__ __forceinline__ uint32_t gb_addr(uint32_t base, int n0, int kk, int lane) {
    int n  = n0 + (lane & 7) + ((lane >> 4) << 3);
    int qb = kk * 32 + (((lane >> 3) & 1) << 4);
    return base + gsw(n, qb);
}

// ---------------------------------------------------------------------------
// Scratch (fp16)
// ---------------------------------------------------------------------------
__device__ __half g_Xh[M1 * KD],  g_Xl[M1 * KD];   // x fp16 hi/lo
__device__ __half g_Wq16[N1 * KD];                 // w_qkv^T fp16
__device__ __half g_Q16[BATCH*NHEAD*SEQ*HDIM];     // Q fp16 (single)
__device__ __half g_K16[BATCH*NHEAD*SEQ*HDIM];     // K fp16 (single)
__device__ __half g_Vh[BATCH*NHEAD*HDIM*SEQ];      // V^T fp16
__device__ __half g_A16[M1 * EMB];
__device__ __half g_Wo16[EMB * EMB];

// ---------------------------------------------------------------------------
// Fused prep: [0, XB) x-split | [XB, XB+WQB) w_qkv transpose | rest w_o transpose
// ---------------------------------------------------------------------------
#define XB  ((M1 * KD) / 256)          // 8192 blocks
#define WQB ((N1 / 32) * (KD / 32))    // 768 blocks (nx = N1/32)
#define WOB ((EMB / 32) * (KD / 32))   // 256 blocks
__global__ __launch_bounds__(256) void prep_kernel(const float* __restrict__ x,
                                                   const float* __restrict__ w_qkv,
                                                   const float* __restrict__ w_o)
{
    __shared__ float tile[32][33];
    const int blk = blockIdx.x;
    if (blk < XB) {
        int i = blk * 256 + threadIdx.x;
        __half a, b; splith(x[i], a, b);
        g_Xh[i] = a; g_Xl[i] = b;
    } else if (blk < XB + WQB) {
        int t = blk - XB;
        const int nb = (t % (N1 / 32)) * 32, kb = (t / (N1 / 32)) * 32;
        const int tx = threadIdx.x & 31, ty = threadIdx.x >> 5;
        #pragma unroll
        for (int i = 0; i < 4; i++)
            tile[ty + i * 8][tx] = w_qkv[(size_t)(kb + ty + i * 8) * N1 + nb + tx];
        __syncthreads();
        #pragma unroll
        for (int i = 0; i < 4; i++) {
            int n = nb + ty + i * 8;
            g_Wq16[(size_t)n * KD + kb + tx] = __float2half(tile[tx][ty + i * 8]);
        }
    } else {
        int t = blk - XB - WQB;
        const int nb = (t % (EMB / 32)) * 32, kb = (t / (EMB / 32)) * 32;
        const int tx = threadIdx.x & 31, ty = threadIdx.x >> 5;
        #pragma unroll
        for (int i = 0; i < 4; i++)
            tile[ty + i * 8][tx] = w_o[(size_t)(kb + ty + i * 8) * EMB + nb + tx];
        __syncthreads();
        #pragma unroll
        for (int i = 0; i < 4; i++) {
            int n = nb + ty + i * 8;
            g_Wo16[(size_t)n * EMB + kb + tx] = __float2half(tile[tx][ty + i * 8]);
        }
    }
}

// ---------------------------------------------------------------------------
// fp16x2 GEMM (QKV projection): X hi/lo fp16, W single fp16. BK=32,
// 4-stage cp.async, 2 CTAs/SM.
// ---------------------------------------------------------------------------
#define G_XH 0
#define G_XL 8192
#define G_W  16384
#define G_STAGE 24576
#define G_SMEM_SZ (4 * G_STAGE)

__device__ __forceinline__ void gemm_load_stage(uint32_t sbase, int m0, int n0, int k0)
{
    const int tid = threadIdx.x;
    #pragma unroll
    for (int i = 0; i < 2; i++) {
        int idx = tid + i * 256;
        int row = idx >> 2, q = idx & 3;
        uint32_t so = gsw(row, q << 4);
        size_t asrc = (size_t)(m0 + row) * KD + k0 + q * 8;
        size_t bsrc = (size_t)(n0 + row) * KD + k0 + q * 8;
        cp16(sbase + G_XH + so, g_Xh + asrc);
        cp16(sbase + G_XL + so, g_Xl + asrc);
        cp16(sbase + G_W  + so, g_Wq16 + bsrc);
    }
}

__device__ __forceinline__ void gemm_compute_stage(uint32_t sbase, int warp, int lane,
                                                   float acc[2][8][4])
{
    const int wm = warp & 3, wn = warp >> 2;
    #pragma unroll
    for (int kk = 0; kk < 2; kk++) {
        uint32_t xh[2][4], xl[2][4];
        #pragma unroll
        for (int mi = 0; mi < 2; mi++) {
            ldsm4(ga_addr(sbase + G_XH, wm * 32 + mi * 16, kk, lane),
                  xh[mi][0], xh[mi][1], xh[mi][2], xh[mi][3]);
            ldsm4(ga_addr(sbase + G_XL, wm * 32 + mi * 16, kk, lane),
                  xl[mi][0], xl[mi][1], xl[mi][2], xl[mi][3]);
        }
        #pragma unroll
        for (int njp = 0; njp < 4; njp++) {
            uint32_t w4[4];
            ldsm4(gb_addr(sbase + G_W, wn * 64 + njp * 16, kk, lane),
                  w4[0], w4[1], w4[2], w4[3]);
            #pragma unroll
            for (int mi = 0; mi < 2; mi++) {
                float* c0 = acc[mi][2 * njp];
                float* c1 = acc[mi][2 * njp + 1];
                mma16816f(c0, xh[mi][0], xh[mi][1], xh[mi][2], xh[mi][3], w4[0], w4[1]);
                mma16816f(c0, xl[mi][0], xl[mi][1], xl[mi][2], xl[mi][3], w4[0], w4[1]);
                mma16816f(c1, xh[mi][0], xh[mi][1], xh[mi][2], xh[mi][3], w4[2], w4[3]);
                mma16816f(c1, xl[mi][0], xl[mi][1], xl[mi][2], xl[mi][3], w4[2], w4[3]);
            }
        }
    }
}

__global__ __launch_bounds__(256, 2) void gemm_qkv_tc()
{
    extern __shared__ char smem[];
    uint32_t sb = smem_u32(smem);
    const int warp = threadIdx.x >> 5, lane = threadIdx.x & 31;
    const int wm = warp & 3, wn = warp >> 2;
    const int m0 = blockIdx.y * 128, n0 = blockIdx.x * 128;

    float acc[2][8][4];
    #pragma unroll
    for (int a = 0; a < 2; a++)
        #pragma unroll
        for (int b = 0; b < 8; b++)
            #pragma unroll
            for (int c = 0; c < 4; c++) acc[a][b][c] = 0.f;

    const int nk = KD / 32;
    gemm_load_stage(sb,               m0, n0, 0);  CP_COMMIT();
    gemm_load_stage(sb + G_STAGE,     m0, n0, 32); CP_COMMIT();
    gemm_load_stage(sb + 2 * G_STAGE, m0, n0, 64); CP_COMMIT();
    for (int kc = 0; kc < nk; kc++) {
        if (kc + 2 < nk) { CP_WAIT(2); } else if (kc + 1 < nk) { CP_WAIT(1); } else { CP_WAIT(0); }
        __syncthreads();
        if (kc + 3 < nk) {
            gemm_load_stage(sb + ((kc + 3) & 3) * G_STAGE, m0, n0, (kc + 3) * 32);
            CP_COMMIT();
        }
        gemm_compute_stage(sb + (kc & 3) * G_STAGE, warp, lane, acc);
    }

    const int region = n0 >> 9;  // 0=Q 1=K 2=V
    const float qscale = ATT_SCALE * LOG2E;
    #pragma unroll
    for (int mi = 0; mi < 2; mi++) {
        #pragma unroll
        for (int ri = 0; ri < 2; ri++) {
            int r = m0 + wm * 32 + mi * 16 + (lane >> 2) + ri * 8;
            int b = r >> 11, s = r & 2047;
            #pragma unroll
            for (int nj = 0; nj < 8; nj++) {
                int c = n0 + wn * 64 + nj * 8 + (lane & 3) * 2;
                int within = c & 511;
                int h = within >> 6, dd = within & 63;
                float v0 = acc[mi][nj][ri * 2 + 0];
                float v1 = acc[mi][nj][ri * 2 + 1];
                if (region < 2) {
                    if (region == 0) { v0 *= qscale; v1 *= qscale; }
                    __half* dst = region == 0 ? g_Q16 : g_K16;
                    size_t idx = (((size_t)(b * NHEAD + h) * SEQ + s) * HDIM + dd);
                    *(uint32_t*)(dst + idx) = h2pack(v0, v1);
                } else {
                    size_t base = ((size_t)(b * NHEAD + h) * HDIM + dd) * SEQ + s;
                    g_Vh[base]       = __float2half(v0);
                    g_Vh[base + SEQ] = __float2half(v1);
                }
            }
        }
    }
}

// ---------------------------------------------------------------------------
// Out projection (fp16): out = g_A16 @ g_Wo16^T + bias. Tiles 128m x 64n,
// BK=64 (144B padded rows), grid (8, 32). 3-stage, 2 CTAs/SM.
// ---------------------------------------------------------------------------
#define O_STR 144
#define O_A 0
#define O_B 18432
#define O_STAGE 27648
#define O_SMEM_SZ (3 * O_STAGE)

__global__ __launch_bounds__(256, 2) void gemm_out_tc(const float* __restrict__ bias,
                                                      float* __restrict__ out)
{
    extern __shared__ char smem[];
    uint32_t sb = smem_u32(smem);
    const int tid = threadIdx.x;
    const int warp = tid >> 5, lane = tid & 31;
    const int wm = warp & 3, wn = warp >> 2;
    const int m0 = blockIdx.y * 128, n0 = blockIdx.x * 64;

    float acc[2][4][4];
    #pragma unroll
    for (int a = 0; a < 2; a++)
        #pragma unroll
        for (int b = 0; b < 4; b++)
            #pragma unroll
            for (int c = 0; c < 4; c++) acc[a][b][c] = 0.f;

    auto load_stage = [&](uint32_t sbase, int k0) {
        #pragma unroll
        for (int i = 0; i < 4; i++) {
            int idx = tid + i * 256;
            int row = idx >> 3, q = idx & 7;
            cp16(sbase + O_A + (uint32_t)row * O_STR + q * 16,
                 g_A16 + (size_t)(m0 + row) * EMB + k0 + q * 8);
        }
        #pragma unroll
        for (int i = 0; i < 2; i++) {
            int idx = tid + i * 256;
            int row = idx >> 3, q = idx & 7;
            cp16(sbase + O_B + (uint32_t)row * O_STR + q * 16,
                 g_Wo16 + (size_t)(n0 + row) * EMB + k0 + q * 8);
        }
    };

    const int nk = EMB / 64;
    load_stage(sb,           0);  CP_COMMIT();
    load_stage(sb + O_STAGE, 64); CP_COMMIT();
    for (int kc = 0; kc < nk; kc++) {
        if (kc + 1 < nk) { CP_WAIT(1); } else { CP_WAIT(0); }
        __syncthreads();
        if (kc + 2 < nk) { load_stage(sb + ((kc + 2) % 3) * O_STAGE, (kc + 2) * 64); CP_COMMIT(); }
        const uint32_t st = sb + (kc % 3) * O_STAGE;

        #pragma unroll
        for (int kk = 0; kk < 4; kk++) {
            uint32_t a4[2][4];
            #pragma unroll
            for (int mi = 0; mi < 2; mi++)
                ldsm4(a_addr(st + O_A, wm * 32 + mi * 16, kk * 16, lane, O_STR),
                      a4[mi][0], a4[mi][1], a4[mi][2], a4[mi][3]);
            #pragma unroll
            for (int njp = 0; njp < 2; njp++) {
                uint32_t b4[4];
                ldsm4(b_addr(st + O_B, wn * 32 + njp * 16, kk * 16, lane, O_STR),
                      b4[0], b4[1], b4[2], b4[3]);
                #pragma unroll
                for (int mi = 0; mi < 2; mi++) {
                    mma16816f(acc[mi][2 * njp],     a4[mi][0], a4[mi][1], a4[mi][2], a4[mi][3], b4[0], b4[1]);
                    mma16816f(acc[mi][2 * njp + 1], a4[mi][0], a4[mi][1], a4[mi][2], a4[mi][3], b4[2], b4[3]);
                }
            }
        }
    }

    #pragma unroll
    for (int mi = 0; mi < 2; mi++) {
        #pragma unroll
        for (int ri = 0; ri < 2; ri++) {
            int r = m0 + wm * 32 + mi * 16 + (lane >> 2) + ri * 8;
            #pragma unroll
            for (int nj = 0; nj < 4; nj++) {
                int c = n0 + wn * 32 + nj * 8 + (lane & 3) * 2;
                float2 v;
                v.x = acc[mi][nj][ri * 2 + 0] + bias[c];
                v.y = acc[mi][nj][ri * 2 + 1] + bias[c + 1];
                *(float2*)(out + (size_t)r * EMB + c) = v;
            }
        }
    }
}

// ---------------------------------------------------------------------------
// Flash attention (exp2). grid (16, 16), 256 threads, 2 CTAs/SM.
// QK^T fp16 single (Q regs, K smem); P·V fp16 k16, C->A reuse. 4-stage.
// ---------------------------------------------------------------------------
#define ASTR 144
#define A_K 0
#define A_V 9216
#define A_STAGE 18432
#define A_SMEM_SZ (4 * A_STAGE)

__device__ __forceinline__ void attn_load_stage(uint32_t sbase, size_t qk_base,
                                                size_t v_base, int t)
{
    const int tid = threadIdx.x;
    #pragma unroll
    for (int i = 0; i < 2; i++) {
        int idx = tid + i * 256;
        int row = idx >> 3, q = idx & 7;
        uint32_t so = (uint32_t)row * ASTR + q * 16;
        { size_t src = qk_base + (size_t)(t * 64 + row) * HDIM + q * 8;
          cp16(sbase + A_K + so, g_K16 + src); }
        { size_t src = v_base + (size_t)row * SEQ + t * 64 + q * 8;
          cp16(sbase + A_V + so, g_Vh + src); }
    }
}

__global__ __launch_bounds__(256, 2) void attn_tc()
{
    extern __shared__ char smem[];
    uint32_t sb = smem_u32(smem);
    const int tid = threadIdx.x;
    const int warp = tid >> 5, lane = tid & 31;
    const int bh = blockIdx.y;
    const int q0 = blockIdx.x * 128;
    const size_t qk_base = (size_t)bh * SEQ * HDIM;
    const size_t v_base  = (size_t)bh * HDIM * SEQ;

    // Stage Q, hoist fragments, then region is reused by pipeline.
    #pragma unroll
    for (int i = 0; i < 4; i++) {
        int idx = tid + i * 256;
        int row = idx >> 3, q = idx & 7;
        uint32_t so = (uint32_t)row * ASTR + q * 16;
        size_t src = qk_base + (size_t)(q0 + row) * HDIM + q * 8;
        *(uint4*)(smem + so) = *(const uint4*)(g_Q16 + src);
    }
    __syncthreads();
    uint32_t qf[4][4];
    #pragma unroll
    for (int kk = 0; kk < 4; kk++)
        ldsm4(a_addr(sb, warp * 16, kk * 16, lane, ASTR),
              qf[kk][0], qf[kk][1], qf[kk][2], qf[kk][3]);
    __syncthreads();

    float o[8][4];
    #pragma unroll
    for (int a = 0; a < 8; a++)
        #pragma unroll
        for (int c = 0; c < 4; c++) o[a][c] = 0.f;
    float m[2] = {-1e30f, -1e30f};
    float lsum[2] = {0.f, 0.f};

    const int NT = SEQ / 64;
    attn_load_stage(sb,               qk_base, v_base, 0); CP_COMMIT();
    attn_load_stage(sb + A_STAGE,     qk_base, v_base, 1); CP_COMMIT();
    attn_load_stage(sb + 2 * A_STAGE, qk_base, v_base, 2); CP_COMMIT();

    for (int t = 0; t < NT; t++) {
        if (t + 2 < NT) { CP_WAIT(2); } else if (t + 1 < NT) { CP_WAIT(1); } else { CP_WAIT(0); }
        __syncthreads();
        if (t + 3 < NT) {
            attn_load_stage(sb + ((t + 3) & 3) * A_STAGE, qk_base, v_base, t + 3);
            CP_COMMIT();
        }
        const uint32_t st = sb + (t & 3) * A_STAGE;

        // S' = Q K^T (fp16 single)
        float sc[8][4];
        #pragma unroll
        for (int a = 0; a < 8; a++)
            #pragma unroll
            for (int c = 0; c < 4; c++) sc[a][c] = 0.f;

        #pragma unroll
        for (int kk = 0; kk < 4; kk++) {
            #pragma unroll
            for (int njp = 0; njp < 4; njp++) {
                uint32_t k4[4];
                ldsm4(b_addr(st + A_K, njp * 16, kk * 16, lane, ASTR),
                      k4[0], k4[1], k4[2], k4[3]);
                mma16816f(sc[2 * njp],     qf[kk][0], qf[kk][1], qf[kk][2], qf[kk][3], k4[0], k4[1]);
                mma16816f(sc[2 * njp + 1], qf[kk][0], qf[kk][1], qf[kk][2], qf[kk][3], k4[2], k4[3]);
            }
        }

        // online softmax (exp2)
        float mx[2] = {-1e30f, -1e30f};
        #pragma unroll
        for (int nj = 0; nj < 8; nj++) {
            mx[0] = fmaxf(mx[0], fmaxf(sc[nj][0], sc[nj][1]));
            mx[1] = fmaxf(mx[1], fmaxf(sc[nj][2], sc[nj][3]));
        }
        #pragma unroll
        for (int ri = 0; ri < 2; ri++) {
            mx[ri] = fmaxf(mx[ri], __shfl_xor_sync(0xffffffff, mx[ri], 1));
            mx[ri] = fmaxf(mx[ri], __shfl_xor_sync(0xffffffff, mx[ri], 2));
        }
        float corr[2];
        #pragma unroll
        for (int ri = 0; ri < 2; ri++) {
            float nm = fmaxf(m[ri], mx[ri]);
            corr[ri] = fexp2(m[ri] - nm);
            m[ri] = nm;
        }

        float ls[2] = {0.f, 0.f};
        uint32_t pa[4][4];
        #pragma unroll
        for (int nj = 0; nj < 8; nj++) {
            sc[nj][0] = fexp2(sc[nj][0] - m[0]);
            sc[nj][1] = fexp2(sc[nj][1] - m[0]);
            sc[nj][2] = fexp2(sc[nj][2] - m[1]);
            sc[nj][3] = fexp2(sc[nj][3] - m[1]);
            ls[0] += sc[nj][0] + sc[nj][1];
            ls[1] += sc[nj][2] + sc[nj][3];
        }
        #pragma unroll
        for (int kk = 0; kk < 4; kk++) {
            pa[kk][0] = h2pack(sc[2 * kk][0],     sc[2 * kk][1]);
            pa[kk][1] = h2pack(sc[2 * kk][2],     sc[2 * kk][3]);
            pa[kk][2] = h2pack(sc[2 * kk + 1][0], sc[2 * kk + 1][1]);
            pa[kk][3] = h2pack(sc[2 * kk + 1][2], sc[2 * kk + 1][3]);
        }
        #pragma unroll
        for (int ri = 0; ri < 2; ri++) {
            ls[ri] += __shfl_xor_sync(0xffffffff, ls[ri], 1);
            ls[ri] += __shfl_xor_sync(0xffffffff, ls[ri], 2);
        }
        lsum[0] = lsum[0] * corr[0] + ls[0];
        lsum[1] = lsum[1] * corr[1] + ls[1];
        #pragma unroll
        for (int nj = 0; nj < 8; nj++) {
            o[nj][0] *= corr[0]; o[nj][1] *= corr[0];
            o[nj][2] *= corr[1]; o[nj][3] *= corr[1];
        }

        // O += P V (fp16 k16)
        #pragma unroll
        for (int kk = 0; kk < 4; kk++) {
            #pragma unroll
            for (int njp = 0; njp < 4; njp++) {
                uint32_t b4[4];
                ldsm4(b_addr(st + A_V, njp * 16, kk * 16, lane, ASTR),
                      b4[0], b4[1], b4[2], b4[3]);
                mma16816f(o[2 * njp],     pa[kk][0], pa[kk][1], pa[kk][2], pa[kk][3], b4[0], b4[1]);
                mma16816f(o[2 * njp + 1], pa[kk][0], pa[kk][1], pa[kk][2], pa[kk][3], b4[2], b4[3]);
            }
        }
    }

    // epilogue
    const int b = bh >> 3, h = bh & 7;
    float inv[2] = {1.f / lsum[0], 1.f / lsum[1]};
    #pragma unroll
    for (int ri = 0; ri < 2; ri++) {
        int r = q0 + warp * 16 + (lane >> 2) + ri * 8;
        size_t R = (size_t)(b * SEQ + r) * EMB + h * HDIM;
        #pragma unroll
        for (int nj = 0; nj < 8; nj++) {
            int dd = nj * 8 + (lane & 3) * 2;
            *(uint32_t*)(g_A16 + R + dd) =
                h2pack(o[nj][ri * 2 + 0] * inv[ri], o[nj][ri * 2 + 1] * inv[ri]);
        }
    }
}

// ---------------------------------------------------------------------------
extern "C" void kernel_launch(void* const* d_in, const int* in_sizes, int n_in,
                              void* d_out, int out_size)
{
    const float* x     = (const float*)d_in[0];
    const float* w_qkv = (const float*)d_in[1];
    const float* w_o   = (const float*)d_in[2];
    const float* b_o   = (const float*)d_in[3];
    float* out = (float*)d_out;

    cudaFuncSetAttribute(gemm_qkv_tc, cudaFuncAttributeMaxDynamicSharedMemorySize, G_SMEM_SZ);
    cudaFuncSetAttribute(gemm_out_tc, cudaFuncAttributeMaxDynamicSharedMemorySize, O_SMEM_SZ);
    cudaFuncSetAttribute(attn_tc,     cudaFuncAttributeMaxDynamicSharedMemorySize, A_SMEM_SZ);

    prep_kernel<<<XB + WQB + WOB, 256>>>(x, w_qkv, w_o);
    gemm_qkv_tc<<<dim3(N1 / 128, M1 / 128), 256, G_SMEM_SZ>>>();
    attn_tc<<<dim3(SEQ / 128, BATCH * NHEAD), 256, A_SMEM_SZ>>>();
    gemm_out_tc<<<dim3(EMB / 64, M1 / 128), 256, O_SMEM_SZ>>>(b_o, out);
}